// round 1
// baseline (speedup 1.0000x reference)
#include <cuda_runtime.h>
#include <cuda_bf16.h>
#include <math.h>

// ---------------- problem constants ----------------
#define L_X   1536
#define S_C   512
#define TT    2048          // L_X + S_C
#define D     1024
#define H     16
#define HD    64
#define FF    4096

// ---------------- scratch (device globals; no cudaMalloc allowed) ----------
__device__ float g_xln[L_X * D];
__device__ float g_cln[S_C * D];
__device__ float g_qk [L_X * 2 * D];      // reused per stream
__device__ float g_vt [L_X * D];          // reused per stream
__device__ float g_q  [H * TT * HD];
__device__ float g_k  [H * TT * HD];
__device__ float g_v  [H * TT * HD];
__device__ float g_y  [TT * D];
__device__ float g_x1 [L_X * D];          // reused per stream
__device__ float g_h  [L_X * D];          // reused per stream
__device__ float g_t1 [L_X * FF];         // reused per stream
__device__ float g_t3 [L_X * FF];         // reused per stream

// ---------------- utils ----------------
__device__ __forceinline__ float warpSum(float v) {
    #pragma unroll
    for (int o = 16; o > 0; o >>= 1) v += __shfl_xor_sync(0xffffffffu, v, o);
    return v;
}

// ---------------- LayerNorm (D=1024, one block per row) ----------------
__global__ void ln_kernel(const float* __restrict__ in, float* __restrict__ out) {
    int row = blockIdx.x;
    const float* x = in + (size_t)row * D;
    float s = 0.f, ss = 0.f;
    for (int i = threadIdx.x; i < D; i += 256) {
        float v = x[i]; s += v; ss += v * v;
    }
    __shared__ float shs[8], shss[8];
    float ws = warpSum(s), wss = warpSum(ss);
    int w = threadIdx.x >> 5;
    if ((threadIdx.x & 31) == 0) { shs[w] = ws; shss[w] = wss; }
    __syncthreads();
    float ts = 0.f, tss = 0.f;
    #pragma unroll
    for (int i = 0; i < 8; i++) { ts += shs[i]; tss += shss[i]; }
    float mean = ts * (1.0f / D);
    float var  = tss * (1.0f / D) - mean * mean;
    float inv  = rsqrtf(var + 1e-6f);
    float* o = out + (size_t)row * D;
    for (int i = threadIdx.x; i < D; i += 256)
        o[i] = (x[i] - mean) * inv;
}

// ---------------- SGEMM: C[M,N] = A[M,K] @ B[N,K]^T (+bias[N]) (+resid[M,N])
// Tiles 128x128x8, 256 threads, 8x8 per-thread microtile. M,N %128==0, K %8==0.
__global__ void sgemm(const float* __restrict__ A, const float* __restrict__ B,
                      const float* __restrict__ bias, const float* __restrict__ resid,
                      float* __restrict__ C, int M, int N, int K) {
    __shared__ float As[8][132];
    __shared__ float Bs[8][132];
    int tid = threadIdx.x;
    int bx = blockIdx.x, by = blockIdx.y;
    int tx = tid & 15, ty = tid >> 4;
    int lr = tid >> 1;              // 0..127
    int lc = (tid & 1) << 2;        // 0 or 4
    const float* Ap = A + (size_t)(by * 128 + lr) * K + lc;
    const float* Bp = B + (size_t)(bx * 128 + lr) * K + lc;
    float acc[8][8];
    #pragma unroll
    for (int i = 0; i < 8; i++)
        #pragma unroll
        for (int j = 0; j < 8; j++) acc[i][j] = 0.f;

    for (int k0 = 0; k0 < K; k0 += 8) {
        float4 a = *(const float4*)(Ap + k0);
        float4 b = *(const float4*)(Bp + k0);
        As[lc + 0][lr] = a.x; As[lc + 1][lr] = a.y; As[lc + 2][lr] = a.z; As[lc + 3][lr] = a.w;
        Bs[lc + 0][lr] = b.x; Bs[lc + 1][lr] = b.y; Bs[lc + 2][lr] = b.z; Bs[lc + 3][lr] = b.w;
        __syncthreads();
        #pragma unroll
        for (int kk = 0; kk < 8; kk++) {
            float4 a0 = *(const float4*)&As[kk][ty * 8];
            float4 a1 = *(const float4*)&As[kk][ty * 8 + 4];
            float4 b0 = *(const float4*)&Bs[kk][tx * 8];
            float4 b1 = *(const float4*)&Bs[kk][tx * 8 + 4];
            float ar[8] = {a0.x, a0.y, a0.z, a0.w, a1.x, a1.y, a1.z, a1.w};
            float br[8] = {b0.x, b0.y, b0.z, b0.w, b1.x, b1.y, b1.z, b1.w};
            #pragma unroll
            for (int i = 0; i < 8; i++)
                #pragma unroll
                for (int j = 0; j < 8; j++)
                    acc[i][j] += ar[i] * br[j];
        }
        __syncthreads();
    }
    #pragma unroll
    for (int i = 0; i < 8; i++) {
        int row = by * 128 + ty * 8 + i;
        size_t rbase = (size_t)row * N;
        #pragma unroll
        for (int j = 0; j < 8; j++) {
            int col = bx * 128 + tx * 8 + j;
            float v = acc[i][j];
            if (bias)  v += bias[col];
            if (resid) v += resid[rbase + col];
            C[rbase + col] = v;
        }
    }
}

// ---------------- qk finish: RMSNorm per head + RoPE, write to [H,T,HD] ------
// grid (rows, H), block 64
__global__ void qk_finish(const float* __restrict__ qk,
                          const float* __restrict__ qn, const float* __restrict__ kn,
                          const float* __restrict__ freqs,
                          float* __restrict__ Q, float* __restrict__ Ko, int t_off) {
    int row = blockIdx.x, h = blockIdx.y, d = threadIdx.x;
    float qv = qk[(size_t)row * (2 * D) + h * HD + d];
    float kv = qk[(size_t)row * (2 * D) + D + h * HD + d];
    __shared__ float sh[4];
    float sq = qv * qv, sk = kv * kv;
    #pragma unroll
    for (int o = 16; o > 0; o >>= 1) { sq += __shfl_xor_sync(0xffffffffu, sq, o); sk += __shfl_xor_sync(0xffffffffu, sk, o); }
    int w = d >> 5;
    if ((d & 31) == 0) { sh[w] = sq; sh[2 + w] = sk; }
    __syncthreads();
    float rq = rsqrtf((sh[0] + sh[1]) * (1.0f / HD) + 1e-6f);
    float rk = rsqrtf((sh[2] + sh[3]) * (1.0f / HD) + 1e-6f);
    __shared__ float sQ[HD], sK[HD];
    sQ[d] = qv * rq * qn[d];
    sK[d] = kv * rk * kn[d];
    __syncthreads();
    int t = t_off + row;
    int i = d >> 1;
    float cs = freqs[((size_t)t * 32 + i) * 2 + 0];
    float sn = freqs[((size_t)t * 32 + i) * 2 + 1];
    float oq, ok;
    if ((d & 1) == 0) { oq = sQ[d] * cs - sQ[d + 1] * sn; ok = sK[d] * cs - sK[d + 1] * sn; }
    else              { oq = sQ[d - 1] * sn + sQ[d] * cs; ok = sK[d - 1] * sn + sK[d] * cs; }
    size_t off = ((size_t)h * TT + t) * HD + d;
    Q[off] = oq; Ko[off] = ok;
}

// ---------------- v reshape: [rows,D] -> [H,T,HD] ----------------
__global__ void v_finish(const float* __restrict__ vt, float* __restrict__ V,
                         int rows, int t_off) {
    int idx = blockIdx.x * 256 + threadIdx.x;
    if (idx >= rows * D) return;
    int row = idx >> 10, col = idx & 1023;
    int h = col >> 6, d = col & 63;
    V[((size_t)h * TT + t_off + row) * HD + d] = vt[idx];
}

// ---------------- flash attention (fp32, causal) ----------------
// Q,K,V: [H][T][64]; Y: [T][D]. grid (T/64, H), block (256), dyn smem 4*64*68*4.
#define ATS 68
__global__ void attn_kernel(const float* __restrict__ Q, const float* __restrict__ K,
                            const float* __restrict__ V, float* __restrict__ Y) {
    extern __shared__ float smem[];
    float* QsT = smem;                 // [d][row]  stride ATS
    float* KsT = QsT + 64 * ATS;       // [d][col]
    float* Vs  = KsT + 64 * ATS;       // [key][c]
    float* PsT = Vs  + 64 * ATS;       // [key][row]
    int bx = blockIdx.x, h = blockIdx.y;
    int tid = threadIdx.x;
    int tx = tid & 15, ty = tid >> 4;
    const float scale = 0.125f;
    const float* Qh = Q + (size_t)h * TT * HD;
    const float* Kh = K + (size_t)h * TT * HD;
    const float* Vh = V + (size_t)h * TT * HD;
    int q0 = bx * 64;

    // load Q tile (prescaled), transposed
    #pragma unroll
    for (int l = 0; l < 4; l++) {
        int e = tid + l * 256;
        int r = e >> 4, c4 = (e & 15) << 2;
        float4 v = *(const float4*)(Qh + (size_t)(q0 + r) * HD + c4);
        QsT[(c4 + 0) * ATS + r] = v.x * scale;
        QsT[(c4 + 1) * ATS + r] = v.y * scale;
        QsT[(c4 + 2) * ATS + r] = v.z * scale;
        QsT[(c4 + 3) * ATS + r] = v.w * scale;
    }
    float m[4], lsum[4], o[4][4];
    #pragma unroll
    for (int i = 0; i < 4; i++) {
        m[i] = -INFINITY; lsum[i] = 0.f;
        #pragma unroll
        for (int j = 0; j < 4; j++) o[i][j] = 0.f;
    }
    int ntiles = bx + 1;
    for (int kt = 0; kt < ntiles; kt++) {
        int k0 = kt * 64;
        __syncthreads();   // protect KsT/Vs/PsT from previous iter readers
        #pragma unroll
        for (int l = 0; l < 4; l++) {
            int e = tid + l * 256;
            int r = e >> 4, c4 = (e & 15) << 2;
            float4 kv = *(const float4*)(Kh + (size_t)(k0 + r) * HD + c4);
            KsT[(c4 + 0) * ATS + r] = kv.x;
            KsT[(c4 + 1) * ATS + r] = kv.y;
            KsT[(c4 + 2) * ATS + r] = kv.z;
            KsT[(c4 + 3) * ATS + r] = kv.w;
            float4 vv = *(const float4*)(Vh + (size_t)(k0 + r) * HD + c4);
            *(float4*)(Vs + r * ATS + c4) = vv;
        }
        __syncthreads();
        // S = Q K^T
        float s[4][4];
        #pragma unroll
        for (int i = 0; i < 4; i++)
            #pragma unroll
            for (int j = 0; j < 4; j++) s[i][j] = 0.f;
        #pragma unroll 8
        for (int kk = 0; kk < 64; kk++) {
            float4 a = *(const float4*)(QsT + kk * ATS + ty * 4);
            float4 b = *(const float4*)(KsT + kk * ATS + tx * 4);
            float ar[4] = {a.x, a.y, a.z, a.w};
            float br[4] = {b.x, b.y, b.z, b.w};
            #pragma unroll
            for (int i = 0; i < 4; i++)
                #pragma unroll
                for (int j = 0; j < 4; j++) s[i][j] += ar[i] * br[j];
        }
        // causal mask + online softmax
        #pragma unroll
        for (int i = 0; i < 4; i++) {
            int rg = q0 + ty * 4 + i;
            float rmax = -INFINITY;
            #pragma unroll
            for (int j = 0; j < 4; j++) {
                int cg = k0 + tx * 4 + j;
                if (cg > rg) s[i][j] = -INFINITY;
                rmax = fmaxf(rmax, s[i][j]);
            }
            #pragma unroll
            for (int off = 1; off < 16; off <<= 1)
                rmax = fmaxf(rmax, __shfl_xor_sync(0xffffffffu, rmax, off));
            float nm = fmaxf(m[i], rmax);
            float corr = expf(m[i] - nm);
            m[i] = nm;
            float psum = 0.f;
            #pragma unroll
            for (int j = 0; j < 4; j++) {
                float p = expf(s[i][j] - nm);
                PsT[(tx * 4 + j) * ATS + ty * 4 + i] = p;
                psum += p;
            }
            #pragma unroll
            for (int off = 1; off < 16; off <<= 1)
                psum += __shfl_xor_sync(0xffffffffu, psum, off);
            lsum[i] = lsum[i] * corr + psum;
            #pragma unroll
            for (int j = 0; j < 4; j++) o[i][j] *= corr;
        }
        __syncthreads();
        // O += P V
        #pragma unroll 8
        for (int key = 0; key < 64; key++) {
            float4 a = *(const float4*)(PsT + key * ATS + ty * 4);
            float4 b = *(const float4*)(Vs + key * ATS + tx * 4);
            float ar[4] = {a.x, a.y, a.z, a.w};
            float br[4] = {b.x, b.y, b.z, b.w};
            #pragma unroll
            for (int i = 0; i < 4; i++)
                #pragma unroll
                for (int j = 0; j < 4; j++) o[i][j] += ar[i] * br[j];
        }
    }
    // epilogue: Y[t][h*64 + c]
    #pragma unroll
    for (int i = 0; i < 4; i++) {
        float inv = 1.0f / lsum[i];
        int t = q0 + ty * 4 + i;
        #pragma unroll
        for (int j = 0; j < 4; j++)
            Y[(size_t)t * D + h * HD + tx * 4 + j] = o[i][j] * inv;
    }
}

// ---------------- SiLU gate ----------------
__global__ void silu_gate(const float* __restrict__ a, const float* __restrict__ b,
                          float* __restrict__ g, int n) {
    int i = blockIdx.x * 256 + threadIdx.x;
    if (i < n) {
        float x = a[i];
        g[i] = (x / (1.0f + expf(-x))) * b[i];
    }
}

// ---------------- host launcher ----------------
static inline dim3 gemm_grid(int M, int N) { return dim3(N / 128, M / 128); }

extern "C" void kernel_launch(void* const* d_in, const int* in_sizes, int n_in,
                              void* d_out, int out_size) {
    const float* x        = (const float*)d_in[0];
    const float* c        = (const float*)d_in[1];
    const float* freqs    = (const float*)d_in[2];
    const float* px_qk_w  = (const float*)d_in[3];
    const float* px_qn    = (const float*)d_in[4];
    const float* px_kn    = (const float*)d_in[5];
    const float* px_v_w   = (const float*)d_in[6];
    const float* px_v_b   = (const float*)d_in[7];
    const float* pc_qk_w  = (const float*)d_in[8];
    const float* pc_qn    = (const float*)d_in[9];
    const float* pc_kn    = (const float*)d_in[10];
    const float* pc_v_w   = (const float*)d_in[11];
    const float* pc_v_b   = (const float*)d_in[12];
    const float* p1_proj_w = (const float*)d_in[13];
    const float* p1_proj_b = (const float*)d_in[14];
    const float* p1_w1    = (const float*)d_in[15];
    const float* p1_b1    = (const float*)d_in[16];
    const float* p1_w3    = (const float*)d_in[17];
    const float* p1_b3    = (const float*)d_in[18];
    const float* p1_w2    = (const float*)d_in[19];
    const float* p1_b2    = (const float*)d_in[20];
    const float* p2_proj_w = (const float*)d_in[21];
    const float* p2_proj_b = (const float*)d_in[22];
    const float* p2_w1    = (const float*)d_in[23];
    const float* p2_b1    = (const float*)d_in[24];
    const float* p2_w3    = (const float*)d_in[25];
    const float* p2_b3    = (const float*)d_in[26];
    const float* p2_w2    = (const float*)d_in[27];
    const float* p2_b2    = (const float*)d_in[28];
    float* out = (float*)d_out;

    float *xln, *cln, *qk, *vt, *q, *k, *v, *y, *x1, *h, *t1, *t3;
    cudaGetSymbolAddress((void**)&xln, g_xln);
    cudaGetSymbolAddress((void**)&cln, g_cln);
    cudaGetSymbolAddress((void**)&qk,  g_qk);
    cudaGetSymbolAddress((void**)&vt,  g_vt);
    cudaGetSymbolAddress((void**)&q,   g_q);
    cudaGetSymbolAddress((void**)&k,   g_k);
    cudaGetSymbolAddress((void**)&v,   g_v);
    cudaGetSymbolAddress((void**)&y,   g_y);
    cudaGetSymbolAddress((void**)&x1,  g_x1);
    cudaGetSymbolAddress((void**)&h,   g_h);
    cudaGetSymbolAddress((void**)&t1,  g_t1);
    cudaGetSymbolAddress((void**)&t3,  g_t3);

    const int SMEM_ATTN = 4 * 64 * ATS * 4;
    cudaFuncSetAttribute(attn_kernel, cudaFuncAttributeMaxDynamicSharedMemorySize, SMEM_ATTN);

    // 1) LayerNorm both streams
    ln_kernel<<<L_X, 256>>>(x, xln);
    ln_kernel<<<S_C, 256>>>(c, cln);

    // 2) c stream QKV (t_off = 0)
    sgemm<<<gemm_grid(S_C, 2 * D), 256>>>(cln, pc_qk_w, nullptr, nullptr, qk, S_C, 2 * D, D);
    qk_finish<<<dim3(S_C, H), HD>>>(qk, pc_qn, pc_kn, freqs, q, k, 0);
    sgemm<<<gemm_grid(S_C, D), 256>>>(cln, pc_v_w, pc_v_b, nullptr, vt, S_C, D, D);
    v_finish<<<(S_C * D + 255) / 256, 256>>>(vt, v, S_C, 0);

    // 3) x stream QKV (t_off = S_C)
    sgemm<<<gemm_grid(L_X, 2 * D), 256>>>(xln, px_qk_w, nullptr, nullptr, qk, L_X, 2 * D, D);
    qk_finish<<<dim3(L_X, H), HD>>>(qk, px_qn, px_kn, freqs, q, k, S_C);
    sgemm<<<gemm_grid(L_X, D), 256>>>(xln, px_v_w, px_v_b, nullptr, vt, L_X, D, D);
    v_finish<<<(L_X * D + 255) / 256, 256>>>(vt, v, L_X, S_C);

    // 4) causal attention
    attn_kernel<<<dim3(TT / 64, H), 256, SMEM_ATTN>>>(q, k, v, y);

    // 5) post for x stream (y rows [S_C, TT))  -> out[0 : L_X*D)
    const float* yx = y + (size_t)S_C * D;
    sgemm<<<gemm_grid(L_X, D), 256>>>(yx, p1_proj_w, p1_proj_b, x, x1, L_X, D, D);
    ln_kernel<<<L_X, 256>>>(x1, h);
    sgemm<<<gemm_grid(L_X, FF), 256>>>(h, p1_w1, p1_b1, nullptr, t1, L_X, FF, D);
    sgemm<<<gemm_grid(L_X, FF), 256>>>(h, p1_w3, p1_b3, nullptr, t3, L_X, FF, D);
    silu_gate<<<(L_X * FF + 255) / 256, 256>>>(t1, t3, t1, L_X * FF);
    sgemm<<<gemm_grid(L_X, D), 256>>>(t1, p1_w2, p1_b2, x1, out, L_X, D, FF);

    // 6) post for c stream (y rows [0, S_C))  -> out[L_X*D : ]
    sgemm<<<gemm_grid(S_C, D), 256>>>(y, p2_proj_w, p2_proj_b, c, x1, S_C, D, D);
    ln_kernel<<<S_C, 256>>>(x1, h);
    sgemm<<<gemm_grid(S_C, FF), 256>>>(h, p2_w1, p2_b1, nullptr, t1, S_C, FF, D);
    sgemm<<<gemm_grid(S_C, FF), 256>>>(h, p2_w3, p2_b3, nullptr, t3, S_C, FF, D);
    silu_gate<<<(S_C * FF + 255) / 256, 256>>>(t1, t3, t1, S_C * FF);
    sgemm<<<gemm_grid(S_C, D), 256>>>(t1, p2_w2, p2_b2, x1, out + (size_t)L_X * D, S_C, D, FF);
}

// round 3
// speedup vs baseline: 3.0523x; 3.0523x over previous
#include <cuda_runtime.h>
#include <cuda_bf16.h>
#include <cstdint>
#include <math.h>

// ---------------- problem constants ----------------
#define L_X   1536
#define S_C   512
#define TT    2048          // L_X + S_C
#define D     1024
#define H     16
#define HD    64
#define FF    4096

// ---------------- scratch (device globals; no cudaMalloc allowed) ----------
__device__ float g_xln[L_X * D];
__device__ float g_cln[S_C * D];
__device__ float g_qk [L_X * 2 * D];      // reused per stream
__device__ float g_vt [L_X * D];          // reused per stream
__device__ float g_q  [H * TT * HD];
__device__ float g_k  [H * TT * HD];
__device__ float g_v  [H * TT * HD];
__device__ float g_y  [TT * D];
__device__ float g_x1 [L_X * D];          // reused per stream
__device__ float g_h  [L_X * D];          // reused per stream
__device__ float g_t1 [L_X * FF];         // reused per stream
__device__ float g_t3 [L_X * FF];         // reused per stream

// ---------------- utils ----------------
__device__ __forceinline__ float warpSum(float v) {
    #pragma unroll
    for (int o = 16; o > 0; o >>= 1) v += __shfl_xor_sync(0xffffffffu, v, o);
    return v;
}
__device__ __forceinline__ uint32_t f2tf32(float v) {
    uint32_t r;
    asm("cvt.rna.tf32.f32 %0, %1;" : "=r"(r) : "f"(v));
    return r;
}

// ---------------- LayerNorm (D=1024, one block per row) ----------------
__global__ void ln_kernel(const float* __restrict__ in, float* __restrict__ out) {
    int row = blockIdx.x;
    const float* x = in + (size_t)row * D;
    float s = 0.f, ss = 0.f;
    for (int i = threadIdx.x; i < D; i += 256) {
        float v = x[i]; s += v; ss += v * v;
    }
    __shared__ float shs[8], shss[8];
    float ws = warpSum(s), wss = warpSum(ss);
    int w = threadIdx.x >> 5;
    if ((threadIdx.x & 31) == 0) { shs[w] = ws; shss[w] = wss; }
    __syncthreads();
    float ts = 0.f, tss = 0.f;
    #pragma unroll
    for (int i = 0; i < 8; i++) { ts += shs[i]; tss += shss[i]; }
    float mean = ts * (1.0f / D);
    float var  = tss * (1.0f / D) - mean * mean;
    float inv  = rsqrtf(var + 1e-6f);
    float* o = out + (size_t)row * D;
    for (int i = threadIdx.x; i < D; i += 256)
        o[i] = (x[i] - mean) * inv;
}

// ======================================================================
// tf32 mma.sync GEMM: C[M,N] = A[M,K] @ B[N,K]^T (+bias) (+resid)
// Tile 128x128, K-chunk 32. 256 threads = 8 warps, each warp 64x32.
// Double-buffered smem (stride 36 -> conflict-free fragment loads).
// M,N multiples of 128; K multiple of 32.
// ======================================================================
#define GST 36
#define GBUF (128 * GST)                 // floats per operand buffer
#define MMG_SMEM (4 * GBUF * 4)          // bytes: 2 bufs x (A+B)

__global__ __launch_bounds__(256)
void mma_gemm(const float* __restrict__ A, const float* __restrict__ B,
              const float* __restrict__ bias, const float* __restrict__ resid,
              float* __restrict__ C, int M, int N, int K) {
    extern __shared__ float smf[];
    int tid = threadIdx.x;
    int wid = tid >> 5, lane = tid & 31;
    int gid = lane >> 2, tig = lane & 3;
    int warp_m = wid >> 2, warp_n = wid & 3;      // 2 x 4 warps
    int m0 = blockIdx.y * 128, n0 = blockIdx.x * 128;

    float acc[4][4][4];
    #pragma unroll
    for (int mt = 0; mt < 4; mt++)
        #pragma unroll
        for (int nt = 0; nt < 4; nt++)
            #pragma unroll
            for (int e = 0; e < 4; e++) acc[mt][nt][e] = 0.f;

    const int nchunk = K >> 5;
    // per-thread load slots: A and B each 1024 float4 per chunk, 4 per thread
    int lr = tid >> 3;                 // row 0..31 step: r = lr + l*32
    int lc4 = (tid & 7) << 2;          // col 0..28

    float4 av[4], bv[4];
    // prologue: load chunk 0
    {
        const float* Ap = A + (size_t)m0 * K + 0;
        const float* Bp = B + (size_t)n0 * K + 0;
        #pragma unroll
        for (int l = 0; l < 4; l++) {
            int r = lr + l * 32;
            av[l] = *(const float4*)(Ap + (size_t)r * K + lc4);
            bv[l] = *(const float4*)(Bp + (size_t)r * K + lc4);
        }
        float* As = smf;
        float* Bs = smf + GBUF;
        #pragma unroll
        for (int l = 0; l < 4; l++) {
            int r = lr + l * 32;
            uint32_t* pa = (uint32_t*)(As + r * GST + lc4);
            uint32_t* pb = (uint32_t*)(Bs + r * GST + lc4);
            pa[0] = f2tf32(av[l].x); pa[1] = f2tf32(av[l].y); pa[2] = f2tf32(av[l].z); pa[3] = f2tf32(av[l].w);
            pb[0] = f2tf32(bv[l].x); pb[1] = f2tf32(bv[l].y); pb[2] = f2tf32(bv[l].z); pb[3] = f2tf32(bv[l].w);
        }
    }
    __syncthreads();

    for (int i = 0; i < nchunk; i++) {
        int buf = i & 1;
        // issue LDG for next chunk
        if (i + 1 < nchunk) {
            const float* Ap = A + (size_t)m0 * K + (i + 1) * 32;
            const float* Bp = B + (size_t)n0 * K + (i + 1) * 32;
            #pragma unroll
            for (int l = 0; l < 4; l++) {
                int r = lr + l * 32;
                av[l] = *(const float4*)(Ap + (size_t)r * K + lc4);
                bv[l] = *(const float4*)(Bp + (size_t)r * K + lc4);
            }
        }
        // compute chunk i
        const float* As = smf + buf * 2 * GBUF;
        const float* Bs = As + GBUF;
        #pragma unroll
        for (int kk = 0; kk < 4; kk++) {
            int k0 = kk * 8;
            uint32_t af[4][4], bf[4][2];
            #pragma unroll
            for (int mt = 0; mt < 4; mt++) {
                int row = warp_m * 64 + mt * 16 + gid;
                const uint32_t* p0 = (const uint32_t*)(As + row * GST + k0);
                const uint32_t* p1 = (const uint32_t*)(As + (row + 8) * GST + k0);
                af[mt][0] = p0[tig];
                af[mt][1] = p1[tig];
                af[mt][2] = p0[tig + 4];
                af[mt][3] = p1[tig + 4];
            }
            #pragma unroll
            for (int nt = 0; nt < 4; nt++) {
                int col = warp_n * 32 + nt * 8 + gid;
                const uint32_t* p = (const uint32_t*)(Bs + col * GST + k0);
                bf[nt][0] = p[tig];
                bf[nt][1] = p[tig + 4];
            }
            #pragma unroll
            for (int mt = 0; mt < 4; mt++)
                #pragma unroll
                for (int nt = 0; nt < 4; nt++) {
                    asm volatile(
                        "mma.sync.aligned.m16n8k8.row.col.f32.tf32.tf32.f32 "
                        "{%0,%1,%2,%3}, {%4,%5,%6,%7}, {%8,%9}, {%0,%1,%2,%3};"
                        : "+f"(acc[mt][nt][0]), "+f"(acc[mt][nt][1]),
                          "+f"(acc[mt][nt][2]), "+f"(acc[mt][nt][3])
                        : "r"(af[mt][0]), "r"(af[mt][1]), "r"(af[mt][2]), "r"(af[mt][3]),
                          "r"(bf[nt][0]), "r"(bf[nt][1]));
                }
        }
        // store next chunk
        if (i + 1 < nchunk) {
            float* Asn = smf + (buf ^ 1) * 2 * GBUF;
            float* Bsn = Asn + GBUF;
            #pragma unroll
            for (int l = 0; l < 4; l++) {
                int r = lr + l * 32;
                uint32_t* pa = (uint32_t*)(Asn + r * GST + lc4);
                uint32_t* pb = (uint32_t*)(Bsn + r * GST + lc4);
                pa[0] = f2tf32(av[l].x); pa[1] = f2tf32(av[l].y); pa[2] = f2tf32(av[l].z); pa[3] = f2tf32(av[l].w);
                pb[0] = f2tf32(bv[l].x); pb[1] = f2tf32(bv[l].y); pb[2] = f2tf32(bv[l].z); pb[3] = f2tf32(bv[l].w);
            }
        }
        __syncthreads();
    }

    // epilogue
    #pragma unroll
    for (int mt = 0; mt < 4; mt++) {
        #pragma unroll
        for (int nt = 0; nt < 4; nt++) {
            int row = m0 + warp_m * 64 + mt * 16 + gid;
            int col = n0 + warp_n * 32 + nt * 8 + tig * 2;
            #pragma unroll
            for (int half = 0; half < 2; half++) {
                int r = row + half * 8;
                float2 v = make_float2(acc[mt][nt][half * 2], acc[mt][nt][half * 2 + 1]);
                if (bias) {
                    float2 bv2 = *(const float2*)(bias + col);
                    v.x += bv2.x; v.y += bv2.y;
                }
                size_t off = (size_t)r * N + col;
                if (resid) {
                    float2 rv = *(const float2*)(resid + off);
                    v.x += rv.x; v.y += rv.y;
                }
                *(float2*)(C + off) = v;
            }
        }
    }
}

// ---------------- qk finish: RMSNorm per head + RoPE, write to [H,T,HD] ------
__global__ void qk_finish(const float* __restrict__ qk,
                          const float* __restrict__ qn, const float* __restrict__ kn,
                          const float* __restrict__ freqs,
                          float* __restrict__ Q, float* __restrict__ Ko, int t_off) {
    int row = blockIdx.x, h = blockIdx.y, d = threadIdx.x;
    float qv = qk[(size_t)row * (2 * D) + h * HD + d];
    float kv = qk[(size_t)row * (2 * D) + D + h * HD + d];
    __shared__ float sh[4];
    float sq = qv * qv, sk = kv * kv;
    #pragma unroll
    for (int o = 16; o > 0; o >>= 1) { sq += __shfl_xor_sync(0xffffffffu, sq, o); sk += __shfl_xor_sync(0xffffffffu, sk, o); }
    int w = d >> 5;
    if ((d & 31) == 0) { sh[w] = sq; sh[2 + w] = sk; }
    __syncthreads();
    float rq = rsqrtf((sh[0] + sh[1]) * (1.0f / HD) + 1e-6f);
    float rk = rsqrtf((sh[2] + sh[3]) * (1.0f / HD) + 1e-6f);
    __shared__ float sQ[HD], sK[HD];
    sQ[d] = qv * rq * qn[d];
    sK[d] = kv * rk * kn[d];
    __syncthreads();
    int t = t_off + row;
    int i = d >> 1;
    float cs = freqs[((size_t)t * 32 + i) * 2 + 0];
    float sn = freqs[((size_t)t * 32 + i) * 2 + 1];
    float oq, ok;
    if ((d & 1) == 0) { oq = sQ[d] * cs - sQ[d + 1] * sn; ok = sK[d] * cs - sK[d + 1] * sn; }
    else              { oq = sQ[d - 1] * sn + sQ[d] * cs; ok = sK[d - 1] * sn + sK[d] * cs; }
    size_t off = ((size_t)h * TT + t) * HD + d;
    Q[off] = oq; Ko[off] = ok;
}

// ---------------- v reshape: [rows,D] -> [H,T,HD] ----------------
__global__ void v_finish(const float* __restrict__ vt, float* __restrict__ V,
                         int rows, int t_off) {
    int idx = blockIdx.x * 256 + threadIdx.x;
    if (idx >= rows * D) return;
    int row = idx >> 10, col = idx & 1023;
    int h = col >> 6, d = col & 63;
    V[((size_t)h * TT + t_off + row) * HD + d] = vt[idx];
}

// ---------------- flash attention (fp32, causal) ----------------
#define ATS 68
__global__ void attn_kernel(const float* __restrict__ Q, const float* __restrict__ K,
                            const float* __restrict__ V, float* __restrict__ Y) {
    extern __shared__ float smemf[];
    float* QsT = smemf;
    float* KsT = QsT + 64 * ATS;
    float* Vs  = KsT + 64 * ATS;
    float* PsT = Vs  + 64 * ATS;
    int bx = blockIdx.x, h = blockIdx.y;
    int tid = threadIdx.x;
    int tx = tid & 15, ty = tid >> 4;
    const float scale = 0.125f;
    const float* Qh = Q + (size_t)h * TT * HD;
    const float* Kh = K + (size_t)h * TT * HD;
    const float* Vh = V + (size_t)h * TT * HD;
    int q0 = bx * 64;

    #pragma unroll
    for (int l = 0; l < 4; l++) {
        int e = tid + l * 256;
        int r = e >> 4, c4 = (e & 15) << 2;
        float4 v = *(const float4*)(Qh + (size_t)(q0 + r) * HD + c4);
        QsT[(c4 + 0) * ATS + r] = v.x * scale;
        QsT[(c4 + 1) * ATS + r] = v.y * scale;
        QsT[(c4 + 2) * ATS + r] = v.z * scale;
        QsT[(c4 + 3) * ATS + r] = v.w * scale;
    }
    float m[4], lsum[4], o[4][4];
    #pragma unroll
    for (int i = 0; i < 4; i++) {
        m[i] = -INFINITY; lsum[i] = 0.f;
        #pragma unroll
        for (int j = 0; j < 4; j++) o[i][j] = 0.f;
    }
    int ntiles = bx + 1;
    for (int kt = 0; kt < ntiles; kt++) {
        int k0 = kt * 64;
        __syncthreads();
        #pragma unroll
        for (int l = 0; l < 4; l++) {
            int e = tid + l * 256;
            int r = e >> 4, c4 = (e & 15) << 2;
            float4 kv = *(const float4*)(Kh + (size_t)(k0 + r) * HD + c4);
            KsT[(c4 + 0) * ATS + r] = kv.x;
            KsT[(c4 + 1) * ATS + r] = kv.y;
            KsT[(c4 + 2) * ATS + r] = kv.z;
            KsT[(c4 + 3) * ATS + r] = kv.w;
            float4 vv = *(const float4*)(Vh + (size_t)(k0 + r) * HD + c4);
            *(float4*)(Vs + r * ATS + c4) = vv;
        }
        __syncthreads();
        float s[4][4];
        #pragma unroll
        for (int i = 0; i < 4; i++)
            #pragma unroll
            for (int j = 0; j < 4; j++) s[i][j] = 0.f;
        #pragma unroll 8
        for (int kk = 0; kk < 64; kk++) {
            float4 a = *(const float4*)(QsT + kk * ATS + ty * 4);
            float4 b = *(const float4*)(KsT + kk * ATS + tx * 4);
            float ar[4] = {a.x, a.y, a.z, a.w};
            float br[4] = {b.x, b.y, b.z, b.w};
            #pragma unroll
            for (int i = 0; i < 4; i++)
                #pragma unroll
                for (int j = 0; j < 4; j++) s[i][j] += ar[i] * br[j];
        }
        #pragma unroll
        for (int i = 0; i < 4; i++) {
            int rg = q0 + ty * 4 + i;
            float rmax = -INFINITY;
            #pragma unroll
            for (int j = 0; j < 4; j++) {
                int cg = k0 + tx * 4 + j;
                if (cg > rg) s[i][j] = -INFINITY;
                rmax = fmaxf(rmax, s[i][j]);
            }
            #pragma unroll
            for (int off = 1; off < 16; off <<= 1)
                rmax = fmaxf(rmax, __shfl_xor_sync(0xffffffffu, rmax, off));
            float nm = fmaxf(m[i], rmax);
            float corr = expf(m[i] - nm);
            m[i] = nm;
            float psum = 0.f;
            #pragma unroll
            for (int j = 0; j < 4; j++) {
                float p = expf(s[i][j] - nm);
                PsT[(tx * 4 + j) * ATS + ty * 4 + i] = p;
                psum += p;
            }
            #pragma unroll
            for (int off = 1; off < 16; off <<= 1)
                psum += __shfl_xor_sync(0xffffffffu, psum, off);
            lsum[i] = lsum[i] * corr + psum;
            #pragma unroll
            for (int j = 0; j < 4; j++) o[i][j] *= corr;
        }
        __syncthreads();
        #pragma unroll 8
        for (int key = 0; key < 64; key++) {
            float4 a = *(const float4*)(PsT + key * ATS + ty * 4);
            float4 b = *(const float4*)(Vs + key * ATS + tx * 4);
            float ar[4] = {a.x, a.y, a.z, a.w};
            float br[4] = {b.x, b.y, b.z, b.w};
            #pragma unroll
            for (int i = 0; i < 4; i++)
                #pragma unroll
                for (int j = 0; j < 4; j++) o[i][j] += ar[i] * br[j];
        }
    }
    #pragma unroll
    for (int i = 0; i < 4; i++) {
        float inv = 1.0f / lsum[i];
        int t = q0 + ty * 4 + i;
        #pragma unroll
        for (int j = 0; j < 4; j++)
            Y[(size_t)t * D + h * HD + tx * 4 + j] = o[i][j] * inv;
    }
}

// ---------------- SiLU gate ----------------
__global__ void silu_gate(const float* __restrict__ a, const float* __restrict__ b,
                          float* __restrict__ g, int n) {
    int i = blockIdx.x * 256 + threadIdx.x;
    if (i < n) {
        float x = a[i];
        g[i] = (x / (1.0f + expf(-x))) * b[i];
    }
}

// ---------------- host launcher ----------------
static inline dim3 gg(int M, int N) { return dim3(N / 128, M / 128); }

extern "C" void kernel_launch(void* const* d_in, const int* in_sizes, int n_in,
                              void* d_out, int out_size) {
    const float* x        = (const float*)d_in[0];
    const float* c        = (const float*)d_in[1];
    const float* freqs    = (const float*)d_in[2];
    const float* px_qk_w  = (const float*)d_in[3];
    const float* px_qn    = (const float*)d_in[4];
    const float* px_kn    = (const float*)d_in[5];
    const float* px_v_w   = (const float*)d_in[6];
    const float* px_v_b   = (const float*)d_in[7];
    const float* pc_qk_w  = (const float*)d_in[8];
    const float* pc_qn    = (const float*)d_in[9];
    const float* pc_kn    = (const float*)d_in[10];
    const float* pc_v_w   = (const float*)d_in[11];
    const float* pc_v_b   = (const float*)d_in[12];
    const float* p1_proj_w = (const float*)d_in[13];
    const float* p1_proj_b = (const float*)d_in[14];
    const float* p1_w1    = (const float*)d_in[15];
    const float* p1_b1    = (const float*)d_in[16];
    const float* p1_w3    = (const float*)d_in[17];
    const float* p1_b3    = (const float*)d_in[18];
    const float* p1_w2    = (const float*)d_in[19];
    const float* p1_b2    = (const float*)d_in[20];
    const float* p2_proj_w = (const float*)d_in[21];
    const float* p2_proj_b = (const float*)d_in[22];
    const float* p2_w1    = (const float*)d_in[23];
    const float* p2_b1    = (const float*)d_in[24];
    const float* p2_w3    = (const float*)d_in[25];
    const float* p2_b3    = (const float*)d_in[26];
    const float* p2_w2    = (const float*)d_in[27];
    const float* p2_b2    = (const float*)d_in[28];
    float* out = (float*)d_out;

    float *xln, *cln, *qk, *vt, *q, *k, *v, *y, *x1, *h, *t1, *t3;
    cudaGetSymbolAddress((void**)&xln, g_xln);
    cudaGetSymbolAddress((void**)&cln, g_cln);
    cudaGetSymbolAddress((void**)&qk,  g_qk);
    cudaGetSymbolAddress((void**)&vt,  g_vt);
    cudaGetSymbolAddress((void**)&q,   g_q);
    cudaGetSymbolAddress((void**)&k,   g_k);
    cudaGetSymbolAddress((void**)&v,   g_v);
    cudaGetSymbolAddress((void**)&y,   g_y);
    cudaGetSymbolAddress((void**)&x1,  g_x1);
    cudaGetSymbolAddress((void**)&h,   g_h);
    cudaGetSymbolAddress((void**)&t1,  g_t1);
    cudaGetSymbolAddress((void**)&t3,  g_t3);

    const int SMEM_ATTN = 4 * 64 * ATS * 4;
    cudaFuncSetAttribute(attn_kernel, cudaFuncAttributeMaxDynamicSharedMemorySize, SMEM_ATTN);
    cudaFuncSetAttribute(mma_gemm, cudaFuncAttributeMaxDynamicSharedMemorySize, MMG_SMEM);

    // 1) LayerNorm both streams
    ln_kernel<<<L_X, 256>>>(x, xln);
    ln_kernel<<<S_C, 256>>>(c, cln);

    // 2) c stream QKV (t_off = 0)
    mma_gemm<<<gg(S_C, 2 * D), 256, MMG_SMEM>>>(cln, pc_qk_w, nullptr, nullptr, qk, S_C, 2 * D, D);
    qk_finish<<<dim3(S_C, H), HD>>>(qk, pc_qn, pc_kn, freqs, q, k, 0);
    mma_gemm<<<gg(S_C, D), 256, MMG_SMEM>>>(cln, pc_v_w, pc_v_b, nullptr, vt, S_C, D, D);
    v_finish<<<(S_C * D + 255) / 256, 256>>>(vt, v, S_C, 0);

    // 3) x stream QKV (t_off = S_C)
    mma_gemm<<<gg(L_X, 2 * D), 256, MMG_SMEM>>>(xln, px_qk_w, nullptr, nullptr, qk, L_X, 2 * D, D);
    qk_finish<<<dim3(L_X, H), HD>>>(qk, px_qn, px_kn, freqs, q, k, S_C);
    mma_gemm<<<gg(L_X, D), 256, MMG_SMEM>>>(xln, px_v_w, px_v_b, nullptr, vt, L_X, D, D);
    v_finish<<<(L_X * D + 255) / 256, 256>>>(vt, v, L_X, S_C);

    // 4) causal attention
    attn_kernel<<<dim3(TT / 64, H), 256, SMEM_ATTN>>>(q, k, v, y);

    // 5) post for x stream (y rows [S_C, TT)) -> out[0 : L_X*D)
    const float* yx = y + (size_t)S_C * D;
    mma_gemm<<<gg(L_X, D), 256, MMG_SMEM>>>(yx, p1_proj_w, p1_proj_b, x, x1, L_X, D, D);
    ln_kernel<<<L_X, 256>>>(x1, h);
    mma_gemm<<<gg(L_X, FF), 256, MMG_SMEM>>>(h, p1_w1, p1_b1, nullptr, t1, L_X, FF, D);
    mma_gemm<<<gg(L_X, FF), 256, MMG_SMEM>>>(h, p1_w3, p1_b3, nullptr, t3, L_X, FF, D);
    silu_gate<<<(L_X * FF + 255) / 256, 256>>>(t1, t3, t1, L_X * FF);
    mma_gemm<<<gg(L_X, D), 256, MMG_SMEM>>>(t1, p1_w2, p1_b2, x1, out, L_X, D, FF);

    // 6) post for c stream (y rows [0, S_C)) -> out[L_X*D : ]
    mma_gemm<<<gg(S_C, D), 256, MMG_SMEM>>>(y, p2_proj_w, p2_proj_b, c, x1, S_C, D, D);
    ln_kernel<<<S_C, 256>>>(x1, h);
    mma_gemm<<<gg(S_C, FF), 256, MMG_SMEM>>>(h, p2_w1, p2_b1, nullptr, t1, S_C, FF, D);
    mma_gemm<<<gg(S_C, FF), 256, MMG_SMEM>>>(h, p2_w3, p2_b3, nullptr, t3, S_C, FF, D);
    silu_gate<<<(S_C * FF + 255) / 256, 256>>>(t1, t3, t1, S_C * FF);
    mma_gemm<<<gg(S_C, D), 256, MMG_SMEM>>>(t1, p2_w2, p2_b2, x1, out + (size_t)L_X * D, S_C, D, FF);
}

// round 4
// speedup vs baseline: 3.5986x; 1.1790x over previous
#include <cuda_runtime.h>
#include <cuda_bf16.h>
#include <cstdint>
#include <math.h>

// ---------------- problem constants ----------------
#define L_X   1536
#define S_C   512
#define TT    2048          // L_X + S_C
#define D     1024
#define H     16
#define HD    64
#define FF    4096

// ---------------- scratch (device globals; no cudaMalloc allowed) ----------
__device__ float g_xln[L_X * D];
__device__ float g_cln[S_C * D];
__device__ float g_qk [L_X * 2 * D];      // reused per stream
__device__ float g_vt [L_X * D];          // reused per stream
__device__ float g_q  [H * TT * HD];
__device__ float g_k  [H * TT * HD];
__device__ float g_v  [H * TT * HD];
__device__ float g_y  [TT * D];
__device__ float g_x1 [L_X * D];          // reused per stream
__device__ float g_h  [L_X * D];          // reused per stream
__device__ float g_t1 [L_X * FF];         // reused per stream
__device__ float g_t3 [L_X * FF];         // reused per stream

// ---------------- utils ----------------
__device__ __forceinline__ float warpSum(float v) {
    #pragma unroll
    for (int o = 16; o > 0; o >>= 1) v += __shfl_xor_sync(0xffffffffu, v, o);
    return v;
}
__device__ __forceinline__ uint32_t f2tf32(float v) {
    uint32_t r;
    asm("cvt.rna.tf32.f32 %0, %1;" : "=r"(r) : "f"(v));
    return r;
}
__device__ __forceinline__ void mma_tf32(float* d, const uint32_t* a, const uint32_t* b) {
    asm volatile(
        "mma.sync.aligned.m16n8k8.row.col.f32.tf32.tf32.f32 "
        "{%0,%1,%2,%3}, {%4,%5,%6,%7}, {%8,%9}, {%0,%1,%2,%3};"
        : "+f"(d[0]), "+f"(d[1]), "+f"(d[2]), "+f"(d[3])
        : "r"(a[0]), "r"(a[1]), "r"(a[2]), "r"(a[3]), "r"(b[0]), "r"(b[1]));
}

// ---------------- LayerNorm (D=1024, one block per row) ----------------
__global__ void ln_kernel(const float* __restrict__ in, float* __restrict__ out) {
    int row = blockIdx.x;
    const float* x = in + (size_t)row * D;
    float s = 0.f, ss = 0.f;
    for (int i = threadIdx.x; i < D; i += 256) {
        float v = x[i]; s += v; ss += v * v;
    }
    __shared__ float shs[8], shss[8];
    float ws = warpSum(s), wss = warpSum(ss);
    int w = threadIdx.x >> 5;
    if ((threadIdx.x & 31) == 0) { shs[w] = ws; shss[w] = wss; }
    __syncthreads();
    float ts = 0.f, tss = 0.f;
    #pragma unroll
    for (int i = 0; i < 8; i++) { ts += shs[i]; tss += shss[i]; }
    float mean = ts * (1.0f / D);
    float var  = tss * (1.0f / D) - mean * mean;
    float inv  = rsqrtf(var + 1e-6f);
    float* o = out + (size_t)row * D;
    for (int i = threadIdx.x; i < D; i += 256)
        o[i] = (x[i] - mean) * inv;
}

// ======================================================================
// tf32 mma.sync GEMM: C[M,N] = A[M,K] @ B[N,K]^T (+bias) (+resid)
// (unchanged from R3 — proven 170+ TF/s)
// ======================================================================
#define GST 36
#define GBUF (128 * GST)
#define MMG_SMEM (4 * GBUF * 4)

__global__ __launch_bounds__(256)
void mma_gemm(const float* __restrict__ A, const float* __restrict__ B,
              const float* __restrict__ bias, const float* __restrict__ resid,
              float* __restrict__ C, int M, int N, int K) {
    extern __shared__ float smf[];
    int tid = threadIdx.x;
    int wid = tid >> 5, lane = tid & 31;
    int gid = lane >> 2, tig = lane & 3;
    int warp_m = wid >> 2, warp_n = wid & 3;
    int m0 = blockIdx.y * 128, n0 = blockIdx.x * 128;

    float acc[4][4][4];
    #pragma unroll
    for (int mt = 0; mt < 4; mt++)
        #pragma unroll
        for (int nt = 0; nt < 4; nt++)
            #pragma unroll
            for (int e = 0; e < 4; e++) acc[mt][nt][e] = 0.f;

    const int nchunk = K >> 5;
    int lr = tid >> 3;
    int lc4 = (tid & 7) << 2;

    float4 av[4], bv[4];
    {
        const float* Ap = A + (size_t)m0 * K + 0;
        const float* Bp = B + (size_t)n0 * K + 0;
        #pragma unroll
        for (int l = 0; l < 4; l++) {
            int r = lr + l * 32;
            av[l] = *(const float4*)(Ap + (size_t)r * K + lc4);
            bv[l] = *(const float4*)(Bp + (size_t)r * K + lc4);
        }
        float* As = smf;
        float* Bs = smf + GBUF;
        #pragma unroll
        for (int l = 0; l < 4; l++) {
            int r = lr + l * 32;
            uint32_t* pa = (uint32_t*)(As + r * GST + lc4);
            uint32_t* pb = (uint32_t*)(Bs + r * GST + lc4);
            pa[0] = f2tf32(av[l].x); pa[1] = f2tf32(av[l].y); pa[2] = f2tf32(av[l].z); pa[3] = f2tf32(av[l].w);
            pb[0] = f2tf32(bv[l].x); pb[1] = f2tf32(bv[l].y); pb[2] = f2tf32(bv[l].z); pb[3] = f2tf32(bv[l].w);
        }
    }
    __syncthreads();

    for (int i = 0; i < nchunk; i++) {
        int buf = i & 1;
        if (i + 1 < nchunk) {
            const float* Ap = A + (size_t)m0 * K + (i + 1) * 32;
            const float* Bp = B + (size_t)n0 * K + (i + 1) * 32;
            #pragma unroll
            for (int l = 0; l < 4; l++) {
                int r = lr + l * 32;
                av[l] = *(const float4*)(Ap + (size_t)r * K + lc4);
                bv[l] = *(const float4*)(Bp + (size_t)r * K + lc4);
            }
        }
        const float* As = smf + buf * 2 * GBUF;
        const float* Bs = As + GBUF;
        #pragma unroll
        for (int kk = 0; kk < 4; kk++) {
            int k0 = kk * 8;
            uint32_t af[4][4], bf[4][2];
            #pragma unroll
            for (int mt = 0; mt < 4; mt++) {
                int row = warp_m * 64 + mt * 16 + gid;
                const uint32_t* p0 = (const uint32_t*)(As + row * GST + k0);
                const uint32_t* p1 = (const uint32_t*)(As + (row + 8) * GST + k0);
                af[mt][0] = p0[tig];
                af[mt][1] = p1[tig];
                af[mt][2] = p0[tig + 4];
                af[mt][3] = p1[tig + 4];
            }
            #pragma unroll
            for (int nt = 0; nt < 4; nt++) {
                int col = warp_n * 32 + nt * 8 + gid;
                const uint32_t* p = (const uint32_t*)(Bs + col * GST + k0);
                bf[nt][0] = p[tig];
                bf[nt][1] = p[tig + 4];
            }
            #pragma unroll
            for (int mt = 0; mt < 4; mt++)
                #pragma unroll
                for (int nt = 0; nt < 4; nt++)
                    mma_tf32(acc[mt][nt], af[mt], bf[nt]);
        }
        if (i + 1 < nchunk) {
            float* Asn = smf + (buf ^ 1) * 2 * GBUF;
            float* Bsn = Asn + GBUF;
            #pragma unroll
            for (int l = 0; l < 4; l++) {
                int r = lr + l * 32;
                uint32_t* pa = (uint32_t*)(Asn + r * GST + lc4);
                uint32_t* pb = (uint32_t*)(Bsn + r * GST + lc4);
                pa[0] = f2tf32(av[l].x); pa[1] = f2tf32(av[l].y); pa[2] = f2tf32(av[l].z); pa[3] = f2tf32(av[l].w);
                pb[0] = f2tf32(bv[l].x); pb[1] = f2tf32(bv[l].y); pb[2] = f2tf32(bv[l].z); pb[3] = f2tf32(bv[l].w);
            }
        }
        __syncthreads();
    }

    #pragma unroll
    for (int mt = 0; mt < 4; mt++) {
        #pragma unroll
        for (int nt = 0; nt < 4; nt++) {
            int row = m0 + warp_m * 64 + mt * 16 + gid;
            int col = n0 + warp_n * 32 + nt * 8 + tig * 2;
            #pragma unroll
            for (int half = 0; half < 2; half++) {
                int r = row + half * 8;
                float2 v = make_float2(acc[mt][nt][half * 2], acc[mt][nt][half * 2 + 1]);
                if (bias) {
                    float2 bv2 = *(const float2*)(bias + col);
                    v.x += bv2.x; v.y += bv2.y;
                }
                size_t off = (size_t)r * N + col;
                if (resid) {
                    float2 rv = *(const float2*)(resid + off);
                    v.x += rv.x; v.y += rv.y;
                }
                *(float2*)(C + off) = v;
            }
        }
    }
}

// ---------------- qk finish: RMSNorm per head + RoPE, write to [H,T,HD] ------
__global__ void qk_finish(const float* __restrict__ qk,
                          const float* __restrict__ qn, const float* __restrict__ kn,
                          const float* __restrict__ freqs,
                          float* __restrict__ Q, float* __restrict__ Ko, int t_off) {
    int row = blockIdx.x, h = blockIdx.y, d = threadIdx.x;
    float qv = qk[(size_t)row * (2 * D) + h * HD + d];
    float kv = qk[(size_t)row * (2 * D) + D + h * HD + d];
    __shared__ float sh[4];
    float sq = qv * qv, sk = kv * kv;
    #pragma unroll
    for (int o = 16; o > 0; o >>= 1) { sq += __shfl_xor_sync(0xffffffffu, sq, o); sk += __shfl_xor_sync(0xffffffffu, sk, o); }
    int w = d >> 5;
    if ((d & 31) == 0) { sh[w] = sq; sh[2 + w] = sk; }
    __syncthreads();
    float rq = rsqrtf((sh[0] + sh[1]) * (1.0f / HD) + 1e-6f);
    float rk = rsqrtf((sh[2] + sh[3]) * (1.0f / HD) + 1e-6f);
    __shared__ float sQ[HD], sK[HD];
    sQ[d] = qv * rq * qn[d];
    sK[d] = kv * rk * kn[d];
    __syncthreads();
    int t = t_off + row;
    int i = d >> 1;
    float cs = freqs[((size_t)t * 32 + i) * 2 + 0];
    float sn = freqs[((size_t)t * 32 + i) * 2 + 1];
    float oq, ok;
    if ((d & 1) == 0) { oq = sQ[d] * cs - sQ[d + 1] * sn; ok = sK[d] * cs - sK[d + 1] * sn; }
    else              { oq = sQ[d - 1] * sn + sQ[d] * cs; ok = sK[d - 1] * sn + sK[d] * cs; }
    size_t off = ((size_t)h * TT + t) * HD + d;
    Q[off] = oq; Ko[off] = ok;
}

// ---------------- v reshape: [rows,D] -> [H,T,HD] ----------------
__global__ void v_finish(const float* __restrict__ vt, float* __restrict__ V,
                         int rows, int t_off) {
    int idx = blockIdx.x * 256 + threadIdx.x;
    if (idx >= rows * D) return;
    int row = idx >> 10, col = idx & 1023;
    int h = col >> 6, d = col & 63;
    V[((size_t)h * TT + t_off + row) * HD + d] = vt[idx];
}

// ======================================================================
// Tensor-core flash attention (tf32 mma, causal).
// Q,K,V: [H][T][64]; Y: [T][D]. Grid (T/128, H), 256 threads.
// Each warp owns 16 query rows. Q prescaled by 0.125*log2e; exp2f softmax.
// smem: Ks[64][68] | VsT[64][68] | Pw[128][68] (Pw doubles as Q stage)
// ======================================================================
#define AST 68
#define ATN_SMEM ((64 + 64 + 128) * AST * 4)

__global__ __launch_bounds__(256)
void attn_tc(const float* __restrict__ Q, const float* __restrict__ K,
             const float* __restrict__ V, float* __restrict__ Y) {
    extern __shared__ float sm[];
    float* Ks  = sm;                  // [key][dim]
    float* VsT = sm + 64 * AST;       // [dim][key]
    float* Pw  = sm + 128 * AST;      // [128][AST]
    int tid = threadIdx.x, wid = tid >> 5, lane = tid & 31;
    int gid = lane >> 2, tig = lane & 3;
    int bxr = gridDim.x - 1 - blockIdx.x;          // heavy tiles first
    int h = blockIdx.y;
    int q0 = bxr * 128;
    const float* Qh = Q + (size_t)h * TT * HD;
    const float* Kh = K + (size_t)h * TT * HD;
    const float* Vh = V + (size_t)h * TT * HD;
    const float QSC = 0.125f * 1.4426950408889634f;

    // stage Q (scaled, tf32) into Pw
    #pragma unroll
    for (int l = 0; l < 8; l++) {
        int e = tid + l * 256;
        int r = e >> 4, c4 = (e & 15) << 2;
        float4 v = *(const float4*)(Qh + (size_t)(q0 + r) * HD + c4);
        uint32_t* p = (uint32_t*)(Pw + r * AST + c4);
        p[0] = f2tf32(v.x * QSC); p[1] = f2tf32(v.y * QSC);
        p[2] = f2tf32(v.z * QSC); p[3] = f2tf32(v.w * QSC);
    }
    __syncthreads();
    // fragment Q: warp rows [wid*16, wid*16+16)
    uint32_t qf[8][4];
    int qrow = wid * 16 + gid;
    #pragma unroll
    for (int ks = 0; ks < 8; ks++) {
        int k0 = ks * 8;
        const uint32_t* p0 = (const uint32_t*)(Pw + qrow * AST + k0);
        const uint32_t* p1 = (const uint32_t*)(Pw + (qrow + 8) * AST + k0);
        qf[ks][0] = p0[tig];
        qf[ks][1] = p1[tig];
        qf[ks][2] = p0[tig + 4];
        qf[ks][3] = p1[tig + 4];
    }
    __syncwarp();

    float ofr[8][4];
    #pragma unroll
    for (int ot = 0; ot < 8; ot++)
        #pragma unroll
        for (int e = 0; e < 4; e++) ofr[ot][e] = 0.f;
    float m0r = -INFINITY, m1r = -INFINITY, l0r = 0.f, l1r = 0.f;

    int ntile = 2 * bxr + 2;
    for (int kt = 0; kt < ntile; kt++) {
        int k0g = kt * 64;
        __syncthreads();
        // load K tile and V tile (transposed), tf32
        #pragma unroll
        for (int l = 0; l < 4; l++) {
            int e = tid + l * 256;
            int r = e >> 4, c4 = (e & 15) << 2;
            float4 kv = *(const float4*)(Kh + (size_t)(k0g + r) * HD + c4);
            uint32_t* pk = (uint32_t*)(Ks + r * AST + c4);
            pk[0] = f2tf32(kv.x); pk[1] = f2tf32(kv.y); pk[2] = f2tf32(kv.z); pk[3] = f2tf32(kv.w);
            float4 vv = *(const float4*)(Vh + (size_t)(k0g + r) * HD + c4);
            *(uint32_t*)(VsT + (c4 + 0) * AST + r) = f2tf32(vv.x);
            *(uint32_t*)(VsT + (c4 + 1) * AST + r) = f2tf32(vv.y);
            *(uint32_t*)(VsT + (c4 + 2) * AST + r) = f2tf32(vv.z);
            *(uint32_t*)(VsT + (c4 + 3) * AST + r) = f2tf32(vv.w);
        }
        __syncthreads();
        // S = Q K^T : 8 n-tiles x 8 k-steps
        float sacc[8][4];
        #pragma unroll
        for (int nt = 0; nt < 8; nt++)
            #pragma unroll
            for (int e = 0; e < 4; e++) sacc[nt][e] = 0.f;
        #pragma unroll
        for (int ks = 0; ks < 8; ks++) {
            int k0 = ks * 8;
            #pragma unroll
            for (int nt = 0; nt < 8; nt++) {
                uint32_t bf[2];
                const uint32_t* p = (const uint32_t*)(Ks + (nt * 8 + gid) * AST + k0);
                bf[0] = p[tig];
                bf[1] = p[tig + 4];
                mma_tf32(sacc[nt], qf[ks], bf);
            }
        }
        // causal mask (only diagonal tiles)
        if (kt >= ntile - 2) {
            int r0 = q0 + wid * 16 + gid;
            #pragma unroll
            for (int nt = 0; nt < 8; nt++) {
                int c0 = k0g + nt * 8 + tig * 2;
                if (c0 > r0)     sacc[nt][0] = -INFINITY;
                if (c0 + 1 > r0) sacc[nt][1] = -INFINITY;
                if (c0 > r0 + 8)     sacc[nt][2] = -INFINITY;
                if (c0 + 1 > r0 + 8) sacc[nt][3] = -INFINITY;
            }
        }
        // online softmax on fragments (rows gid, gid+8)
        float tm0 = -INFINITY, tm1 = -INFINITY;
        #pragma unroll
        for (int nt = 0; nt < 8; nt++) {
            tm0 = fmaxf(tm0, fmaxf(sacc[nt][0], sacc[nt][1]));
            tm1 = fmaxf(tm1, fmaxf(sacc[nt][2], sacc[nt][3]));
        }
        #pragma unroll
        for (int o = 1; o < 4; o <<= 1) {
            tm0 = fmaxf(tm0, __shfl_xor_sync(0xffffffffu, tm0, o));
            tm1 = fmaxf(tm1, __shfl_xor_sync(0xffffffffu, tm1, o));
        }
        float nm0 = fmaxf(m0r, tm0), nm1 = fmaxf(m1r, tm1);
        float c0 = exp2f(m0r - nm0), c1 = exp2f(m1r - nm1);
        m0r = nm0; m1r = nm1;
        float ps0 = 0.f, ps1 = 0.f;
        #pragma unroll
        for (int nt = 0; nt < 8; nt++) {
            float p00 = exp2f(sacc[nt][0] - nm0);
            float p01 = exp2f(sacc[nt][1] - nm0);
            float p10 = exp2f(sacc[nt][2] - nm1);
            float p11 = exp2f(sacc[nt][3] - nm1);
            ps0 += p00 + p01; ps1 += p10 + p11;
            uint32_t* pr0 = (uint32_t*)(Pw + (wid * 16 + gid) * AST + nt * 8 + tig * 2);
            uint32_t* pr1 = (uint32_t*)(Pw + (wid * 16 + gid + 8) * AST + nt * 8 + tig * 2);
            pr0[0] = f2tf32(p00); pr0[1] = f2tf32(p01);
            pr1[0] = f2tf32(p10); pr1[1] = f2tf32(p11);
        }
        #pragma unroll
        for (int o = 1; o < 4; o <<= 1) {
            ps0 += __shfl_xor_sync(0xffffffffu, ps0, o);
            ps1 += __shfl_xor_sync(0xffffffffu, ps1, o);
        }
        l0r = l0r * c0 + ps0;
        l1r = l1r * c1 + ps1;
        #pragma unroll
        for (int ot = 0; ot < 8; ot++) {
            ofr[ot][0] *= c0; ofr[ot][1] *= c0;
            ofr[ot][2] *= c1; ofr[ot][3] *= c1;
        }
        __syncwarp();
        // O += P V  (A = Pw slice, B = VsT)
        #pragma unroll
        for (int ks = 0; ks < 8; ks++) {
            int k0 = ks * 8;
            uint32_t af[4];
            const uint32_t* p0 = (const uint32_t*)(Pw + (wid * 16 + gid) * AST + k0);
            const uint32_t* p1 = (const uint32_t*)(Pw + (wid * 16 + gid + 8) * AST + k0);
            af[0] = p0[tig];
            af[1] = p1[tig];
            af[2] = p0[tig + 4];
            af[3] = p1[tig + 4];
            #pragma unroll
            for (int ot = 0; ot < 8; ot++) {
                uint32_t bf[2];
                const uint32_t* p = (const uint32_t*)(VsT + (ot * 8 + gid) * AST + k0);
                bf[0] = p[tig];
                bf[1] = p[tig + 4];
                mma_tf32(ofr[ot], af, bf);
            }
        }
    }
    // epilogue
    float i0 = 1.0f / l0r, i1 = 1.0f / l1r;
    int t0 = q0 + wid * 16 + gid, t1 = t0 + 8;
    #pragma unroll
    for (int ot = 0; ot < 8; ot++) {
        int col = h * HD + ot * 8 + tig * 2;
        *(float2*)(Y + (size_t)t0 * D + col) = make_float2(ofr[ot][0] * i0, ofr[ot][1] * i0);
        *(float2*)(Y + (size_t)t1 * D + col) = make_float2(ofr[ot][2] * i1, ofr[ot][3] * i1);
    }
}

// ---------------- SiLU gate ----------------
__global__ void silu_gate(const float* __restrict__ a, const float* __restrict__ b,
                          float* __restrict__ g, int n) {
    int i = blockIdx.x * 256 + threadIdx.x;
    if (i < n) {
        float x = a[i];
        g[i] = (x / (1.0f + expf(-x))) * b[i];
    }
}

// ---------------- host launcher ----------------
static inline dim3 gg(int M, int N) { return dim3(N / 128, M / 128); }

extern "C" void kernel_launch(void* const* d_in, const int* in_sizes, int n_in,
                              void* d_out, int out_size) {
    const float* x        = (const float*)d_in[0];
    const float* c        = (const float*)d_in[1];
    const float* freqs    = (const float*)d_in[2];
    const float* px_qk_w  = (const float*)d_in[3];
    const float* px_qn    = (const float*)d_in[4];
    const float* px_kn    = (const float*)d_in[5];
    const float* px_v_w   = (const float*)d_in[6];
    const float* px_v_b   = (const float*)d_in[7];
    const float* pc_qk_w  = (const float*)d_in[8];
    const float* pc_qn    = (const float*)d_in[9];
    const float* pc_kn    = (const float*)d_in[10];
    const float* pc_v_w   = (const float*)d_in[11];
    const float* pc_v_b   = (const float*)d_in[12];
    const float* p1_proj_w = (const float*)d_in[13];
    const float* p1_proj_b = (const float*)d_in[14];
    const float* p1_w1    = (const float*)d_in[15];
    const float* p1_b1    = (const float*)d_in[16];
    const float* p1_w3    = (const float*)d_in[17];
    const float* p1_b3    = (const float*)d_in[18];
    const float* p1_w2    = (const float*)d_in[19];
    const float* p1_b2    = (const float*)d_in[20];
    const float* p2_proj_w = (const float*)d_in[21];
    const float* p2_proj_b = (const float*)d_in[22];
    const float* p2_w1    = (const float*)d_in[23];
    const float* p2_b1    = (const float*)d_in[24];
    const float* p2_w3    = (const float*)d_in[25];
    const float* p2_b3    = (const float*)d_in[26];
    const float* p2_w2    = (const float*)d_in[27];
    const float* p2_b2    = (const float*)d_in[28];
    float* out = (float*)d_out;

    float *xln, *cln, *qk, *vt, *q, *k, *v, *y, *x1, *h, *t1, *t3;
    cudaGetSymbolAddress((void**)&xln, g_xln);
    cudaGetSymbolAddress((void**)&cln, g_cln);
    cudaGetSymbolAddress((void**)&qk,  g_qk);
    cudaGetSymbolAddress((void**)&vt,  g_vt);
    cudaGetSymbolAddress((void**)&q,   g_q);
    cudaGetSymbolAddress((void**)&k,   g_k);
    cudaGetSymbolAddress((void**)&v,   g_v);
    cudaGetSymbolAddress((void**)&y,   g_y);
    cudaGetSymbolAddress((void**)&x1,  g_x1);
    cudaGetSymbolAddress((void**)&h,   g_h);
    cudaGetSymbolAddress((void**)&t1,  g_t1);
    cudaGetSymbolAddress((void**)&t3,  g_t3);

    cudaFuncSetAttribute(attn_tc, cudaFuncAttributeMaxDynamicSharedMemorySize, ATN_SMEM);
    cudaFuncSetAttribute(mma_gemm, cudaFuncAttributeMaxDynamicSharedMemorySize, MMG_SMEM);

    // 1) LayerNorm both streams
    ln_kernel<<<L_X, 256>>>(x, xln);
    ln_kernel<<<S_C, 256>>>(c, cln);

    // 2) c stream QKV (t_off = 0)
    mma_gemm<<<gg(S_C, 2 * D), 256, MMG_SMEM>>>(cln, pc_qk_w, nullptr, nullptr, qk, S_C, 2 * D, D);
    qk_finish<<<dim3(S_C, H), HD>>>(qk, pc_qn, pc_kn, freqs, q, k, 0);
    mma_gemm<<<gg(S_C, D), 256, MMG_SMEM>>>(cln, pc_v_w, pc_v_b, nullptr, vt, S_C, D, D);
    v_finish<<<(S_C * D + 255) / 256, 256>>>(vt, v, S_C, 0);

    // 3) x stream QKV (t_off = S_C)
    mma_gemm<<<gg(L_X, 2 * D), 256, MMG_SMEM>>>(xln, px_qk_w, nullptr, nullptr, qk, L_X, 2 * D, D);
    qk_finish<<<dim3(L_X, H), HD>>>(qk, px_qn, px_kn, freqs, q, k, S_C);
    mma_gemm<<<gg(L_X, D), 256, MMG_SMEM>>>(xln, px_v_w, px_v_b, nullptr, vt, L_X, D, D);
    v_finish<<<(L_X * D + 255) / 256, 256>>>(vt, v, L_X, S_C);

    // 4) causal attention (tensor cores)
    attn_tc<<<dim3(TT / 128, H), 256, ATN_SMEM>>>(q, k, v, y);

    // 5) post for x stream (y rows [S_C, TT)) -> out[0 : L_X*D)
    const float* yx = y + (size_t)S_C * D;
    mma_gemm<<<gg(L_X, D), 256, MMG_SMEM>>>(yx, p1_proj_w, p1_proj_b, x, x1, L_X, D, D);
    ln_kernel<<<L_X, 256>>>(x1, h);
    mma_gemm<<<gg(L_X, FF), 256, MMG_SMEM>>>(h, p1_w1, p1_b1, nullptr, t1, L_X, FF, D);
    mma_gemm<<<gg(L_X, FF), 256, MMG_SMEM>>>(h, p1_w3, p1_b3, nullptr, t3, L_X, FF, D);
    silu_gate<<<(L_X * FF + 255) / 256, 256>>>(t1, t3, t1, L_X * FF);
    mma_gemm<<<gg(L_X, D), 256, MMG_SMEM>>>(t1, p1_w2, p1_b2, x1, out, L_X, D, FF);

    // 6) post for c stream (y rows [0, S_C)) -> out[L_X*D : ]
    mma_gemm<<<gg(S_C, D), 256, MMG_SMEM>>>(y, p2_proj_w, p2_proj_b, c, x1, S_C, D, D);
    ln_kernel<<<S_C, 256>>>(x1, h);
    mma_gemm<<<gg(S_C, FF), 256, MMG_SMEM>>>(h, p2_w1, p2_b1, nullptr, t1, S_C, FF, D);
    mma_gemm<<<gg(S_C, FF), 256, MMG_SMEM>>>(h, p2_w3, p2_b3, nullptr, t3, S_C, FF, D);
    silu_gate<<<(S_C * FF + 255) / 256, 256>>>(t1, t3, t1, S_C * FF);
    mma_gemm<<<gg(S_C, D), 256, MMG_SMEM>>>(t1, p2_w2, p2_b2, x1, out + (size_t)L_X * D, S_C, D, FF);
}

// round 5
// speedup vs baseline: 5.0354x; 1.3993x over previous
#include <cuda_runtime.h>
#include <cuda_bf16.h>
#include <cstdint>
#include <math.h>

// ---------------- problem constants ----------------
#define L_X   1536
#define S_C   512
#define TT    2048          // L_X + S_C
#define D     1024
#define H     16
#define HD    64
#define FF    4096

// ---------------- scratch (device globals; no cudaMalloc allowed) ----------
__device__ float g_xln[L_X * D];
__device__ float g_cln[S_C * D];
__device__ float g_qkx[L_X * 2 * D];
__device__ float g_qkc[S_C * 2 * D];
__device__ float g_vtx[L_X * D];
__device__ float g_vtc[S_C * D];
__device__ float g_q  [H * TT * HD];
__device__ float g_k  [H * TT * HD];
__device__ float g_v  [H * TT * HD];
__device__ float g_y  [TT * D];
__device__ float g_x1x[L_X * D];
__device__ float g_x1c[S_C * D];
__device__ float g_hx [L_X * D];
__device__ float g_hc [S_C * D];
__device__ float g_t1x[L_X * FF];
__device__ float g_t3x[L_X * FF];
__device__ float g_t1c[S_C * FF];
__device__ float g_t3c[S_C * FF];

// ---------------- utils ----------------
__device__ __forceinline__ float warpSum(float v) {
    #pragma unroll
    for (int o = 16; o > 0; o >>= 1) v += __shfl_xor_sync(0xffffffffu, v, o);
    return v;
}
__device__ __forceinline__ uint32_t f2tf32(float v) {
    uint32_t r;
    asm("cvt.rna.tf32.f32 %0, %1;" : "=r"(r) : "f"(v));
    return r;
}
__device__ __forceinline__ void mma_tf32(float* d, const uint32_t* a, const uint32_t* b) {
    asm volatile(
        "mma.sync.aligned.m16n8k8.row.col.f32.tf32.tf32.f32 "
        "{%0,%1,%2,%3}, {%4,%5,%6,%7}, {%8,%9}, {%0,%1,%2,%3};"
        : "+f"(d[0]), "+f"(d[1]), "+f"(d[2]), "+f"(d[3])
        : "r"(a[0]), "r"(a[1]), "r"(a[2]), "r"(a[3]), "r"(b[0]), "r"(b[1]));
}
__device__ __forceinline__ uint32_t smem_u32(const void* p) {
    uint32_t a;
    asm("{ .reg .u64 t; cvta.to.shared.u64 t, %1; cvt.u32.u64 %0, t; }" : "=r"(a) : "l"(p));
    return a;
}
__device__ __forceinline__ void cp_async16(uint32_t saddr, const void* gaddr) {
    asm volatile("cp.async.cg.shared.global [%0], [%1], 16;" :: "r"(saddr), "l"(gaddr));
}
#define CP_COMMIT() asm volatile("cp.async.commit_group;" ::: "memory")
#define CP_WAIT0()  asm volatile("cp.async.wait_group 0;" ::: "memory")

// ---------------- LayerNorm (D=1024, one block per row) ----------------
__global__ void ln_kernel(const float* __restrict__ in, float* __restrict__ out) {
    int row = blockIdx.x;
    const float* x = in + (size_t)row * D;
    float s = 0.f, ss = 0.f;
    for (int i = threadIdx.x; i < D; i += 256) {
        float v = x[i]; s += v; ss += v * v;
    }
    __shared__ float shs[8], shss[8];
    float ws = warpSum(s), wss = warpSum(ss);
    int w = threadIdx.x >> 5;
    if ((threadIdx.x & 31) == 0) { shs[w] = ws; shss[w] = wss; }
    __syncthreads();
    float ts = 0.f, tss = 0.f;
    #pragma unroll
    for (int i = 0; i < 8; i++) { ts += shs[i]; tss += shss[i]; }
    float mean = ts * (1.0f / D);
    float var  = tss * (1.0f / D) - mean * mean;
    float inv  = rsqrtf(var + 1e-6f);
    float* o = out + (size_t)row * D;
    for (int i = threadIdx.x; i < D; i += 256)
        o[i] = (x[i] - mean) * inv;
}

// ======================================================================
// Multi-job tf32 GEMM, cp.async 2-stage pipeline.
// C[M,N] = A[M,K] @ B[N,K]^T (+bias[N]) (+resid). Raw fp32 bits fed to
// tf32 mma (HW truncation). Tile 128x128x32, 8 warps (2x4), warp 64x32.
// ======================================================================
struct GJob {
    const float* A; const float* B; const float* bias; const float* resid;
    float* C; int M, N, K, off;
};
struct GJobs { GJob j[4]; int n; };

#define GST 36
#define SBUF (128 * GST)                    // floats per operand per stage
#define MMG_SMEM (2 * 2 * SBUF * 4)         // 2 stages x (A+B) x 4B = 73728

__global__ __launch_bounds__(256)
void mma_gemm_mj(GJobs jobs) {
    int ji = 0;
    if (jobs.n > 1 && (int)blockIdx.x >= jobs.j[1].off) ji = 1;
    if (jobs.n > 2 && (int)blockIdx.x >= jobs.j[2].off) ji = 2;
    if (jobs.n > 3 && (int)blockIdx.x >= jobs.j[3].off) ji = 3;
    const float* A = jobs.j[ji].A;
    const float* B = jobs.j[ji].B;
    const float* bias = jobs.j[ji].bias;
    const float* resid = jobs.j[ji].resid;
    float* C = jobs.j[ji].C;
    int N = jobs.j[ji].N, K = jobs.j[ji].K;
    int lid0 = blockIdx.x - jobs.j[ji].off;
    int nbx = N >> 7;
    int by = lid0 / nbx, bx = lid0 - by * nbx;
    int m0 = by * 128, n0 = bx * 128;

    extern __shared__ float smf[];
    uint32_t sbase = smem_u32(smf);
    int tid = threadIdx.x;
    int wid = tid >> 5, lane = tid & 31;
    int gid = lane >> 2, tig = lane & 3;
    int warp_m = wid >> 2, warp_n = wid & 3;

    float acc[4][4][4];
    #pragma unroll
    for (int mt = 0; mt < 4; mt++)
        #pragma unroll
        for (int nt = 0; nt < 4; nt++)
            #pragma unroll
            for (int e = 0; e < 4; e++) acc[mt][nt][e] = 0.f;

    const int nchunk = K >> 5;
    int lr = tid >> 3;                 // 0..31
    int lc4 = (tid & 7) << 2;          // 0..28

    // prefetch chunk 0 into stage 0
    {
        const float* Ap = A + (size_t)m0 * K + lc4;
        const float* Bp = B + (size_t)n0 * K + lc4;
        uint32_t sA = sbase;
        uint32_t sB = sbase + SBUF * 4;
        #pragma unroll
        for (int l = 0; l < 4; l++) {
            int r = lr + l * 32;
            cp_async16(sA + (r * GST + lc4) * 4, Ap + (size_t)r * K);
            cp_async16(sB + (r * GST + lc4) * 4, Bp + (size_t)r * K);
        }
    }
    CP_COMMIT();

    for (int i = 0; i < nchunk; i++) {
        int buf = i & 1;
        CP_WAIT0();
        __syncthreads();
        if (i + 1 < nchunk) {
            int nb = (i + 1) & 1;
            const float* Ap = A + (size_t)m0 * K + (i + 1) * 32 + lc4;
            const float* Bp = B + (size_t)n0 * K + (i + 1) * 32 + lc4;
            uint32_t sA = sbase + nb * 2 * SBUF * 4;
            uint32_t sB = sA + SBUF * 4;
            #pragma unroll
            for (int l = 0; l < 4; l++) {
                int r = lr + l * 32;
                cp_async16(sA + (r * GST + lc4) * 4, Ap + (size_t)r * K);
                cp_async16(sB + (r * GST + lc4) * 4, Bp + (size_t)r * K);
            }
        }
        CP_COMMIT();
        const float* As = smf + buf * 2 * SBUF;
        const float* Bs = As + SBUF;
        #pragma unroll
        for (int kk = 0; kk < 4; kk++) {
            int k0 = kk * 8;
            uint32_t af[4][4], bf[4][2];
            #pragma unroll
            for (int mt = 0; mt < 4; mt++) {
                int row = warp_m * 64 + mt * 16 + gid;
                const uint32_t* p0 = (const uint32_t*)(As + row * GST + k0);
                const uint32_t* p1 = (const uint32_t*)(As + (row + 8) * GST + k0);
                af[mt][0] = p0[tig];
                af[mt][1] = p1[tig];
                af[mt][2] = p0[tig + 4];
                af[mt][3] = p1[tig + 4];
            }
            #pragma unroll
            for (int nt = 0; nt < 4; nt++) {
                int col = warp_n * 32 + nt * 8 + gid;
                const uint32_t* p = (const uint32_t*)(Bs + col * GST + k0);
                bf[nt][0] = p[tig];
                bf[nt][1] = p[tig + 4];
            }
            #pragma unroll
            for (int mt = 0; mt < 4; mt++)
                #pragma unroll
                for (int nt = 0; nt < 4; nt++)
                    mma_tf32(acc[mt][nt], af[mt], bf[nt]);
        }
        __syncthreads();
    }

    #pragma unroll
    for (int mt = 0; mt < 4; mt++) {
        #pragma unroll
        for (int nt = 0; nt < 4; nt++) {
            int row = m0 + warp_m * 64 + mt * 16 + gid;
            int col = n0 + warp_n * 32 + nt * 8 + tig * 2;
            #pragma unroll
            for (int half = 0; half < 2; half++) {
                int r = row + half * 8;
                float2 v = make_float2(acc[mt][nt][half * 2], acc[mt][nt][half * 2 + 1]);
                if (bias) {
                    float2 bv2 = *(const float2*)(bias + col);
                    v.x += bv2.x; v.y += bv2.y;
                }
                size_t off = (size_t)r * N + col;
                if (resid) {
                    float2 rv = *(const float2*)(resid + off);
                    v.x += rv.x; v.y += rv.y;
                }
                *(float2*)(C + off) = v;
            }
        }
    }
}

// ---------------- qk finish: RMSNorm per head + RoPE, write to [H,T,HD] ------
__global__ void qk_finish(const float* __restrict__ qk,
                          const float* __restrict__ qn, const float* __restrict__ kn,
                          const float* __restrict__ freqs,
                          float* __restrict__ Q, float* __restrict__ Ko, int t_off) {
    int row = blockIdx.x, h = blockIdx.y, d = threadIdx.x;
    float qv = qk[(size_t)row * (2 * D) + h * HD + d];
    float kv = qk[(size_t)row * (2 * D) + D + h * HD + d];
    __shared__ float sh[4];
    float sq = qv * qv, sk = kv * kv;
    #pragma unroll
    for (int o = 16; o > 0; o >>= 1) { sq += __shfl_xor_sync(0xffffffffu, sq, o); sk += __shfl_xor_sync(0xffffffffu, sk, o); }
    int w = d >> 5;
    if ((d & 31) == 0) { sh[w] = sq; sh[2 + w] = sk; }
    __syncthreads();
    float rq = rsqrtf((sh[0] + sh[1]) * (1.0f / HD) + 1e-6f);
    float rk = rsqrtf((sh[2] + sh[3]) * (1.0f / HD) + 1e-6f);
    __shared__ float sQ[HD], sK[HD];
    sQ[d] = qv * rq * qn[d];
    sK[d] = kv * rk * kn[d];
    __syncthreads();
    int t = t_off + row;
    int i = d >> 1;
    float cs = freqs[((size_t)t * 32 + i) * 2 + 0];
    float sn = freqs[((size_t)t * 32 + i) * 2 + 1];
    float oq, ok;
    if ((d & 1) == 0) { oq = sQ[d] * cs - sQ[d + 1] * sn; ok = sK[d] * cs - sK[d + 1] * sn; }
    else              { oq = sQ[d - 1] * sn + sQ[d] * cs; ok = sK[d - 1] * sn + sK[d] * cs; }
    size_t off = ((size_t)h * TT + t) * HD + d;
    Q[off] = oq; Ko[off] = ok;
}

// ---------------- v reshape: [rows,D] -> [H,T,HD] ----------------
__global__ void v_finish(const float* __restrict__ vt, float* __restrict__ V,
                         int rows, int t_off) {
    int idx = blockIdx.x * 256 + threadIdx.x;
    if (idx >= rows * D) return;
    int row = idx >> 10, col = idx & 1023;
    int h = col >> 6, d = col & 63;
    V[((size_t)h * TT + t_off + row) * HD + d] = vt[idx];
}

// ======================================================================
// Tensor-core flash attention (tf32 mma, causal) — unchanged from R4.
// ======================================================================
#define AST 68
#define ATN_SMEM ((64 + 64 + 128) * AST * 4)

__global__ __launch_bounds__(256)
void attn_tc(const float* __restrict__ Q, const float* __restrict__ K,
             const float* __restrict__ V, float* __restrict__ Y) {
    extern __shared__ float sm[];
    float* Ks  = sm;
    float* VsT = sm + 64 * AST;
    float* Pw  = sm + 128 * AST;
    int tid = threadIdx.x, wid = tid >> 5, lane = tid & 31;
    int gid = lane >> 2, tig = lane & 3;
    int bxr = gridDim.x - 1 - blockIdx.x;
    int h = blockIdx.y;
    int q0 = bxr * 128;
    const float* Qh = Q + (size_t)h * TT * HD;
    const float* Kh = K + (size_t)h * TT * HD;
    const float* Vh = V + (size_t)h * TT * HD;
    const float QSC = 0.125f * 1.4426950408889634f;

    #pragma unroll
    for (int l = 0; l < 8; l++) {
        int e = tid + l * 256;
        int r = e >> 4, c4 = (e & 15) << 2;
        float4 v = *(const float4*)(Qh + (size_t)(q0 + r) * HD + c4);
        uint32_t* p = (uint32_t*)(Pw + r * AST + c4);
        p[0] = f2tf32(v.x * QSC); p[1] = f2tf32(v.y * QSC);
        p[2] = f2tf32(v.z * QSC); p[3] = f2tf32(v.w * QSC);
    }
    __syncthreads();
    uint32_t qf[8][4];
    int qrow = wid * 16 + gid;
    #pragma unroll
    for (int ks = 0; ks < 8; ks++) {
        int k0 = ks * 8;
        const uint32_t* p0 = (const uint32_t*)(Pw + qrow * AST + k0);
        const uint32_t* p1 = (const uint32_t*)(Pw + (qrow + 8) * AST + k0);
        qf[ks][0] = p0[tig];
        qf[ks][1] = p1[tig];
        qf[ks][2] = p0[tig + 4];
        qf[ks][3] = p1[tig + 4];
    }
    __syncwarp();

    float ofr[8][4];
    #pragma unroll
    for (int ot = 0; ot < 8; ot++)
        #pragma unroll
        for (int e = 0; e < 4; e++) ofr[ot][e] = 0.f;
    float m0r = -INFINITY, m1r = -INFINITY, l0r = 0.f, l1r = 0.f;

    int ntile = 2 * bxr + 2;
    for (int kt = 0; kt < ntile; kt++) {
        int k0g = kt * 64;
        __syncthreads();
        #pragma unroll
        for (int l = 0; l < 4; l++) {
            int e = tid + l * 256;
            int r = e >> 4, c4 = (e & 15) << 2;
            float4 kv = *(const float4*)(Kh + (size_t)(k0g + r) * HD + c4);
            uint32_t* pk = (uint32_t*)(Ks + r * AST + c4);
            pk[0] = f2tf32(kv.x); pk[1] = f2tf32(kv.y); pk[2] = f2tf32(kv.z); pk[3] = f2tf32(kv.w);
            float4 vv = *(const float4*)(Vh + (size_t)(k0g + r) * HD + c4);
            *(uint32_t*)(VsT + (c4 + 0) * AST + r) = f2tf32(vv.x);
            *(uint32_t*)(VsT + (c4 + 1) * AST + r) = f2tf32(vv.y);
            *(uint32_t*)(VsT + (c4 + 2) * AST + r) = f2tf32(vv.z);
            *(uint32_t*)(VsT + (c4 + 3) * AST + r) = f2tf32(vv.w);
        }
        __syncthreads();
        float sacc[8][4];
        #pragma unroll
        for (int nt = 0; nt < 8; nt++)
            #pragma unroll
            for (int e = 0; e < 4; e++) sacc[nt][e] = 0.f;
        #pragma unroll
        for (int ks = 0; ks < 8; ks++) {
            int k0 = ks * 8;
            #pragma unroll
            for (int nt = 0; nt < 8; nt++) {
                uint32_t bf[2];
                const uint32_t* p = (const uint32_t*)(Ks + (nt * 8 + gid) * AST + k0);
                bf[0] = p[tig];
                bf[1] = p[tig + 4];
                mma_tf32(sacc[nt], qf[ks], bf);
            }
        }
        if (kt >= ntile - 2) {
            int r0 = q0 + wid * 16 + gid;
            #pragma unroll
            for (int nt = 0; nt < 8; nt++) {
                int c0 = k0g + nt * 8 + tig * 2;
                if (c0 > r0)     sacc[nt][0] = -INFINITY;
                if (c0 + 1 > r0) sacc[nt][1] = -INFINITY;
                if (c0 > r0 + 8)     sacc[nt][2] = -INFINITY;
                if (c0 + 1 > r0 + 8) sacc[nt][3] = -INFINITY;
            }
        }
        float tm0 = -INFINITY, tm1 = -INFINITY;
        #pragma unroll
        for (int nt = 0; nt < 8; nt++) {
            tm0 = fmaxf(tm0, fmaxf(sacc[nt][0], sacc[nt][1]));
            tm1 = fmaxf(tm1, fmaxf(sacc[nt][2], sacc[nt][3]));
        }
        #pragma unroll
        for (int o = 1; o < 4; o <<= 1) {
            tm0 = fmaxf(tm0, __shfl_xor_sync(0xffffffffu, tm0, o));
            tm1 = fmaxf(tm1, __shfl_xor_sync(0xffffffffu, tm1, o));
        }
        float nm0 = fmaxf(m0r, tm0), nm1 = fmaxf(m1r, tm1);
        float c0 = exp2f(m0r - nm0), c1 = exp2f(m1r - nm1);
        m0r = nm0; m1r = nm1;
        float ps0 = 0.f, ps1 = 0.f;
        #pragma unroll
        for (int nt = 0; nt < 8; nt++) {
            float p00 = exp2f(sacc[nt][0] - nm0);
            float p01 = exp2f(sacc[nt][1] - nm0);
            float p10 = exp2f(sacc[nt][2] - nm1);
            float p11 = exp2f(sacc[nt][3] - nm1);
            ps0 += p00 + p01; ps1 += p10 + p11;
            uint32_t* pr0 = (uint32_t*)(Pw + (wid * 16 + gid) * AST + nt * 8 + tig * 2);
            uint32_t* pr1 = (uint32_t*)(Pw + (wid * 16 + gid + 8) * AST + nt * 8 + tig * 2);
            pr0[0] = f2tf32(p00); pr0[1] = f2tf32(p01);
            pr1[0] = f2tf32(p10); pr1[1] = f2tf32(p11);
        }
        #pragma unroll
        for (int o = 1; o < 4; o <<= 1) {
            ps0 += __shfl_xor_sync(0xffffffffu, ps0, o);
            ps1 += __shfl_xor_sync(0xffffffffu, ps1, o);
        }
        l0r = l0r * c0 + ps0;
        l1r = l1r * c1 + ps1;
        #pragma unroll
        for (int ot = 0; ot < 8; ot++) {
            ofr[ot][0] *= c0; ofr[ot][1] *= c0;
            ofr[ot][2] *= c1; ofr[ot][3] *= c1;
        }
        __syncwarp();
        #pragma unroll
        for (int ks = 0; ks < 8; ks++) {
            int k0 = ks * 8;
            uint32_t af[4];
            const uint32_t* p0 = (const uint32_t*)(Pw + (wid * 16 + gid) * AST + k0);
            const uint32_t* p1 = (const uint32_t*)(Pw + (wid * 16 + gid + 8) * AST + k0);
            af[0] = p0[tig];
            af[1] = p1[tig];
            af[2] = p0[tig + 4];
            af[3] = p1[tig + 4];
            #pragma unroll
            for (int ot = 0; ot < 8; ot++) {
                uint32_t bf[2];
                const uint32_t* p = (const uint32_t*)(VsT + (ot * 8 + gid) * AST + k0);
                bf[0] = p[tig];
                bf[1] = p[tig + 4];
                mma_tf32(ofr[ot], af, bf);
            }
        }
    }
    float i0 = 1.0f / l0r, i1 = 1.0f / l1r;
    int t0 = q0 + wid * 16 + gid, t1 = t0 + 8;
    #pragma unroll
    for (int ot = 0; ot < 8; ot++) {
        int col = h * HD + ot * 8 + tig * 2;
        *(float2*)(Y + (size_t)t0 * D + col) = make_float2(ofr[ot][0] * i0, ofr[ot][1] * i0);
        *(float2*)(Y + (size_t)t1 * D + col) = make_float2(ofr[ot][2] * i1, ofr[ot][3] * i1);
    }
}

// ---------------- SiLU gate ----------------
__global__ void silu_gate(const float* __restrict__ a, const float* __restrict__ b,
                          float* __restrict__ g, int n) {
    int i = blockIdx.x * 256 + threadIdx.x;
    if (i < n) {
        float x = a[i];
        g[i] = (x / (1.0f + expf(-x))) * b[i];
    }
}

// ---------------- host launcher ----------------
static inline int nct(int M, int N) { return (M / 128) * (N / 128); }

extern "C" void kernel_launch(void* const* d_in, const int* in_sizes, int n_in,
                              void* d_out, int out_size) {
    const float* x        = (const float*)d_in[0];
    const float* c        = (const float*)d_in[1];
    const float* freqs    = (const float*)d_in[2];
    const float* px_qk_w  = (const float*)d_in[3];
    const float* px_qn    = (const float*)d_in[4];
    const float* px_kn    = (const float*)d_in[5];
    const float* px_v_w   = (const float*)d_in[6];
    const float* px_v_b   = (const float*)d_in[7];
    const float* pc_qk_w  = (const float*)d_in[8];
    const float* pc_qn    = (const float*)d_in[9];
    const float* pc_kn    = (const float*)d_in[10];
    const float* pc_v_w   = (const float*)d_in[11];
    const float* pc_v_b   = (const float*)d_in[12];
    const float* p1_proj_w = (const float*)d_in[13];
    const float* p1_proj_b = (const float*)d_in[14];
    const float* p1_w1    = (const float*)d_in[15];
    const float* p1_b1    = (const float*)d_in[16];
    const float* p1_w3    = (const float*)d_in[17];
    const float* p1_b3    = (const float*)d_in[18];
    const float* p1_w2    = (const float*)d_in[19];
    const float* p1_b2    = (const float*)d_in[20];
    const float* p2_proj_w = (const float*)d_in[21];
    const float* p2_proj_b = (const float*)d_in[22];
    const float* p2_w1    = (const float*)d_in[23];
    const float* p2_b1    = (const float*)d_in[24];
    const float* p2_w3    = (const float*)d_in[25];
    const float* p2_b3    = (const float*)d_in[26];
    const float* p2_w2    = (const float*)d_in[27];
    const float* p2_b2    = (const float*)d_in[28];
    float* out = (float*)d_out;

    float *xln, *cln, *qkx, *qkc, *vtx, *vtc, *q, *k, *v, *y;
    float *x1x, *x1c, *hx, *hc, *t1x, *t3x, *t1c, *t3c;
    cudaGetSymbolAddress((void**)&xln, g_xln);
    cudaGetSymbolAddress((void**)&cln, g_cln);
    cudaGetSymbolAddress((void**)&qkx, g_qkx);
    cudaGetSymbolAddress((void**)&qkc, g_qkc);
    cudaGetSymbolAddress((void**)&vtx, g_vtx);
    cudaGetSymbolAddress((void**)&vtc, g_vtc);
    cudaGetSymbolAddress((void**)&q,   g_q);
    cudaGetSymbolAddress((void**)&k,   g_k);
    cudaGetSymbolAddress((void**)&v,   g_v);
    cudaGetSymbolAddress((void**)&y,   g_y);
    cudaGetSymbolAddress((void**)&x1x, g_x1x);
    cudaGetSymbolAddress((void**)&x1c, g_x1c);
    cudaGetSymbolAddress((void**)&hx,  g_hx);
    cudaGetSymbolAddress((void**)&hc,  g_hc);
    cudaGetSymbolAddress((void**)&t1x, g_t1x);
    cudaGetSymbolAddress((void**)&t3x, g_t3x);
    cudaGetSymbolAddress((void**)&t1c, g_t1c);
    cudaGetSymbolAddress((void**)&t3c, g_t3c);

    cudaFuncSetAttribute(attn_tc, cudaFuncAttributeMaxDynamicSharedMemorySize, ATN_SMEM);
    cudaFuncSetAttribute(mma_gemm_mj, cudaFuncAttributeMaxDynamicSharedMemorySize, MMG_SMEM);

    // 1) LayerNorm both streams
    ln_kernel<<<L_X, 256>>>(x, xln);
    ln_kernel<<<S_C, 256>>>(c, cln);

    // 2) QKV GEMMs for both streams (one batched launch)
    {
        GJobs J; J.n = 4;
        int o = 0;
        J.j[0] = {cln, pc_qk_w, nullptr, nullptr, qkc, S_C, 2 * D, D, o}; o += nct(S_C, 2 * D);
        J.j[1] = {cln, pc_v_w,  pc_v_b,  nullptr, vtc, S_C, D,     D, o}; o += nct(S_C, D);
        J.j[2] = {xln, px_qk_w, nullptr, nullptr, qkx, L_X, 2 * D, D, o}; o += nct(L_X, 2 * D);
        J.j[3] = {xln, px_v_w,  px_v_b,  nullptr, vtx, L_X, D,     D, o}; o += nct(L_X, D);
        mma_gemm_mj<<<o, 256, MMG_SMEM>>>(J);
    }
    qk_finish<<<dim3(S_C, H), HD>>>(qkc, pc_qn, pc_kn, freqs, q, k, 0);
    qk_finish<<<dim3(L_X, H), HD>>>(qkx, px_qn, px_kn, freqs, q, k, S_C);
    v_finish<<<(S_C * D + 255) / 256, 256>>>(vtc, v, S_C, 0);
    v_finish<<<(L_X * D + 255) / 256, 256>>>(vtx, v, L_X, S_C);

    // 3) causal attention (tensor cores)
    attn_tc<<<dim3(TT / 128, H), 256, ATN_SMEM>>>(q, k, v, y);

    // 4) output projections for both streams (batched)
    const float* yx = y + (size_t)S_C * D;
    {
        GJobs J; J.n = 2;
        int o = 0;
        J.j[0] = {yx, p1_proj_w, p1_proj_b, x, x1x, L_X, D, D, o}; o += nct(L_X, D);
        J.j[1] = {y,  p2_proj_w, p2_proj_b, c, x1c, S_C, D, D, o}; o += nct(S_C, D);
        J.j[2] = J.j[0]; J.j[3] = J.j[0];
        mma_gemm_mj<<<o, 256, MMG_SMEM>>>(J);
    }
    ln_kernel<<<L_X, 256>>>(x1x, hx);
    ln_kernel<<<S_C, 256>>>(x1c, hc);

    // 5) w1/w3 for both streams (batched)
    {
        GJobs J; J.n = 4;
        int o = 0;
        J.j[0] = {hx, p1_w1, p1_b1, nullptr, t1x, L_X, FF, D, o}; o += nct(L_X, FF);
        J.j[1] = {hx, p1_w3, p1_b3, nullptr, t3x, L_X, FF, D, o}; o += nct(L_X, FF);
        J.j[2] = {hc, p2_w1, p2_b1, nullptr, t1c, S_C, FF, D, o}; o += nct(S_C, FF);
        J.j[3] = {hc, p2_w3, p2_b3, nullptr, t3c, S_C, FF, D, o}; o += nct(S_C, FF);
        mma_gemm_mj<<<o, 256, MMG_SMEM>>>(J);
    }
    silu_gate<<<(L_X * FF + 255) / 256, 256>>>(t1x, t3x, t1x, L_X * FF);
    silu_gate<<<(S_C * FF + 255) / 256, 256>>>(t1c, t3c, t1c, S_C * FF);

    // 6) w2 for both streams (batched)
    {
        GJobs J; J.n = 2;
        int o = 0;
        J.j[0] = {t1x, p1_w2, p1_b2, x1x, out,                    L_X, D, FF, o}; o += nct(L_X, D);
        J.j[1] = {t1c, p2_w2, p2_b2, x1c, out + (size_t)L_X * D,  S_C, D, FF, o}; o += nct(S_C, D);
        J.j[2] = J.j[0]; J.j[3] = J.j[0];
        mma_gemm_mj<<<o, 256, MMG_SMEM>>>(J);
    }
}

// round 6
// speedup vs baseline: 5.7225x; 1.1365x over previous
#include <cuda_runtime.h>
#include <cuda_bf16.h>
#include <cstdint>
#include <math.h>

// ---------------- problem constants ----------------
#define L_X   1536
#define S_C   512
#define TT    2048          // L_X + S_C
#define D     1024
#define H     16
#define HD    64
#define FF    4096

// ---------------- scratch (device globals; no cudaMalloc allowed) ----------
__device__ float g_xln[L_X * D];
__device__ float g_cln[S_C * D];
__device__ float g_qkx[L_X * 2 * D];
__device__ float g_qkc[S_C * 2 * D];
__device__ float g_vtx[L_X * D];
__device__ float g_vtc[S_C * D];
__device__ float g_q  [H * TT * HD];
__device__ float g_k  [H * TT * HD];
__device__ float g_v  [H * TT * HD];
__device__ float g_y  [TT * D];
__device__ float g_x1x[L_X * D];
__device__ float g_x1c[S_C * D];
__device__ float g_hx [L_X * D];
__device__ float g_hc [S_C * D];
__device__ float g_t1x[L_X * FF];
__device__ float g_t3x[L_X * FF];
__device__ float g_t1c[S_C * FF];
__device__ float g_t3c[S_C * FF];

// ---------------- utils ----------------
__device__ __forceinline__ float warpSum(float v) {
    #pragma unroll
    for (int o = 16; o > 0; o >>= 1) v += __shfl_xor_sync(0xffffffffu, v, o);
    return v;
}
__device__ __forceinline__ uint32_t f2tf32(float v) {
    uint32_t r;
    asm("cvt.rna.tf32.f32 %0, %1;" : "=r"(r) : "f"(v));
    return r;
}
__device__ __forceinline__ float ex2f(float x) {
    float y;
    asm("ex2.approx.f32 %0, %1;" : "=f"(y) : "f"(x));
    return y;
}
__device__ __forceinline__ void mma_tf32(float* d, const uint32_t* a, const uint32_t* b) {
    asm volatile(
        "mma.sync.aligned.m16n8k8.row.col.f32.tf32.tf32.f32 "
        "{%0,%1,%2,%3}, {%4,%5,%6,%7}, {%8,%9}, {%0,%1,%2,%3};"
        : "+f"(d[0]), "+f"(d[1]), "+f"(d[2]), "+f"(d[3])
        : "r"(a[0]), "r"(a[1]), "r"(a[2]), "r"(a[3]), "r"(b[0]), "r"(b[1]));
}
__device__ __forceinline__ uint32_t smem_u32(const void* p) {
    uint32_t a;
    asm("{ .reg .u64 t; cvta.to.shared.u64 t, %1; cvt.u32.u64 %0, t; }" : "=r"(a) : "l"(p));
    return a;
}
__device__ __forceinline__ void cp_async16(uint32_t saddr, const void* gaddr) {
    asm volatile("cp.async.cg.shared.global [%0], [%1], 16;" :: "r"(saddr), "l"(gaddr));
}
#define CP_COMMIT() asm volatile("cp.async.commit_group;" ::: "memory")
#define CP_WAIT1()  asm volatile("cp.async.wait_group 1;" ::: "memory")

// ---------------- LayerNorm pair (one launch, both streams) ----------------
__global__ void ln2_kernel(const float* __restrict__ in0, float* __restrict__ out0,
                           int rows0,
                           const float* __restrict__ in1, float* __restrict__ out1) {
    int row = blockIdx.x;
    const float* x;
    float* o;
    if (row < rows0) { x = in0 + (size_t)row * D; o = out0 + (size_t)row * D; }
    else             { x = in1 + (size_t)(row - rows0) * D; o = out1 + (size_t)(row - rows0) * D; }
    float s = 0.f, ss = 0.f;
    for (int i = threadIdx.x; i < D; i += 256) {
        float v = x[i]; s += v; ss += v * v;
    }
    __shared__ float shs[8], shss[8];
    float ws = warpSum(s), wss = warpSum(ss);
    int w = threadIdx.x >> 5;
    if ((threadIdx.x & 31) == 0) { shs[w] = ws; shss[w] = wss; }
    __syncthreads();
    float ts = 0.f, tss = 0.f;
    #pragma unroll
    for (int i = 0; i < 8; i++) { ts += shs[i]; tss += shss[i]; }
    float mean = ts * (1.0f / D);
    float var  = tss * (1.0f / D) - mean * mean;
    float inv  = rsqrtf(var + 1e-6f);
    for (int i = threadIdx.x; i < D; i += 256)
        o[i] = (x[i] - mean) * inv;
}

// ======================================================================
// Multi-job tf32 GEMM, 3-stage cp.async pipeline, swizzled smem.
// C[M,N] = A[M,K] @ B[N,K]^T (+bias[N]) (+resid). Raw fp32 bits fed to
// tf32 mma (HW truncation). Tile 128x128x32, 8 warps (2x4), warp 64x32.
// smem layout: elem (r,c) at r*32 + (c ^ ((r&7)<<2)); 16KB/operand/stage.
// ======================================================================
struct GJob {
    const float* A; const float* B; const float* bias; const float* resid;
    float* C; int M, N, K, off;
};
struct GJobs { GJob j[4]; int n; };

#define SBUF 4096                           // floats per operand per stage
#define MMG_SMEM (3 * 2 * SBUF * 4)         // 98304 bytes
#define SWIZ(r, c) (((r) << 5) + ((c) ^ (((r) & 7) << 2)))

__global__ __launch_bounds__(256)
void mma_gemm_mj(GJobs jobs) {
    int ji = 0;
    if (jobs.n > 1 && (int)blockIdx.x >= jobs.j[1].off) ji = 1;
    if (jobs.n > 2 && (int)blockIdx.x >= jobs.j[2].off) ji = 2;
    if (jobs.n > 3 && (int)blockIdx.x >= jobs.j[3].off) ji = 3;
    const float* A = jobs.j[ji].A;
    const float* B = jobs.j[ji].B;
    const float* bias = jobs.j[ji].bias;
    const float* resid = jobs.j[ji].resid;
    float* C = jobs.j[ji].C;
    int N = jobs.j[ji].N, K = jobs.j[ji].K;
    int lid0 = blockIdx.x - jobs.j[ji].off;
    int nbx = N >> 7;
    int by = lid0 / nbx, bx = lid0 - by * nbx;
    int m0 = by * 128, n0 = bx * 128;

    extern __shared__ float smf[];
    uint32_t sbase = smem_u32(smf);
    int tid = threadIdx.x;
    int wid = tid >> 5, lane = tid & 31;
    int gid = lane >> 2, tig = lane & 3;
    int warp_m = wid >> 2, warp_n = wid & 3;

    float acc[4][4][4];
    #pragma unroll
    for (int mt = 0; mt < 4; mt++)
        #pragma unroll
        for (int nt = 0; nt < 4; nt++)
            #pragma unroll
            for (int e = 0; e < 4; e++) acc[mt][nt][e] = 0.f;

    const int nchunk = K >> 5;
    int lr = tid >> 3;                 // 0..31
    int lc4 = (tid & 7) << 2;          // 0..28

    // prefetch chunks 0,1 into stages 0,1
    #pragma unroll
    for (int pc = 0; pc < 2; pc++) {
        const float* Ap = A + (size_t)m0 * K + pc * 32 + lc4;
        const float* Bp = B + (size_t)n0 * K + pc * 32 + lc4;
        uint32_t sA = sbase + pc * 2 * SBUF * 4;
        uint32_t sB = sA + SBUF * 4;
        #pragma unroll
        for (int l = 0; l < 4; l++) {
            int r = lr + l * 32;
            uint32_t so = SWIZ(r, lc4) * 4;
            cp_async16(sA + so, Ap + (size_t)r * K);
            cp_async16(sB + so, Bp + (size_t)r * K);
        }
        CP_COMMIT();
    }

    int st = 0;                         // stage of current chunk
    for (int i = 0; i < nchunk; i++) {
        CP_WAIT1();
        __syncthreads();
        // prefetch chunk i+2 into stage (st+2)%3 (freed by iter i-1's compute)
        if (i + 2 < nchunk) {
            int ps = st + 2; if (ps >= 3) ps -= 3;
            const float* Ap = A + (size_t)m0 * K + (i + 2) * 32 + lc4;
            const float* Bp = B + (size_t)n0 * K + (i + 2) * 32 + lc4;
            uint32_t sA = sbase + ps * 2 * SBUF * 4;
            uint32_t sB = sA + SBUF * 4;
            #pragma unroll
            for (int l = 0; l < 4; l++) {
                int r = lr + l * 32;
                uint32_t so = SWIZ(r, lc4) * 4;
                cp_async16(sA + so, Ap + (size_t)r * K);
                cp_async16(sB + so, Bp + (size_t)r * K);
            }
        }
        CP_COMMIT();
        const float* As = smf + st * 2 * SBUF;
        const float* Bs = As + SBUF;
        #pragma unroll
        for (int kk = 0; kk < 4; kk++) {
            int k0 = kk * 8;
            uint32_t af[4][4], bf[4][2];
            #pragma unroll
            for (int mt = 0; mt < 4; mt++) {
                int r0 = warp_m * 64 + mt * 16 + gid;
                const uint32_t* p0 = (const uint32_t*)As;
                af[mt][0] = p0[SWIZ(r0,     k0 + tig)];
                af[mt][1] = p0[SWIZ(r0 + 8, k0 + tig)];
                af[mt][2] = p0[SWIZ(r0,     k0 + tig + 4)];
                af[mt][3] = p0[SWIZ(r0 + 8, k0 + tig + 4)];
            }
            #pragma unroll
            for (int nt = 0; nt < 4; nt++) {
                int col = warp_n * 32 + nt * 8 + gid;
                const uint32_t* p = (const uint32_t*)Bs;
                bf[nt][0] = p[SWIZ(col, k0 + tig)];
                bf[nt][1] = p[SWIZ(col, k0 + tig + 4)];
            }
            #pragma unroll
            for (int mt = 0; mt < 4; mt++)
                #pragma unroll
                for (int nt = 0; nt < 4; nt++)
                    mma_tf32(acc[mt][nt], af[mt], bf[nt]);
        }
        st++; if (st >= 3) st = 0;
    }

    #pragma unroll
    for (int mt = 0; mt < 4; mt++) {
        #pragma unroll
        for (int nt = 0; nt < 4; nt++) {
            int row = m0 + warp_m * 64 + mt * 16 + gid;
            int col = n0 + warp_n * 32 + nt * 8 + tig * 2;
            #pragma unroll
            for (int half = 0; half < 2; half++) {
                int r = row + half * 8;
                float2 v = make_float2(acc[mt][nt][half * 2], acc[mt][nt][half * 2 + 1]);
                if (bias) {
                    float2 bv2 = *(const float2*)(bias + col);
                    v.x += bv2.x; v.y += bv2.y;
                }
                size_t off = (size_t)r * N + col;
                if (resid) {
                    float2 rv = *(const float2*)(resid + off);
                    v.x += rv.x; v.y += rv.y;
                }
                *(float2*)(C + off) = v;
            }
        }
    }
}

// ---------------- qk finish (both streams, one launch) ----------------
__global__ void qk_finish_all(const float* __restrict__ qkc, const float* __restrict__ qkx,
                              const float* __restrict__ cqn, const float* __restrict__ ckn,
                              const float* __restrict__ xqn, const float* __restrict__ xkn,
                              const float* __restrict__ freqs,
                              float* __restrict__ Q, float* __restrict__ Ko) {
    int t = blockIdx.x, h = blockIdx.y, d = threadIdx.x;
    const float* qk; const float* qn; const float* kn; int row;
    if (t < S_C) { qk = qkc; qn = cqn; kn = ckn; row = t; }
    else         { qk = qkx; qn = xqn; kn = xkn; row = t - S_C; }
    float qv = qk[(size_t)row * (2 * D) + h * HD + d];
    float kv = qk[(size_t)row * (2 * D) + D + h * HD + d];
    __shared__ float sh[4];
    float sq = qv * qv, sk = kv * kv;
    #pragma unroll
    for (int o = 16; o > 0; o >>= 1) { sq += __shfl_xor_sync(0xffffffffu, sq, o); sk += __shfl_xor_sync(0xffffffffu, sk, o); }
    int w = d >> 5;
    if ((d & 31) == 0) { sh[w] = sq; sh[2 + w] = sk; }
    __syncthreads();
    float rq = rsqrtf((sh[0] + sh[1]) * (1.0f / HD) + 1e-6f);
    float rk = rsqrtf((sh[2] + sh[3]) * (1.0f / HD) + 1e-6f);
    __shared__ float sQ[HD], sK[HD];
    sQ[d] = qv * rq * qn[d];
    sK[d] = kv * rk * kn[d];
    __syncthreads();
    int i = d >> 1;
    float cs = freqs[((size_t)t * 32 + i) * 2 + 0];
    float sn = freqs[((size_t)t * 32 + i) * 2 + 1];
    float oq, ok;
    if ((d & 1) == 0) { oq = sQ[d] * cs - sQ[d + 1] * sn; ok = sK[d] * cs - sK[d + 1] * sn; }
    else              { oq = sQ[d - 1] * sn + sQ[d] * cs; ok = sK[d - 1] * sn + sK[d] * cs; }
    size_t off = ((size_t)h * TT + t) * HD + d;
    Q[off] = oq; Ko[off] = ok;
}

// ---------------- v reshape (both streams): [rows,D] -> [H,T,HD] -------
__global__ void v_finish_all(const float* __restrict__ vtc, const float* __restrict__ vtx,
                             float* __restrict__ V) {
    int idx = blockIdx.x * 256 + threadIdx.x;
    if (idx >= TT * D) return;
    int t = idx >> 10, col = idx & 1023;
    int h = col >> 6, d = col & 63;
    float val = (t < S_C) ? vtc[((size_t)t << 10) + col]
                          : vtx[((size_t)(t - S_C) << 10) + col];
    V[((size_t)h * TT + t) * HD + d] = val;
}

// ======================================================================
// Tensor-core flash attention (tf32 mma, causal).
// ======================================================================
#define AST 68
#define ATN_SMEM ((64 + 64 + 128) * AST * 4)

__global__ __launch_bounds__(256)
void attn_tc(const float* __restrict__ Q, const float* __restrict__ K,
             const float* __restrict__ V, float* __restrict__ Y) {
    extern __shared__ float sm[];
    float* Ks  = sm;
    float* VsT = sm + 64 * AST;
    float* Pw  = sm + 128 * AST;
    int tid = threadIdx.x, wid = tid >> 5, lane = tid & 31;
    int gid = lane >> 2, tig = lane & 3;
    int bxr = gridDim.x - 1 - blockIdx.x;
    int h = blockIdx.y;
    int q0 = bxr * 128;
    const float* Qh = Q + (size_t)h * TT * HD;
    const float* Kh = K + (size_t)h * TT * HD;
    const float* Vh = V + (size_t)h * TT * HD;
    const float QSC = 0.125f * 1.4426950408889634f;

    #pragma unroll
    for (int l = 0; l < 8; l++) {
        int e = tid + l * 256;
        int r = e >> 4, c4 = (e & 15) << 2;
        float4 v = *(const float4*)(Qh + (size_t)(q0 + r) * HD + c4);
        uint32_t* p = (uint32_t*)(Pw + r * AST + c4);
        p[0] = f2tf32(v.x * QSC); p[1] = f2tf32(v.y * QSC);
        p[2] = f2tf32(v.z * QSC); p[3] = f2tf32(v.w * QSC);
    }
    __syncthreads();
    uint32_t qf[8][4];
    int qrow = wid * 16 + gid;
    #pragma unroll
    for (int ks = 0; ks < 8; ks++) {
        int k0 = ks * 8;
        const uint32_t* p0 = (const uint32_t*)(Pw + qrow * AST + k0);
        const uint32_t* p1 = (const uint32_t*)(Pw + (qrow + 8) * AST + k0);
        qf[ks][0] = p0[tig];
        qf[ks][1] = p1[tig];
        qf[ks][2] = p0[tig + 4];
        qf[ks][3] = p1[tig + 4];
    }
    __syncwarp();

    float ofr[8][4];
    #pragma unroll
    for (int ot = 0; ot < 8; ot++)
        #pragma unroll
        for (int e = 0; e < 4; e++) ofr[ot][e] = 0.f;
    float m0r = -INFINITY, m1r = -INFINITY, l0r = 0.f, l1r = 0.f;

    int ntile = 2 * bxr + 2;
    for (int kt = 0; kt < ntile; kt++) {
        int k0g = kt * 64;
        __syncthreads();
        #pragma unroll
        for (int l = 0; l < 4; l++) {
            int e = tid + l * 256;
            int r = e >> 4, c4 = (e & 15) << 2;
            float4 kv = *(const float4*)(Kh + (size_t)(k0g + r) * HD + c4);
            uint32_t* pk = (uint32_t*)(Ks + r * AST + c4);
            pk[0] = f2tf32(kv.x); pk[1] = f2tf32(kv.y); pk[2] = f2tf32(kv.z); pk[3] = f2tf32(kv.w);
            float4 vv = *(const float4*)(Vh + (size_t)(k0g + r) * HD + c4);
            *(uint32_t*)(VsT + (c4 + 0) * AST + r) = f2tf32(vv.x);
            *(uint32_t*)(VsT + (c4 + 1) * AST + r) = f2tf32(vv.y);
            *(uint32_t*)(VsT + (c4 + 2) * AST + r) = f2tf32(vv.z);
            *(uint32_t*)(VsT + (c4 + 3) * AST + r) = f2tf32(vv.w);
        }
        __syncthreads();
        float sacc[8][4];
        #pragma unroll
        for (int nt = 0; nt < 8; nt++)
            #pragma unroll
            for (int e = 0; e < 4; e++) sacc[nt][e] = 0.f;
        #pragma unroll
        for (int ks = 0; ks < 8; ks++) {
            int k0 = ks * 8;
            #pragma unroll
            for (int nt = 0; nt < 8; nt++) {
                uint32_t bf[2];
                const uint32_t* p = (const uint32_t*)(Ks + (nt * 8 + gid) * AST + k0);
                bf[0] = p[tig];
                bf[1] = p[tig + 4];
                mma_tf32(sacc[nt], qf[ks], bf);
            }
        }
        if (kt >= ntile - 2) {
            int r0 = q0 + wid * 16 + gid;
            #pragma unroll
            for (int nt = 0; nt < 8; nt++) {
                int c0 = k0g + nt * 8 + tig * 2;
                if (c0 > r0)     sacc[nt][0] = -INFINITY;
                if (c0 + 1 > r0) sacc[nt][1] = -INFINITY;
                if (c0 > r0 + 8)     sacc[nt][2] = -INFINITY;
                if (c0 + 1 > r0 + 8) sacc[nt][3] = -INFINITY;
            }
        }
        float tm0 = -INFINITY, tm1 = -INFINITY;
        #pragma unroll
        for (int nt = 0; nt < 8; nt++) {
            tm0 = fmaxf(tm0, fmaxf(sacc[nt][0], sacc[nt][1]));
            tm1 = fmaxf(tm1, fmaxf(sacc[nt][2], sacc[nt][3]));
        }
        #pragma unroll
        for (int o = 1; o < 4; o <<= 1) {
            tm0 = fmaxf(tm0, __shfl_xor_sync(0xffffffffu, tm0, o));
            tm1 = fmaxf(tm1, __shfl_xor_sync(0xffffffffu, tm1, o));
        }
        float nm0 = fmaxf(m0r, tm0), nm1 = fmaxf(m1r, tm1);
        float c0 = ex2f(m0r - nm0), c1 = ex2f(m1r - nm1);
        m0r = nm0; m1r = nm1;
        float ps0 = 0.f, ps1 = 0.f;
        #pragma unroll
        for (int nt = 0; nt < 8; nt++) {
            float p00 = ex2f(sacc[nt][0] - nm0);
            float p01 = ex2f(sacc[nt][1] - nm0);
            float p10 = ex2f(sacc[nt][2] - nm1);
            float p11 = ex2f(sacc[nt][3] - nm1);
            ps0 += p00 + p01; ps1 += p10 + p11;
            uint32_t* pr0 = (uint32_t*)(Pw + (wid * 16 + gid) * AST + nt * 8 + tig * 2);
            uint32_t* pr1 = (uint32_t*)(Pw + (wid * 16 + gid + 8) * AST + nt * 8 + tig * 2);
            pr0[0] = f2tf32(p00); pr0[1] = f2tf32(p01);
            pr1[0] = f2tf32(p10); pr1[1] = f2tf32(p11);
        }
        #pragma unroll
        for (int o = 1; o < 4; o <<= 1) {
            ps0 += __shfl_xor_sync(0xffffffffu, ps0, o);
            ps1 += __shfl_xor_sync(0xffffffffu, ps1, o);
        }
        l0r = l0r * c0 + ps0;
        l1r = l1r * c1 + ps1;
        #pragma unroll
        for (int ot = 0; ot < 8; ot++) {
            ofr[ot][0] *= c0; ofr[ot][1] *= c0;
            ofr[ot][2] *= c1; ofr[ot][3] *= c1;
        }
        __syncwarp();
        #pragma unroll
        for (int ks = 0; ks < 8; ks++) {
            int k0 = ks * 8;
            uint32_t af[4];
            const uint32_t* p0 = (const uint32_t*)(Pw + (wid * 16 + gid) * AST + k0);
            const uint32_t* p1 = (const uint32_t*)(Pw + (wid * 16 + gid + 8) * AST + k0);
            af[0] = p0[tig];
            af[1] = p1[tig];
            af[2] = p0[tig + 4];
            af[3] = p1[tig + 4];
            #pragma unroll
            for (int ot = 0; ot < 8; ot++) {
                uint32_t bf[2];
                const uint32_t* p = (const uint32_t*)(VsT + (ot * 8 + gid) * AST + k0);
                bf[0] = p[tig];
                bf[1] = p[tig + 4];
                mma_tf32(ofr[ot], af, bf);
            }
        }
    }
    float i0 = 1.0f / l0r, i1 = 1.0f / l1r;
    int t0 = q0 + wid * 16 + gid, t1 = t0 + 8;
    #pragma unroll
    for (int ot = 0; ot < 8; ot++) {
        int col = h * HD + ot * 8 + tig * 2;
        *(float2*)(Y + (size_t)t0 * D + col) = make_float2(ofr[ot][0] * i0, ofr[ot][1] * i0);
        *(float2*)(Y + (size_t)t1 * D + col) = make_float2(ofr[ot][2] * i1, ofr[ot][3] * i1);
    }
}

// ---------------- SiLU gate (both streams) ----------------
__global__ void silu_all(const float* __restrict__ a0, const float* __restrict__ b0,
                         float* __restrict__ g0, int n0,
                         const float* __restrict__ a1, const float* __restrict__ b1,
                         float* __restrict__ g1, int n1) {
    int i = blockIdx.x * 256 + threadIdx.x;
    if (i < n0) {
        float x = a0[i];
        g0[i] = (x / (1.0f + expf(-x))) * b0[i];
    } else if (i < n0 + n1) {
        int j = i - n0;
        float x = a1[j];
        g1[j] = (x / (1.0f + expf(-x))) * b1[j];
    }
}

// ---------------- host launcher ----------------
static inline int nct(int M, int N) { return (M / 128) * (N / 128); }

extern "C" void kernel_launch(void* const* d_in, const int* in_sizes, int n_in,
                              void* d_out, int out_size) {
    const float* x        = (const float*)d_in[0];
    const float* c        = (const float*)d_in[1];
    const float* freqs    = (const float*)d_in[2];
    const float* px_qk_w  = (const float*)d_in[3];
    const float* px_qn    = (const float*)d_in[4];
    const float* px_kn    = (const float*)d_in[5];
    const float* px_v_w   = (const float*)d_in[6];
    const float* px_v_b   = (const float*)d_in[7];
    const float* pc_qk_w  = (const float*)d_in[8];
    const float* pc_qn    = (const float*)d_in[9];
    const float* pc_kn    = (const float*)d_in[10];
    const float* pc_v_w   = (const float*)d_in[11];
    const float* pc_v_b   = (const float*)d_in[12];
    const float* p1_proj_w = (const float*)d_in[13];
    const float* p1_proj_b = (const float*)d_in[14];
    const float* p1_w1    = (const float*)d_in[15];
    const float* p1_b1    = (const float*)d_in[16];
    const float* p1_w3    = (const float*)d_in[17];
    const float* p1_b3    = (const float*)d_in[18];
    const float* p1_w2    = (const float*)d_in[19];
    const float* p1_b2    = (const float*)d_in[20];
    const float* p2_proj_w = (const float*)d_in[21];
    const float* p2_proj_b = (const float*)d_in[22];
    const float* p2_w1    = (const float*)d_in[23];
    const float* p2_b1    = (const float*)d_in[24];
    const float* p2_w3    = (const float*)d_in[25];
    const float* p2_b3    = (const float*)d_in[26];
    const float* p2_w2    = (const float*)d_in[27];
    const float* p2_b2    = (const float*)d_in[28];
    float* out = (float*)d_out;

    float *xln, *cln, *qkx, *qkc, *vtx, *vtc, *q, *k, *v, *y;
    float *x1x, *x1c, *hx, *hc, *t1x, *t3x, *t1c, *t3c;
    cudaGetSymbolAddress((void**)&xln, g_xln);
    cudaGetSymbolAddress((void**)&cln, g_cln);
    cudaGetSymbolAddress((void**)&qkx, g_qkx);
    cudaGetSymbolAddress((void**)&qkc, g_qkc);
    cudaGetSymbolAddress((void**)&vtx, g_vtx);
    cudaGetSymbolAddress((void**)&vtc, g_vtc);
    cudaGetSymbolAddress((void**)&q,   g_q);
    cudaGetSymbolAddress((void**)&k,   g_k);
    cudaGetSymbolAddress((void**)&v,   g_v);
    cudaGetSymbolAddress((void**)&y,   g_y);
    cudaGetSymbolAddress((void**)&x1x, g_x1x);
    cudaGetSymbolAddress((void**)&x1c, g_x1c);
    cudaGetSymbolAddress((void**)&hx,  g_hx);
    cudaGetSymbolAddress((void**)&hc,  g_hc);
    cudaGetSymbolAddress((void**)&t1x, g_t1x);
    cudaGetSymbolAddress((void**)&t3x, g_t3x);
    cudaGetSymbolAddress((void**)&t1c, g_t1c);
    cudaGetSymbolAddress((void**)&t3c, g_t3c);

    cudaFuncSetAttribute(attn_tc, cudaFuncAttributeMaxDynamicSharedMemorySize, ATN_SMEM);
    cudaFuncSetAttribute(mma_gemm_mj, cudaFuncAttributeMaxDynamicSharedMemorySize, MMG_SMEM);

    // 1) LayerNorm both streams (one launch)
    ln2_kernel<<<L_X + S_C, 256>>>(x, xln, L_X, c, cln);

    // 2) QKV GEMMs for both streams (one batched launch)
    {
        GJobs J; J.n = 4;
        int o = 0;
        J.j[0] = {cln, pc_qk_w, nullptr, nullptr, qkc, S_C, 2 * D, D, o}; o += nct(S_C, 2 * D);
        J.j[1] = {cln, pc_v_w,  pc_v_b,  nullptr, vtc, S_C, D,     D, o}; o += nct(S_C, D);
        J.j[2] = {xln, px_qk_w, nullptr, nullptr, qkx, L_X, 2 * D, D, o}; o += nct(L_X, 2 * D);
        J.j[3] = {xln, px_v_w,  px_v_b,  nullptr, vtx, L_X, D,     D, o}; o += nct(L_X, D);
        mma_gemm_mj<<<o, 256, MMG_SMEM>>>(J);
    }
    qk_finish_all<<<dim3(TT, H), HD>>>(qkc, qkx, pc_qn, pc_kn, px_qn, px_kn, freqs, q, k);
    v_finish_all<<<(TT * D + 255) / 256, 256>>>(vtc, vtx, v);

    // 3) causal attention (tensor cores)
    attn_tc<<<dim3(TT / 128, H), 256, ATN_SMEM>>>(q, k, v, y);

    // 4) output projections for both streams (batched)
    const float* yx = y + (size_t)S_C * D;
    {
        GJobs J; J.n = 2;
        int o = 0;
        J.j[0] = {yx, p1_proj_w, p1_proj_b, x, x1x, L_X, D, D, o}; o += nct(L_X, D);
        J.j[1] = {y,  p2_proj_w, p2_proj_b, c, x1c, S_C, D, D, o}; o += nct(S_C, D);
        J.j[2] = J.j[0]; J.j[3] = J.j[0];
        mma_gemm_mj<<<o, 256, MMG_SMEM>>>(J);
    }
    ln2_kernel<<<L_X + S_C, 256>>>(x1x, hx, L_X, x1c, hc);

    // 5) w1/w3 for both streams (batched)
    {
        GJobs J; J.n = 4;
        int o = 0;
        J.j[0] = {hx, p1_w1, p1_b1, nullptr, t1x, L_X, FF, D, o}; o += nct(L_X, FF);
        J.j[1] = {hx, p1_w3, p1_b3, nullptr, t3x, L_X, FF, D, o}; o += nct(L_X, FF);
        J.j[2] = {hc, p2_w1, p2_b1, nullptr, t1c, S_C, FF, D, o}; o += nct(S_C, FF);
        J.j[3] = {hc, p2_w3, p2_b3, nullptr, t3c, S_C, FF, D, o}; o += nct(S_C, FF);
        mma_gemm_mj<<<o, 256, MMG_SMEM>>>(J);
    }
    silu_all<<<(TT * FF + 255) / 256, 256>>>(t1x, t3x, t1x, L_X * FF, t1c, t3c, t1c, S_C * FF);

    // 6) w2 for both streams (batched)
    {
        GJobs J; J.n = 2;
        int o = 0;
        J.j[0] = {t1x, p1_w2, p1_b2, x1x, out,                    L_X, D, FF, o}; o += nct(L_X, D);
        J.j[1] = {t1c, p2_w2, p2_b2, x1c, out + (size_t)L_X * D,  S_C, D, FF, o}; o += nct(S_C, D);
        J.j[2] = J.j[0]; J.j[3] = J.j[0];
        mma_gemm_mj<<<o, 256, MMG_SMEM>>>(J);
    }
}

// round 7
// speedup vs baseline: 6.0270x; 1.0532x over previous
#include <cuda_runtime.h>
#include <cuda_bf16.h>
#include <cstdint>
#include <math.h>

// ---------------- problem constants ----------------
#define L_X   1536
#define S_C   512
#define TT    2048          // L_X + S_C
#define D     1024
#define H     16
#define HD    64
#define FF    4096

// ---------------- scratch (device globals; no cudaMalloc allowed) ----------
__device__ float g_xln[L_X * D];
__device__ float g_cln[S_C * D];
__device__ float g_qkx[L_X * 2 * D];
__device__ float g_qkc[S_C * 2 * D];
__device__ float g_q  [H * TT * HD];
__device__ float g_k  [H * TT * HD];
__device__ float g_v  [H * TT * HD];
__device__ float g_y  [TT * D];
__device__ float g_x1x[L_X * D];
__device__ float g_x1c[S_C * D];
__device__ float g_hx [L_X * D];
__device__ float g_hc [S_C * D];
__device__ float g_t1x[L_X * FF];
__device__ float g_t3x[L_X * FF];
__device__ float g_t1c[S_C * FF];
__device__ float g_t3c[S_C * FF];

// ---------------- utils ----------------
__device__ __forceinline__ float warpSum(float v) {
    #pragma unroll
    for (int o = 16; o > 0; o >>= 1) v += __shfl_xor_sync(0xffffffffu, v, o);
    return v;
}
__device__ __forceinline__ uint32_t f2tf32(float v) {
    uint32_t r;
    asm("cvt.rna.tf32.f32 %0, %1;" : "=r"(r) : "f"(v));
    return r;
}
__device__ __forceinline__ float ex2f(float x) {
    float y;
    asm("ex2.approx.f32 %0, %1;" : "=f"(y) : "f"(x));
    return y;
}
__device__ __forceinline__ void mma_tf32(float* d, const uint32_t* a, const uint32_t* b) {
    asm volatile(
        "mma.sync.aligned.m16n8k8.row.col.f32.tf32.tf32.f32 "
        "{%0,%1,%2,%3}, {%4,%5,%6,%7}, {%8,%9}, {%0,%1,%2,%3};"
        : "+f"(d[0]), "+f"(d[1]), "+f"(d[2]), "+f"(d[3])
        : "r"(a[0]), "r"(a[1]), "r"(a[2]), "r"(a[3]), "r"(b[0]), "r"(b[1]));
}
__device__ __forceinline__ uint32_t smem_u32(const void* p) {
    uint32_t a;
    asm("{ .reg .u64 t; cvta.to.shared.u64 t, %1; cvt.u32.u64 %0, t; }" : "=r"(a) : "l"(p));
    return a;
}
__device__ __forceinline__ void cp_async16(uint32_t saddr, const void* gaddr) {
    asm volatile("cp.async.cg.shared.global [%0], [%1], 16;" :: "r"(saddr), "l"(gaddr));
}
#define CP_COMMIT() asm volatile("cp.async.commit_group;" ::: "memory")
#define CP_WAIT1()  asm volatile("cp.async.wait_group 1;" ::: "memory")

// ---------------- LayerNorm pair (one launch, both streams) ----------------
__global__ void ln2_kernel(const float* __restrict__ in0, float* __restrict__ out0,
                           int rows0,
                           const float* __restrict__ in1, float* __restrict__ out1) {
    int row = blockIdx.x;
    const float* x;
    float* o;
    if (row < rows0) { x = in0 + (size_t)row * D; o = out0 + (size_t)row * D; }
    else             { x = in1 + (size_t)(row - rows0) * D; o = out1 + (size_t)(row - rows0) * D; }
    float s = 0.f, ss = 0.f;
    for (int i = threadIdx.x; i < D; i += 256) {
        float v = x[i]; s += v; ss += v * v;
    }
    __shared__ float shs[8], shss[8];
    float ws = warpSum(s), wss = warpSum(ss);
    int w = threadIdx.x >> 5;
    if ((threadIdx.x & 31) == 0) { shs[w] = ws; shss[w] = wss; }
    __syncthreads();
    float ts = 0.f, tss = 0.f;
    #pragma unroll
    for (int i = 0; i < 8; i++) { ts += shs[i]; tss += shss[i]; }
    float mean = ts * (1.0f / D);
    float var  = tss * (1.0f / D) - mean * mean;
    float inv  = rsqrtf(var + 1e-6f);
    for (int i = threadIdx.x; i < D; i += 256)
        o[i] = (x[i] - mean) * inv;
}

// ======================================================================
// Multi-job tf32 GEMM, 3-stage cp.async pipeline, swizzled smem.
// C[M,N] = A[M,K] @ B[N,K]^T (+bias[N]) (+resid). Raw fp32 bits -> tf32 mma.
// Tile 128x128x32; 128 threads = 4 warps (2x2), warp tile 64x64.
// mode 0: row-major C. mode 1: V attention layout [H][TT][HD], t_off given.
// ======================================================================
struct GJob {
    const float* A; const float* B; const float* bias; const float* resid;
    float* C; int N, K, off, mode, t_off;
};
struct GJobs { GJob j[4]; int n; };

#define SBUF 4096                           // floats per operand per stage
#define MMG_SMEM (3 * 2 * SBUF * 4)         // 98304 bytes
#define SWIZ(r, c) (((r) << 5) + ((c) ^ (((r) & 7) << 2)))

__global__ __launch_bounds__(128)
void mma_gemm_mj(GJobs jobs) {
    int ji = 0;
    if (jobs.n > 1 && (int)blockIdx.x >= jobs.j[1].off) ji = 1;
    if (jobs.n > 2 && (int)blockIdx.x >= jobs.j[2].off) ji = 2;
    if (jobs.n > 3 && (int)blockIdx.x >= jobs.j[3].off) ji = 3;
    const float* A = jobs.j[ji].A;
    const float* B = jobs.j[ji].B;
    const float* bias = jobs.j[ji].bias;
    const float* resid = jobs.j[ji].resid;
    float* C = jobs.j[ji].C;
    int N = jobs.j[ji].N, K = jobs.j[ji].K;
    int mode = jobs.j[ji].mode, t_off = jobs.j[ji].t_off;
    int lid0 = blockIdx.x - jobs.j[ji].off;
    int nbx = N >> 7;
    int by = lid0 / nbx, bx = lid0 - by * nbx;
    int m0 = by * 128, n0 = bx * 128;

    extern __shared__ float smf[];
    uint32_t sbase = smem_u32(smf);
    int tid = threadIdx.x;
    int wid = tid >> 5, lane = tid & 31;
    int gid = lane >> 2, tig = lane & 3;
    int warp_m = wid >> 1, warp_n = wid & 1;       // 2x2 warps, 64x64 each

    float acc[4][8][4];
    #pragma unroll
    for (int mt = 0; mt < 4; mt++)
        #pragma unroll
        for (int nt = 0; nt < 8; nt++)
            #pragma unroll
            for (int e = 0; e < 4; e++) acc[mt][nt][e] = 0.f;

    const int nchunk = K >> 5;
    int lr = tid >> 3;                 // 0..15
    int lc4 = (tid & 7) << 2;          // 0..28

    // prefetch chunks 0,1 into stages 0,1
    #pragma unroll
    for (int pc = 0; pc < 2; pc++) {
        const float* Ap = A + (size_t)m0 * K + pc * 32 + lc4;
        const float* Bp = B + (size_t)n0 * K + pc * 32 + lc4;
        uint32_t sA = sbase + pc * 2 * SBUF * 4;
        uint32_t sB = sA + SBUF * 4;
        #pragma unroll
        for (int l = 0; l < 8; l++) {
            int r = lr + l * 16;
            uint32_t so = SWIZ(r, lc4) * 4;
            cp_async16(sA + so, Ap + (size_t)r * K);
            cp_async16(sB + so, Bp + (size_t)r * K);
        }
        CP_COMMIT();
    }

    int st = 0;
    for (int i = 0; i < nchunk; i++) {
        CP_WAIT1();
        __syncthreads();
        if (i + 2 < nchunk) {
            int ps = st + 2; if (ps >= 3) ps -= 3;
            const float* Ap = A + (size_t)m0 * K + (i + 2) * 32 + lc4;
            const float* Bp = B + (size_t)n0 * K + (i + 2) * 32 + lc4;
            uint32_t sA = sbase + ps * 2 * SBUF * 4;
            uint32_t sB = sA + SBUF * 4;
            #pragma unroll
            for (int l = 0; l < 8; l++) {
                int r = lr + l * 16;
                uint32_t so = SWIZ(r, lc4) * 4;
                cp_async16(sA + so, Ap + (size_t)r * K);
                cp_async16(sB + so, Bp + (size_t)r * K);
            }
        }
        CP_COMMIT();
        const float* As = smf + st * 2 * SBUF;
        const float* Bs = As + SBUF;
        #pragma unroll
        for (int kk = 0; kk < 4; kk++) {
            int k0 = kk * 8;
            uint32_t af[4][4], bf[8][2];
            #pragma unroll
            for (int mt = 0; mt < 4; mt++) {
                int r0 = warp_m * 64 + mt * 16 + gid;
                const uint32_t* p0 = (const uint32_t*)As;
                af[mt][0] = p0[SWIZ(r0,     k0 + tig)];
                af[mt][1] = p0[SWIZ(r0 + 8, k0 + tig)];
                af[mt][2] = p0[SWIZ(r0,     k0 + tig + 4)];
                af[mt][3] = p0[SWIZ(r0 + 8, k0 + tig + 4)];
            }
            #pragma unroll
            for (int nt = 0; nt < 8; nt++) {
                int col = warp_n * 64 + nt * 8 + gid;
                const uint32_t* p = (const uint32_t*)Bs;
                bf[nt][0] = p[SWIZ(col, k0 + tig)];
                bf[nt][1] = p[SWIZ(col, k0 + tig + 4)];
            }
            #pragma unroll
            for (int mt = 0; mt < 4; mt++)
                #pragma unroll
                for (int nt = 0; nt < 8; nt++)
                    mma_tf32(acc[mt][nt], af[mt], bf[nt]);
        }
        st++; if (st >= 3) st = 0;
    }

    #pragma unroll
    for (int mt = 0; mt < 4; mt++) {
        #pragma unroll
        for (int nt = 0; nt < 8; nt++) {
            int row = m0 + warp_m * 64 + mt * 16 + gid;
            int col = n0 + warp_n * 64 + nt * 8 + tig * 2;
            #pragma unroll
            for (int half = 0; half < 2; half++) {
                int r = row + half * 8;
                float2 v = make_float2(acc[mt][nt][half * 2], acc[mt][nt][half * 2 + 1]);
                if (bias) {
                    float2 bv2 = *(const float2*)(bias + col);
                    v.x += bv2.x; v.y += bv2.y;
                }
                if (mode == 0) {
                    size_t off = (size_t)r * N + col;
                    if (resid) {
                        float2 rv = *(const float2*)(resid + off);
                        v.x += rv.x; v.y += rv.y;
                    }
                    *(float2*)(C + off) = v;
                } else {
                    // V layout: token r -> [h][t_off + r][d]
                    int hh = col >> 6, dd = col & 63;
                    *(float2*)(C + ((size_t)hh * TT + t_off + r) * HD + dd) = v;
                }
            }
        }
    }
}

// ---------------- qk finish (both streams, one launch) ----------------
__global__ void qk_finish_all(const float* __restrict__ qkc, const float* __restrict__ qkx,
                              const float* __restrict__ cqn, const float* __restrict__ ckn,
                              const float* __restrict__ xqn, const float* __restrict__ xkn,
                              const float* __restrict__ freqs,
                              float* __restrict__ Q, float* __restrict__ Ko) {
    int t = blockIdx.x, h = blockIdx.y, d = threadIdx.x;
    const float* qk; const float* qn; const float* kn; int row;
    if (t < S_C) { qk = qkc; qn = cqn; kn = ckn; row = t; }
    else         { qk = qkx; qn = xqn; kn = xkn; row = t - S_C; }
    float qv = qk[(size_t)row * (2 * D) + h * HD + d];
    float kv = qk[(size_t)row * (2 * D) + D + h * HD + d];
    __shared__ float sh[4];
    float sq = qv * qv, sk = kv * kv;
    #pragma unroll
    for (int o = 16; o > 0; o >>= 1) { sq += __shfl_xor_sync(0xffffffffu, sq, o); sk += __shfl_xor_sync(0xffffffffu, sk, o); }
    int w = d >> 5;
    if ((d & 31) == 0) { sh[w] = sq; sh[2 + w] = sk; }
    __syncthreads();
    float rq = rsqrtf((sh[0] + sh[1]) * (1.0f / HD) + 1e-6f);
    float rk = rsqrtf((sh[2] + sh[3]) * (1.0f / HD) + 1e-6f);
    __shared__ float sQ[HD], sK[HD];
    sQ[d] = qv * rq * qn[d];
    sK[d] = kv * rk * kn[d];
    __syncthreads();
    int i = d >> 1;
    float cs = freqs[((size_t)t * 32 + i) * 2 + 0];
    float sn = freqs[((size_t)t * 32 + i) * 2 + 1];
    float oq, ok;
    if ((d & 1) == 0) { oq = sQ[d] * cs - sQ[d + 1] * sn; ok = sK[d] * cs - sK[d + 1] * sn; }
    else              { oq = sQ[d - 1] * sn + sQ[d] * cs; ok = sK[d - 1] * sn + sK[d] * cs; }
    size_t off = ((size_t)h * TT + t) * HD + d;
    Q[off] = oq; Ko[off] = ok;
}

// ======================================================================
// Tensor-core flash attention (tf32 mma, causal).
// ======================================================================
#define AST 68
#define ATN_SMEM ((64 + 64 + 128) * AST * 4)

__global__ __launch_bounds__(256)
void attn_tc(const float* __restrict__ Q, const float* __restrict__ K,
             const float* __restrict__ V, float* __restrict__ Y) {
    extern __shared__ float sm[];
    float* Ks  = sm;
    float* VsT = sm + 64 * AST;
    float* Pw  = sm + 128 * AST;
    int tid = threadIdx.x, wid = tid >> 5, lane = tid & 31;
    int gid = lane >> 2, tig = lane & 3;
    int bxr = gridDim.x - 1 - blockIdx.x;
    int h = blockIdx.y;
    int q0 = bxr * 128;
    const float* Qh = Q + (size_t)h * TT * HD;
    const float* Kh = K + (size_t)h * TT * HD;
    const float* Vh = V + (size_t)h * TT * HD;
    const float QSC = 0.125f * 1.4426950408889634f;

    #pragma unroll
    for (int l = 0; l < 8; l++) {
        int e = tid + l * 256;
        int r = e >> 4, c4 = (e & 15) << 2;
        float4 v = *(const float4*)(Qh + (size_t)(q0 + r) * HD + c4);
        uint32_t* p = (uint32_t*)(Pw + r * AST + c4);
        p[0] = f2tf32(v.x * QSC); p[1] = f2tf32(v.y * QSC);
        p[2] = f2tf32(v.z * QSC); p[3] = f2tf32(v.w * QSC);
    }
    __syncthreads();
    uint32_t qf[8][4];
    int qrow = wid * 16 + gid;
    #pragma unroll
    for (int ks = 0; ks < 8; ks++) {
        int k0 = ks * 8;
        const uint32_t* p0 = (const uint32_t*)(Pw + qrow * AST + k0);
        const uint32_t* p1 = (const uint32_t*)(Pw + (qrow + 8) * AST + k0);
        qf[ks][0] = p0[tig];
        qf[ks][1] = p1[tig];
        qf[ks][2] = p0[tig + 4];
        qf[ks][3] = p1[tig + 4];
    }
    __syncwarp();

    float ofr[8][4];
    #pragma unroll
    for (int ot = 0; ot < 8; ot++)
        #pragma unroll
        for (int e = 0; e < 4; e++) ofr[ot][e] = 0.f;
    float m0r = -INFINITY, m1r = -INFINITY, l0r = 0.f, l1r = 0.f;

    int ntile = 2 * bxr + 2;
    for (int kt = 0; kt < ntile; kt++) {
        int k0g = kt * 64;
        __syncthreads();
        #pragma unroll
        for (int l = 0; l < 4; l++) {
            int e = tid + l * 256;
            int r = e >> 4, c4 = (e & 15) << 2;
            float4 kv = *(const float4*)(Kh + (size_t)(k0g + r) * HD + c4);
            uint32_t* pk = (uint32_t*)(Ks + r * AST + c4);
            pk[0] = f2tf32(kv.x); pk[1] = f2tf32(kv.y); pk[2] = f2tf32(kv.z); pk[3] = f2tf32(kv.w);
            float4 vv = *(const float4*)(Vh + (size_t)(k0g + r) * HD + c4);
            *(uint32_t*)(VsT + (c4 + 0) * AST + r) = f2tf32(vv.x);
            *(uint32_t*)(VsT + (c4 + 1) * AST + r) = f2tf32(vv.y);
            *(uint32_t*)(VsT + (c4 + 2) * AST + r) = f2tf32(vv.z);
            *(uint32_t*)(VsT + (c4 + 3) * AST + r) = f2tf32(vv.w);
        }
        __syncthreads();
        float sacc[8][4];
        #pragma unroll
        for (int nt = 0; nt < 8; nt++)
            #pragma unroll
            for (int e = 0; e < 4; e++) sacc[nt][e] = 0.f;
        #pragma unroll
        for (int ks = 0; ks < 8; ks++) {
            int k0 = ks * 8;
            #pragma unroll
            for (int nt = 0; nt < 8; nt++) {
                uint32_t bf[2];
                const uint32_t* p = (const uint32_t*)(Ks + (nt * 8 + gid) * AST + k0);
                bf[0] = p[tig];
                bf[1] = p[tig + 4];
                mma_tf32(sacc[nt], qf[ks], bf);
            }
        }
        if (kt >= ntile - 2) {
            int r0 = q0 + wid * 16 + gid;
            #pragma unroll
            for (int nt = 0; nt < 8; nt++) {
                int c0 = k0g + nt * 8 + tig * 2;
                if (c0 > r0)     sacc[nt][0] = -INFINITY;
                if (c0 + 1 > r0) sacc[nt][1] = -INFINITY;
                if (c0 > r0 + 8)     sacc[nt][2] = -INFINITY;
                if (c0 + 1 > r0 + 8) sacc[nt][3] = -INFINITY;
            }
        }
        float tm0 = -INFINITY, tm1 = -INFINITY;
        #pragma unroll
        for (int nt = 0; nt < 8; nt++) {
            tm0 = fmaxf(tm0, fmaxf(sacc[nt][0], sacc[nt][1]));
            tm1 = fmaxf(tm1, fmaxf(sacc[nt][2], sacc[nt][3]));
        }
        #pragma unroll
        for (int o = 1; o < 4; o <<= 1) {
            tm0 = fmaxf(tm0, __shfl_xor_sync(0xffffffffu, tm0, o));
            tm1 = fmaxf(tm1, __shfl_xor_sync(0xffffffffu, tm1, o));
        }
        float nm0 = fmaxf(m0r, tm0), nm1 = fmaxf(m1r, tm1);
        float c0 = ex2f(m0r - nm0), c1 = ex2f(m1r - nm1);
        m0r = nm0; m1r = nm1;
        float ps0 = 0.f, ps1 = 0.f;
        #pragma unroll
        for (int nt = 0; nt < 8; nt++) {
            float p00 = ex2f(sacc[nt][0] - nm0);
            float p01 = ex2f(sacc[nt][1] - nm0);
            float p10 = ex2f(sacc[nt][2] - nm1);
            float p11 = ex2f(sacc[nt][3] - nm1);
            ps0 += p00 + p01; ps1 += p10 + p11;
            uint32_t* pr0 = (uint32_t*)(Pw + (wid * 16 + gid) * AST + nt * 8 + tig * 2);
            uint32_t* pr1 = (uint32_t*)(Pw + (wid * 16 + gid + 8) * AST + nt * 8 + tig * 2);
            pr0[0] = f2tf32(p00); pr0[1] = f2tf32(p01);
            pr1[0] = f2tf32(p10); pr1[1] = f2tf32(p11);
        }
        #pragma unroll
        for (int o = 1; o < 4; o <<= 1) {
            ps0 += __shfl_xor_sync(0xffffffffu, ps0, o);
            ps1 += __shfl_xor_sync(0xffffffffu, ps1, o);
        }
        l0r = l0r * c0 + ps0;
        l1r = l1r * c1 + ps1;
        #pragma unroll
        for (int ot = 0; ot < 8; ot++) {
            ofr[ot][0] *= c0; ofr[ot][1] *= c0;
            ofr[ot][2] *= c1; ofr[ot][3] *= c1;
        }
        __syncwarp();
        #pragma unroll
        for (int ks = 0; ks < 8; ks++) {
            int k0 = ks * 8;
            uint32_t af[4];
            const uint32_t* p0 = (const uint32_t*)(Pw + (wid * 16 + gid) * AST + k0);
            const uint32_t* p1 = (const uint32_t*)(Pw + (wid * 16 + gid + 8) * AST + k0);
            af[0] = p0[tig];
            af[1] = p1[tig];
            af[2] = p0[tig + 4];
            af[3] = p1[tig + 4];
            #pragma unroll
            for (int ot = 0; ot < 8; ot++) {
                uint32_t bf[2];
                const uint32_t* p = (const uint32_t*)(VsT + (ot * 8 + gid) * AST + k0);
                bf[0] = p[tig];
                bf[1] = p[tig + 4];
                mma_tf32(ofr[ot], af, bf);
            }
        }
    }
    float i0 = 1.0f / l0r, i1 = 1.0f / l1r;
    int t0 = q0 + wid * 16 + gid, t1 = t0 + 8;
    #pragma unroll
    for (int ot = 0; ot < 8; ot++) {
        int col = h * HD + ot * 8 + tig * 2;
        *(float2*)(Y + (size_t)t0 * D + col) = make_float2(ofr[ot][0] * i0, ofr[ot][1] * i0);
        *(float2*)(Y + (size_t)t1 * D + col) = make_float2(ofr[ot][2] * i1, ofr[ot][3] * i1);
    }
}

// ---------------- SiLU gate (both streams) ----------------
__global__ void silu_all(const float* __restrict__ a0, const float* __restrict__ b0,
                         float* __restrict__ g0, int n0,
                         const float* __restrict__ a1, const float* __restrict__ b1,
                         float* __restrict__ g1, int n1) {
    int i = blockIdx.x * 256 + threadIdx.x;
    if (i < n0) {
        float x = a0[i];
        g0[i] = (x / (1.0f + expf(-x))) * b0[i];
    } else if (i < n0 + n1) {
        int j = i - n0;
        float x = a1[j];
        g1[j] = (x / (1.0f + expf(-x))) * b1[j];
    }
}

// ---------------- host launcher ----------------
static inline int nct(int M, int N) { return (M / 128) * (N / 128); }

extern "C" void kernel_launch(void* const* d_in, const int* in_sizes, int n_in,
                              void* d_out, int out_size) {
    const float* x        = (const float*)d_in[0];
    const float* c        = (const float*)d_in[1];
    const float* freqs    = (const float*)d_in[2];
    const float* px_qk_w  = (const float*)d_in[3];
    const float* px_qn    = (const float*)d_in[4];
    const float* px_kn    = (const float*)d_in[5];
    const float* px_v_w   = (const float*)d_in[6];
    const float* px_v_b   = (const float*)d_in[7];
    const float* pc_qk_w  = (const float*)d_in[8];
    const float* pc_qn    = (const float*)d_in[9];
    const float* pc_kn    = (const float*)d_in[10];
    const float* pc_v_w   = (const float*)d_in[11];
    const float* pc_v_b   = (const float*)d_in[12];
    const float* p1_proj_w = (const float*)d_in[13];
    const float* p1_proj_b = (const float*)d_in[14];
    const float* p1_w1    = (const float*)d_in[15];
    const float* p1_b1    = (const float*)d_in[16];
    const float* p1_w3    = (const float*)d_in[17];
    const float* p1_b3    = (const float*)d_in[18];
    const float* p1_w2    = (const float*)d_in[19];
    const float* p1_b2    = (const float*)d_in[20];
    const float* p2_proj_w = (const float*)d_in[21];
    const float* p2_proj_b = (const float*)d_in[22];
    const float* p2_w1    = (const float*)d_in[23];
    const float* p2_b1    = (const float*)d_in[24];
    const float* p2_w3    = (const float*)d_in[25];
    const float* p2_b3    = (const float*)d_in[26];
    const float* p2_w2    = (const float*)d_in[27];
    const float* p2_b2    = (const float*)d_in[28];
    float* out = (float*)d_out;

    float *xln, *cln, *qkx, *qkc, *q, *k, *v, *y;
    float *x1x, *x1c, *hx, *hc, *t1x, *t3x, *t1c, *t3c;
    cudaGetSymbolAddress((void**)&xln, g_xln);
    cudaGetSymbolAddress((void**)&cln, g_cln);
    cudaGetSymbolAddress((void**)&qkx, g_qkx);
    cudaGetSymbolAddress((void**)&qkc, g_qkc);
    cudaGetSymbolAddress((void**)&q,   g_q);
    cudaGetSymbolAddress((void**)&k,   g_k);
    cudaGetSymbolAddress((void**)&v,   g_v);
    cudaGetSymbolAddress((void**)&y,   g_y);
    cudaGetSymbolAddress((void**)&x1x, g_x1x);
    cudaGetSymbolAddress((void**)&x1c, g_x1c);
    cudaGetSymbolAddress((void**)&hx,  g_hx);
    cudaGetSymbolAddress((void**)&hc,  g_hc);
    cudaGetSymbolAddress((void**)&t1x, g_t1x);
    cudaGetSymbolAddress((void**)&t3x, g_t3x);
    cudaGetSymbolAddress((void**)&t1c, g_t1c);
    cudaGetSymbolAddress((void**)&t3c, g_t3c);

    cudaFuncSetAttribute(attn_tc, cudaFuncAttributeMaxDynamicSharedMemorySize, ATN_SMEM);
    cudaFuncSetAttribute(mma_gemm_mj, cudaFuncAttributeMaxDynamicSharedMemorySize, MMG_SMEM);

    // 1) LayerNorm both streams (one launch)
    ln2_kernel<<<L_X + S_C, 256>>>(x, xln, L_X, c, cln);

    // 2) QKV GEMMs for both streams (one batched launch); V written in attn layout
    {
        GJobs J; J.n = 4;
        int o = 0;
        J.j[0] = {cln, pc_qk_w, nullptr, nullptr, qkc, 2 * D, D, o, 0, 0};  o += nct(S_C, 2 * D);
        J.j[1] = {cln, pc_v_w,  pc_v_b,  nullptr, v,   D,     D, o, 1, 0};  o += nct(S_C, D);
        J.j[2] = {xln, px_qk_w, nullptr, nullptr, qkx, 2 * D, D, o, 0, 0};  o += nct(L_X, 2 * D);
        J.j[3] = {xln, px_v_w,  px_v_b,  nullptr, v,   D,     D, o, 1, S_C}; o += nct(L_X, D);
        mma_gemm_mj<<<o, 128, MMG_SMEM>>>(J);
    }
    qk_finish_all<<<dim3(TT, H), HD>>>(qkc, qkx, pc_qn, pc_kn, px_qn, px_kn, freqs, q, k);

    // 3) causal attention (tensor cores)
    attn_tc<<<dim3(TT / 128, H), 256, ATN_SMEM>>>(q, k, v, y);

    // 4) output projections for both streams (batched)
    const float* yx = y + (size_t)S_C * D;
    {
        GJobs J; J.n = 2;
        int o = 0;
        J.j[0] = {yx, p1_proj_w, p1_proj_b, x, x1x, D, D, o, 0, 0}; o += nct(L_X, D);
        J.j[1] = {y,  p2_proj_w, p2_proj_b, c, x1c, D, D, o, 0, 0}; o += nct(S_C, D);
        J.j[2] = J.j[0]; J.j[3] = J.j[0];
        mma_gemm_mj<<<o, 128, MMG_SMEM>>>(J);
    }
    ln2_kernel<<<L_X + S_C, 256>>>(x1x, hx, L_X, x1c, hc);

    // 5) w1/w3 for both streams (batched)
    {
        GJobs J; J.n = 4;
        int o = 0;
        J.j[0] = {hx, p1_w1, p1_b1, nullptr, t1x, FF, D, o, 0, 0}; o += nct(L_X, FF);
        J.j[1] = {hx, p1_w3, p1_b3, nullptr, t3x, FF, D, o, 0, 0}; o += nct(L_X, FF);
        J.j[2] = {hc, p2_w1, p2_b1, nullptr, t1c, FF, D, o, 0, 0}; o += nct(S_C, FF);
        J.j[3] = {hc, p2_w3, p2_b3, nullptr, t3c, FF, D, o, 0, 0}; o += nct(S_C, FF);
        mma_gemm_mj<<<o, 128, MMG_SMEM>>>(J);
    }
    silu_all<<<(TT * FF + 255) / 256, 256>>>(t1x, t3x, t1x, L_X * FF, t1c, t3c, t1c, S_C * FF);

    // 6) w2 for both streams (batched)
    {
        GJobs J; J.n = 2;
        int o = 0;
        J.j[0] = {t1x, p1_w2, p1_b2, x1x, out,                   D, FF, o, 0, 0}; o += nct(L_X, D);
        J.j[1] = {t1c, p2_w2, p2_b2, x1c, out + (size_t)L_X * D, D, FF, o, 0, 0}; o += nct(S_C, D);
        J.j[2] = J.j[0]; J.j[3] = J.j[0];
        mma_gemm_mj<<<o, 128, MMG_SMEM>>>(J);
    }
}

// round 8
// speedup vs baseline: 6.5915x; 1.0937x over previous
#include <cuda_runtime.h>
#include <cuda_bf16.h>
#include <cstdint>
#include <math.h>

// ---------------- problem constants ----------------
#define L_X   1536
#define S_C   512
#define TT    2048          // L_X + S_C
#define D     1024
#define H     16
#define HD    64
#define FF    4096

// ---------------- scratch (device globals; no cudaMalloc allowed) ----------
__device__ float g_xln[L_X * D];
__device__ float g_cln[S_C * D];
__device__ float g_qkx[L_X * 2 * D];
__device__ float g_qkc[S_C * 2 * D];
__device__ float g_q  [H * TT * HD];
__device__ float g_k  [H * TT * HD];
__device__ float g_v  [H * TT * HD];
__device__ float g_y  [TT * D];
__device__ float g_x1x[L_X * D];
__device__ float g_x1c[S_C * D];
__device__ float g_hx [L_X * D];
__device__ float g_hc [S_C * D];
__device__ float g_t1x[L_X * FF];
__device__ float g_t3x[L_X * FF];
__device__ float g_t1c[S_C * FF];
__device__ float g_t3c[S_C * FF];

// ---------------- utils ----------------
__device__ __forceinline__ float warpSum(float v) {
    #pragma unroll
    for (int o = 16; o > 0; o >>= 1) v += __shfl_xor_sync(0xffffffffu, v, o);
    return v;
}
__device__ __forceinline__ uint32_t f2tf32(float v) {
    uint32_t r;
    asm("cvt.rna.tf32.f32 %0, %1;" : "=r"(r) : "f"(v));
    return r;
}
__device__ __forceinline__ float ex2f(float x) {
    float y;
    asm("ex2.approx.f32 %0, %1;" : "=f"(y) : "f"(x));
    return y;
}
__device__ __forceinline__ void mma_tf32(float* d, const uint32_t* a, const uint32_t* b) {
    asm volatile(
        "mma.sync.aligned.m16n8k8.row.col.f32.tf32.tf32.f32 "
        "{%0,%1,%2,%3}, {%4,%5,%6,%7}, {%8,%9}, {%0,%1,%2,%3};"
        : "+f"(d[0]), "+f"(d[1]), "+f"(d[2]), "+f"(d[3])
        : "r"(a[0]), "r"(a[1]), "r"(a[2]), "r"(a[3]), "r"(b[0]), "r"(b[1]));
}
__device__ __forceinline__ uint32_t smem_u32(const void* p) {
    uint32_t a;
    asm("{ .reg .u64 t; cvta.to.shared.u64 t, %1; cvt.u32.u64 %0, t; }" : "=r"(a) : "l"(p));
    return a;
}
__device__ __forceinline__ void cp_async16(uint32_t saddr, const void* gaddr) {
    asm volatile("cp.async.cg.shared.global [%0], [%1], 16;" :: "r"(saddr), "l"(gaddr));
}
#define CP_COMMIT() asm volatile("cp.async.commit_group;" ::: "memory")
#define CP_WAIT0()  asm volatile("cp.async.wait_group 0;" ::: "memory")
#define CP_WAIT1()  asm volatile("cp.async.wait_group 1;" ::: "memory")

// ---------------- LayerNorm pair (one launch, both streams) ----------------
__global__ void ln2_kernel(const float* __restrict__ in0, float* __restrict__ out0,
                           int rows0,
                           const float* __restrict__ in1, float* __restrict__ out1) {
    int row = blockIdx.x;
    const float* x;
    float* o;
    if (row < rows0) { x = in0 + (size_t)row * D; o = out0 + (size_t)row * D; }
    else             { x = in1 + (size_t)(row - rows0) * D; o = out1 + (size_t)(row - rows0) * D; }
    float s = 0.f, ss = 0.f;
    for (int i = threadIdx.x; i < D; i += 256) {
        float v = x[i]; s += v; ss += v * v;
    }
    __shared__ float shs[8], shss[8];
    float ws = warpSum(s), wss = warpSum(ss);
    int w = threadIdx.x >> 5;
    if ((threadIdx.x & 31) == 0) { shs[w] = ws; shss[w] = wss; }
    __syncthreads();
    float ts = 0.f, tss = 0.f;
    #pragma unroll
    for (int i = 0; i < 8; i++) { ts += shs[i]; tss += shss[i]; }
    float mean = ts * (1.0f / D);
    float var  = tss * (1.0f / D) - mean * mean;
    float inv  = rsqrtf(var + 1e-6f);
    for (int i = threadIdx.x; i < D; i += 256)
        o[i] = (x[i] - mean) * inv;
}

// ======================================================================
// Multi-job tf32 GEMM, 3-stage cp.async pipeline, swizzled smem.
// (unchanged from R7)
// ======================================================================
struct GJob {
    const float* A; const float* B; const float* bias; const float* resid;
    float* C; int N, K, off, mode, t_off;
};
struct GJobs { GJob j[4]; int n; };

#define SBUF 4096
#define MMG_SMEM (3 * 2 * SBUF * 4)
#define SWIZ(r, c) (((r) << 5) + ((c) ^ (((r) & 7) << 2)))

__global__ __launch_bounds__(128)
void mma_gemm_mj(GJobs jobs) {
    int ji = 0;
    if (jobs.n > 1 && (int)blockIdx.x >= jobs.j[1].off) ji = 1;
    if (jobs.n > 2 && (int)blockIdx.x >= jobs.j[2].off) ji = 2;
    if (jobs.n > 3 && (int)blockIdx.x >= jobs.j[3].off) ji = 3;
    const float* A = jobs.j[ji].A;
    const float* B = jobs.j[ji].B;
    const float* bias = jobs.j[ji].bias;
    const float* resid = jobs.j[ji].resid;
    float* C = jobs.j[ji].C;
    int N = jobs.j[ji].N, K = jobs.j[ji].K;
    int mode = jobs.j[ji].mode, t_off = jobs.j[ji].t_off;
    int lid0 = blockIdx.x - jobs.j[ji].off;
    int nbx = N >> 7;
    int by = lid0 / nbx, bx = lid0 - by * nbx;
    int m0 = by * 128, n0 = bx * 128;

    extern __shared__ float smf[];
    uint32_t sbase = smem_u32(smf);
    int tid = threadIdx.x;
    int wid = tid >> 5, lane = tid & 31;
    int gid = lane >> 2, tig = lane & 3;
    int warp_m = wid >> 1, warp_n = wid & 1;

    float acc[4][8][4];
    #pragma unroll
    for (int mt = 0; mt < 4; mt++)
        #pragma unroll
        for (int nt = 0; nt < 8; nt++)
            #pragma unroll
            for (int e = 0; e < 4; e++) acc[mt][nt][e] = 0.f;

    const int nchunk = K >> 5;
    int lr = tid >> 3;
    int lc4 = (tid & 7) << 2;

    #pragma unroll
    for (int pc = 0; pc < 2; pc++) {
        const float* Ap = A + (size_t)m0 * K + pc * 32 + lc4;
        const float* Bp = B + (size_t)n0 * K + pc * 32 + lc4;
        uint32_t sA = sbase + pc * 2 * SBUF * 4;
        uint32_t sB = sA + SBUF * 4;
        #pragma unroll
        for (int l = 0; l < 8; l++) {
            int r = lr + l * 16;
            uint32_t so = SWIZ(r, lc4) * 4;
            cp_async16(sA + so, Ap + (size_t)r * K);
            cp_async16(sB + so, Bp + (size_t)r * K);
        }
        CP_COMMIT();
    }

    int st = 0;
    for (int i = 0; i < nchunk; i++) {
        CP_WAIT1();
        __syncthreads();
        if (i + 2 < nchunk) {
            int ps = st + 2; if (ps >= 3) ps -= 3;
            const float* Ap = A + (size_t)m0 * K + (i + 2) * 32 + lc4;
            const float* Bp = B + (size_t)n0 * K + (i + 2) * 32 + lc4;
            uint32_t sA = sbase + ps * 2 * SBUF * 4;
            uint32_t sB = sA + SBUF * 4;
            #pragma unroll
            for (int l = 0; l < 8; l++) {
                int r = lr + l * 16;
                uint32_t so = SWIZ(r, lc4) * 4;
                cp_async16(sA + so, Ap + (size_t)r * K);
                cp_async16(sB + so, Bp + (size_t)r * K);
            }
        }
        CP_COMMIT();
        const float* As = smf + st * 2 * SBUF;
        const float* Bs = As + SBUF;
        #pragma unroll
        for (int kk = 0; kk < 4; kk++) {
            int k0 = kk * 8;
            uint32_t af[4][4], bf[8][2];
            #pragma unroll
            for (int mt = 0; mt < 4; mt++) {
                int r0 = warp_m * 64 + mt * 16 + gid;
                const uint32_t* p0 = (const uint32_t*)As;
                af[mt][0] = p0[SWIZ(r0,     k0 + tig)];
                af[mt][1] = p0[SWIZ(r0 + 8, k0 + tig)];
                af[mt][2] = p0[SWIZ(r0,     k0 + tig + 4)];
                af[mt][3] = p0[SWIZ(r0 + 8, k0 + tig + 4)];
            }
            #pragma unroll
            for (int nt = 0; nt < 8; nt++) {
                int col = warp_n * 64 + nt * 8 + gid;
                const uint32_t* p = (const uint32_t*)Bs;
                bf[nt][0] = p[SWIZ(col, k0 + tig)];
                bf[nt][1] = p[SWIZ(col, k0 + tig + 4)];
            }
            #pragma unroll
            for (int mt = 0; mt < 4; mt++)
                #pragma unroll
                for (int nt = 0; nt < 8; nt++)
                    mma_tf32(acc[mt][nt], af[mt], bf[nt]);
        }
        st++; if (st >= 3) st = 0;
    }

    #pragma unroll
    for (int mt = 0; mt < 4; mt++) {
        #pragma unroll
        for (int nt = 0; nt < 8; nt++) {
            int row = m0 + warp_m * 64 + mt * 16 + gid;
            int col = n0 + warp_n * 64 + nt * 8 + tig * 2;
            #pragma unroll
            for (int half = 0; half < 2; half++) {
                int r = row + half * 8;
                float2 v = make_float2(acc[mt][nt][half * 2], acc[mt][nt][half * 2 + 1]);
                if (bias) {
                    float2 bv2 = *(const float2*)(bias + col);
                    v.x += bv2.x; v.y += bv2.y;
                }
                if (mode == 0) {
                    size_t off = (size_t)r * N + col;
                    if (resid) {
                        float2 rv = *(const float2*)(resid + off);
                        v.x += rv.x; v.y += rv.y;
                    }
                    *(float2*)(C + off) = v;
                } else {
                    int hh = col >> 6, dd = col & 63;
                    *(float2*)(C + ((size_t)hh * TT + t_off + r) * HD + dd) = v;
                }
            }
        }
    }
}

// ---------------- qk finish (both streams, one launch) ----------------
__global__ void qk_finish_all(const float* __restrict__ qkc, const float* __restrict__ qkx,
                              const float* __restrict__ cqn, const float* __restrict__ ckn,
                              const float* __restrict__ xqn, const float* __restrict__ xkn,
                              const float* __restrict__ freqs,
                              float* __restrict__ Q, float* __restrict__ Ko) {
    int t = blockIdx.x, h = blockIdx.y, d = threadIdx.x;
    const float* qk; const float* qn; const float* kn; int row;
    if (t < S_C) { qk = qkc; qn = cqn; kn = ckn; row = t; }
    else         { qk = qkx; qn = xqn; kn = xkn; row = t - S_C; }
    float qv = qk[(size_t)row * (2 * D) + h * HD + d];
    float kv = qk[(size_t)row * (2 * D) + D + h * HD + d];
    __shared__ float sh[4];
    float sq = qv * qv, sk = kv * kv;
    #pragma unroll
    for (int o = 16; o > 0; o >>= 1) { sq += __shfl_xor_sync(0xffffffffu, sq, o); sk += __shfl_xor_sync(0xffffffffu, sk, o); }
    int w = d >> 5;
    if ((d & 31) == 0) { sh[w] = sq; sh[2 + w] = sk; }
    __syncthreads();
    float rq = rsqrtf((sh[0] + sh[1]) * (1.0f / HD) + 1e-6f);
    float rk = rsqrtf((sh[2] + sh[3]) * (1.0f / HD) + 1e-6f);
    __shared__ float sQ[HD], sK[HD];
    sQ[d] = qv * rq * qn[d];
    sK[d] = kv * rk * kn[d];
    __syncthreads();
    int i = d >> 1;
    float cs = freqs[((size_t)t * 32 + i) * 2 + 0];
    float sn = freqs[((size_t)t * 32 + i) * 2 + 1];
    float oq, ok;
    if ((d & 1) == 0) { oq = sQ[d] * cs - sQ[d + 1] * sn; ok = sK[d] * cs - sK[d + 1] * sn; }
    else              { oq = sQ[d - 1] * sn + sQ[d] * cs; ok = sK[d - 1] * sn + sK[d] * cs; }
    size_t off = ((size_t)h * TT + t) * HD + d;
    Q[off] = oq; Ko[off] = ok;
}

// ======================================================================
// Tensor-core flash attention, 64-row q-tiles, cp.async double-buffered
// K/V (natural layout, raw-bit tf32). Grid (32, H), 128 threads.
// smem (floats, stride 72): Pw[64x72] | Ks0 | Ks1 | Vs0 | Vs1 (64x72 each)
// ======================================================================
#define AST 72
#define ATN_SMEM (5 * 64 * AST * 4)     // 92160 bytes

__global__ __launch_bounds__(128)
void attn_tc(const float* __restrict__ Q, const float* __restrict__ K,
             const float* __restrict__ V, float* __restrict__ Y) {
    extern __shared__ float sm[];
    float* Pw = sm;
    uint32_t sbase = smem_u32(sm);
    int tid = threadIdx.x, wid = tid >> 5, lane = tid & 31;
    int gid = lane >> 2, tig = lane & 3;
    int bxr = 31 - blockIdx.x;               // heavy tiles first
    int h = blockIdx.y;
    int q0 = bxr * 64;
    const float* Qh = Q + (size_t)h * TT * HD;
    const float* Kh = K + (size_t)h * TT * HD;
    const float* Vh = V + (size_t)h * TT * HD;
    const float QSC = 0.125f * 1.4426950408889634f;

    int lrow = tid >> 4;              // 0..7  (r = lrow + l*8)
    int lc4 = (tid & 15) << 2;        // 0..60

    // prefetch K/V tile 0
    {
        const float* Kp = Kh;
        const float* Vp = Vh;
        uint32_t kb = sbase + (64 * AST) * 4;          // Ks0
        uint32_t vb = sbase + (3 * 64 * AST) * 4;      // Vs0
        #pragma unroll
        for (int l = 0; l < 8; l++) {
            int r = lrow + l * 8;
            uint32_t so = (r * AST + lc4) * 4;
            cp_async16(kb + so, Kp + (size_t)r * HD + lc4);
            cp_async16(vb + so, Vp + (size_t)r * HD + lc4);
        }
        CP_COMMIT();
    }

    // stage Q (scaled, tf32 RNA) into Pw
    #pragma unroll
    for (int l = 0; l < 8; l++) {
        int e = tid + l * 128;
        int r = e >> 4, c4 = (e & 15) << 2;
        float4 v = *(const float4*)(Qh + (size_t)(q0 + r) * HD + c4);
        uint32_t* p = (uint32_t*)(Pw + r * AST + c4);
        p[0] = f2tf32(v.x * QSC); p[1] = f2tf32(v.y * QSC);
        p[2] = f2tf32(v.z * QSC); p[3] = f2tf32(v.w * QSC);
    }
    __syncthreads();
    uint32_t qf[8][4];
    int qrow = wid * 16 + gid;
    #pragma unroll
    for (int ks = 0; ks < 8; ks++) {
        int k0 = ks * 8;
        const uint32_t* p0 = (const uint32_t*)(Pw + qrow * AST + k0);
        const uint32_t* p1 = (const uint32_t*)(Pw + (qrow + 8) * AST + k0);
        qf[ks][0] = p0[tig];
        qf[ks][1] = p1[tig];
        qf[ks][2] = p0[tig + 4];
        qf[ks][3] = p1[tig + 4];
    }
    __syncwarp();

    float ofr[8][4];
    #pragma unroll
    for (int ot = 0; ot < 8; ot++)
        #pragma unroll
        for (int e = 0; e < 4; e++) ofr[ot][e] = 0.f;
    float m0r = -INFINITY, m1r = -INFINITY, l0r = 0.f, l1r = 0.f;

    int ntile = bxr + 1;
    for (int kt = 0; kt < ntile; kt++) {
        int k0g = kt * 64;
        int buf = kt & 1;
        const float* Ksb = sm + (1 + buf) * 64 * AST;
        const float* Vsb = sm + (3 + buf) * 64 * AST;
        CP_WAIT0();
        __syncthreads();
        // S = Q K^T
        float sacc[8][4];
        #pragma unroll
        for (int nt = 0; nt < 8; nt++)
            #pragma unroll
            for (int e = 0; e < 4; e++) sacc[nt][e] = 0.f;
        #pragma unroll
        for (int ks = 0; ks < 8; ks++) {
            int k0 = ks * 8;
            #pragma unroll
            for (int nt = 0; nt < 8; nt++) {
                uint32_t bf[2];
                const uint32_t* p = (const uint32_t*)(Ksb + (nt * 8 + gid) * AST + k0);
                bf[0] = p[tig];
                bf[1] = p[tig + 4];
                mma_tf32(sacc[nt], qf[ks], bf);
            }
        }
        // prefetch next tile (other buffers) — overlaps softmax + PV
        if (kt + 1 < ntile) {
            const float* Kp = Kh + (size_t)(k0g + 64) * HD;
            const float* Vp = Vh + (size_t)(k0g + 64) * HD;
            uint32_t kb = sbase + ((1 + (buf ^ 1)) * 64 * AST) * 4;
            uint32_t vb = sbase + ((3 + (buf ^ 1)) * 64 * AST) * 4;
            #pragma unroll
            for (int l = 0; l < 8; l++) {
                int r = lrow + l * 8;
                uint32_t so = (r * AST + lc4) * 4;
                cp_async16(kb + so, Kp + (size_t)r * HD + lc4);
                cp_async16(vb + so, Vp + (size_t)r * HD + lc4);
            }
        }
        CP_COMMIT();
        // causal mask on diagonal tile
        if (kt == ntile - 1) {
            int r0 = q0 + wid * 16 + gid;
            #pragma unroll
            for (int nt = 0; nt < 8; nt++) {
                int c0 = k0g + nt * 8 + tig * 2;
                if (c0 > r0)     sacc[nt][0] = -INFINITY;
                if (c0 + 1 > r0) sacc[nt][1] = -INFINITY;
                if (c0 > r0 + 8)     sacc[nt][2] = -INFINITY;
                if (c0 + 1 > r0 + 8) sacc[nt][3] = -INFINITY;
            }
        }
        // online softmax
        float tm0 = -INFINITY, tm1 = -INFINITY;
        #pragma unroll
        for (int nt = 0; nt < 8; nt++) {
            tm0 = fmaxf(tm0, fmaxf(sacc[nt][0], sacc[nt][1]));
            tm1 = fmaxf(tm1, fmaxf(sacc[nt][2], sacc[nt][3]));
        }
        #pragma unroll
        for (int o = 1; o < 4; o <<= 1) {
            tm0 = fmaxf(tm0, __shfl_xor_sync(0xffffffffu, tm0, o));
            tm1 = fmaxf(tm1, __shfl_xor_sync(0xffffffffu, tm1, o));
        }
        float nm0 = fmaxf(m0r, tm0), nm1 = fmaxf(m1r, tm1);
        float c0 = ex2f(m0r - nm0), c1 = ex2f(m1r - nm1);
        m0r = nm0; m1r = nm1;
        float ps0 = 0.f, ps1 = 0.f;
        #pragma unroll
        for (int nt = 0; nt < 8; nt++) {
            float p00 = ex2f(sacc[nt][0] - nm0);
            float p01 = ex2f(sacc[nt][1] - nm0);
            float p10 = ex2f(sacc[nt][2] - nm1);
            float p11 = ex2f(sacc[nt][3] - nm1);
            ps0 += p00 + p01; ps1 += p10 + p11;
            uint32_t* pr0 = (uint32_t*)(Pw + (wid * 16 + gid) * AST + nt * 8 + tig * 2);
            uint32_t* pr1 = (uint32_t*)(Pw + (wid * 16 + gid + 8) * AST + nt * 8 + tig * 2);
            pr0[0] = f2tf32(p00); pr0[1] = f2tf32(p01);
            pr1[0] = f2tf32(p10); pr1[1] = f2tf32(p11);
        }
        #pragma unroll
        for (int o = 1; o < 4; o <<= 1) {
            ps0 += __shfl_xor_sync(0xffffffffu, ps0, o);
            ps1 += __shfl_xor_sync(0xffffffffu, ps1, o);
        }
        l0r = l0r * c0 + ps0;
        l1r = l1r * c1 + ps1;
        #pragma unroll
        for (int ot = 0; ot < 8; ot++) {
            ofr[ot][0] *= c0; ofr[ot][1] *= c0;
            ofr[ot][2] *= c1; ofr[ot][3] *= c1;
        }
        __syncwarp();
        // O += P V   (B from natural-layout Vs)
        #pragma unroll
        for (int ks = 0; ks < 8; ks++) {
            int k0 = ks * 8;
            uint32_t af[4];
            const uint32_t* p0 = (const uint32_t*)(Pw + (wid * 16 + gid) * AST + k0);
            const uint32_t* p1 = (const uint32_t*)(Pw + (wid * 16 + gid + 8) * AST + k0);
            af[0] = p0[tig];
            af[1] = p1[tig];
            af[2] = p0[tig + 4];
            af[3] = p1[tig + 4];
            #pragma unroll
            for (int ot = 0; ot < 8; ot++) {
                uint32_t bf[2];
                const uint32_t* pv0 = (const uint32_t*)(Vsb + (k0 + tig) * AST + ot * 8 + gid);
                const uint32_t* pv1 = (const uint32_t*)(Vsb + (k0 + tig + 4) * AST + ot * 8 + gid);
                bf[0] = pv0[0];
                bf[1] = pv1[0];
                mma_tf32(ofr[ot], af, bf);
            }
        }
        __syncthreads();   // all warps done with Pw before next tile's softmax writes
    }
    float i0 = 1.0f / l0r, i1 = 1.0f / l1r;
    int t0 = q0 + wid * 16 + gid, t1 = t0 + 8;
    #pragma unroll
    for (int ot = 0; ot < 8; ot++) {
        int col = h * HD + ot * 8 + tig * 2;
        *(float2*)(Y + (size_t)t0 * D + col) = make_float2(ofr[ot][0] * i0, ofr[ot][1] * i0);
        *(float2*)(Y + (size_t)t1 * D + col) = make_float2(ofr[ot][2] * i1, ofr[ot][3] * i1);
    }
}

// ---------------- SiLU gate (both streams) ----------------
__global__ void silu_all(const float* __restrict__ a0, const float* __restrict__ b0,
                         float* __restrict__ g0, int n0,
                         const float* __restrict__ a1, const float* __restrict__ b1,
                         float* __restrict__ g1, int n1) {
    int i = blockIdx.x * 256 + threadIdx.x;
    if (i < n0) {
        float x = a0[i];
        g0[i] = (x / (1.0f + expf(-x))) * b0[i];
    } else if (i < n0 + n1) {
        int j = i - n0;
        float x = a1[j];
        g1[j] = (x / (1.0f + expf(-x))) * b1[j];
    }
}

// ---------------- host launcher ----------------
static inline int nct(int M, int N) { return (M / 128) * (N / 128); }

extern "C" void kernel_launch(void* const* d_in, const int* in_sizes, int n_in,
                              void* d_out, int out_size) {
    const float* x        = (const float*)d_in[0];
    const float* c        = (const float*)d_in[1];
    const float* freqs    = (const float*)d_in[2];
    const float* px_qk_w  = (const float*)d_in[3];
    const float* px_qn    = (const float*)d_in[4];
    const float* px_kn    = (const float*)d_in[5];
    const float* px_v_w   = (const float*)d_in[6];
    const float* px_v_b   = (const float*)d_in[7];
    const float* pc_qk_w  = (const float*)d_in[8];
    const float* pc_qn    = (const float*)d_in[9];
    const float* pc_kn    = (const float*)d_in[10];
    const float* pc_v_w   = (const float*)d_in[11];
    const float* pc_v_b   = (const float*)d_in[12];
    const float* p1_proj_w = (const float*)d_in[13];
    const float* p1_proj_b = (const float*)d_in[14];
    const float* p1_w1    = (const float*)d_in[15];
    const float* p1_b1    = (const float*)d_in[16];
    const float* p1_w3    = (const float*)d_in[17];
    const float* p1_b3    = (const float*)d_in[18];
    const float* p1_w2    = (const float*)d_in[19];
    const float* p1_b2    = (const float*)d_in[20];
    const float* p2_proj_w = (const float*)d_in[21];
    const float* p2_proj_b = (const float*)d_in[22];
    const float* p2_w1    = (const float*)d_in[23];
    const float* p2_b1    = (const float*)d_in[24];
    const float* p2_w3    = (const float*)d_in[25];
    const float* p2_b3    = (const float*)d_in[26];
    const float* p2_w2    = (const float*)d_in[27];
    const float* p2_b2    = (const float*)d_in[28];
    float* out = (float*)d_out;

    float *xln, *cln, *qkx, *qkc, *q, *k, *v, *y;
    float *x1x, *x1c, *hx, *hc, *t1x, *t3x, *t1c, *t3c;
    cudaGetSymbolAddress((void**)&xln, g_xln);
    cudaGetSymbolAddress((void**)&cln, g_cln);
    cudaGetSymbolAddress((void**)&qkx, g_qkx);
    cudaGetSymbolAddress((void**)&qkc, g_qkc);
    cudaGetSymbolAddress((void**)&q,   g_q);
    cudaGetSymbolAddress((void**)&k,   g_k);
    cudaGetSymbolAddress((void**)&v,   g_v);
    cudaGetSymbolAddress((void**)&y,   g_y);
    cudaGetSymbolAddress((void**)&x1x, g_x1x);
    cudaGetSymbolAddress((void**)&x1c, g_x1c);
    cudaGetSymbolAddress((void**)&hx,  g_hx);
    cudaGetSymbolAddress((void**)&hc,  g_hc);
    cudaGetSymbolAddress((void**)&t1x, g_t1x);
    cudaGetSymbolAddress((void**)&t3x, g_t3x);
    cudaGetSymbolAddress((void**)&t1c, g_t1c);
    cudaGetSymbolAddress((void**)&t3c, g_t3c);

    cudaFuncSetAttribute(attn_tc, cudaFuncAttributeMaxDynamicSharedMemorySize, ATN_SMEM);
    cudaFuncSetAttribute(mma_gemm_mj, cudaFuncAttributeMaxDynamicSharedMemorySize, MMG_SMEM);

    // 1) LayerNorm both streams (one launch)
    ln2_kernel<<<L_X + S_C, 256>>>(x, xln, L_X, c, cln);

    // 2) QKV GEMMs for both streams; V written directly in attn layout
    {
        GJobs J; J.n = 4;
        int o = 0;
        J.j[0] = {cln, pc_qk_w, nullptr, nullptr, qkc, 2 * D, D, o, 0, 0};  o += nct(S_C, 2 * D);
        J.j[1] = {cln, pc_v_w,  pc_v_b,  nullptr, v,   D,     D, o, 1, 0};  o += nct(S_C, D);
        J.j[2] = {xln, px_qk_w, nullptr, nullptr, qkx, 2 * D, D, o, 0, 0};  o += nct(L_X, 2 * D);
        J.j[3] = {xln, px_v_w,  px_v_b,  nullptr, v,   D,     D, o, 1, S_C}; o += nct(L_X, D);
        mma_gemm_mj<<<o, 128, MMG_SMEM>>>(J);
    }
    qk_finish_all<<<dim3(TT, H), HD>>>(qkc, qkx, pc_qn, pc_kn, px_qn, px_kn, freqs, q, k);

    // 3) causal attention (tensor cores, cp.async pipelined)
    attn_tc<<<dim3(32, H), 128, ATN_SMEM>>>(q, k, v, y);

    // 4) output projections for both streams (batched)
    const float* yx = y + (size_t)S_C * D;
    {
        GJobs J; J.n = 2;
        int o = 0;
        J.j[0] = {yx, p1_proj_w, p1_proj_b, x, x1x, D, D, o, 0, 0}; o += nct(L_X, D);
        J.j[1] = {y,  p2_proj_w, p2_proj_b, c, x1c, D, D, o, 0, 0}; o += nct(S_C, D);
        J.j[2] = J.j[0]; J.j[3] = J.j[0];
        mma_gemm_mj<<<o, 128, MMG_SMEM>>>(J);
    }
    ln2_kernel<<<L_X + S_C, 256>>>(x1x, hx, L_X, x1c, hc);

    // 5) w1/w3 for both streams (batched)
    {
        GJobs J; J.n = 4;
        int o = 0;
        J.j[0] = {hx, p1_w1, p1_b1, nullptr, t1x, FF, D, o, 0, 0}; o += nct(L_X, FF);
        J.j[1] = {hx, p1_w3, p1_b3, nullptr, t3x, FF, D, o, 0, 0}; o += nct(L_X, FF);
        J.j[2] = {hc, p2_w1, p2_b1, nullptr, t1c, FF, D, o, 0, 0}; o += nct(S_C, FF);
        J.j[3] = {hc, p2_w3, p2_b3, nullptr, t3c, FF, D, o, 0, 0}; o += nct(S_C, FF);
        mma_gemm_mj<<<o, 128, MMG_SMEM>>>(J);
    }
    silu_all<<<(TT * FF + 255) / 256, 256>>>(t1x, t3x, t1x, L_X * FF, t1c, t3c, t1c, S_C * FF);

    // 6) w2 for both streams (batched)
    {
        GJobs J; J.n = 2;
        int o = 0;
        J.j[0] = {t1x, p1_w2, p1_b2, x1x, out,                   D, FF, o, 0, 0}; o += nct(L_X, D);
        J.j[1] = {t1c, p2_w2, p2_b2, x1c, out + (size_t)L_X * D, D, FF, o, 0, 0}; o += nct(S_C, D);
        J.j[2] = J.j[0]; J.j[3] = J.j[0];
        mma_gemm_mj<<<o, 128, MMG_SMEM>>>(J);
    }
}

// round 9
// speedup vs baseline: 7.5464x; 1.1449x over previous
#include <cuda_runtime.h>
#include <cuda_fp16.h>
#include <cstdint>
#include <math.h>

// ---------------- problem constants ----------------
#define L_X   1536
#define S_C   512
#define TT    2048          // L_X + S_C
#define D     1024
#define H     16
#define HD    64
#define FF    4096

// ---------------- scratch (device globals; no cudaMalloc allowed) ----------
__device__ float g_qkx[L_X * 2 * D];
__device__ float g_qkc[S_C * 2 * D];
__device__ float g_q  [H * TT * HD];
__device__ float g_k  [H * TT * HD];
__device__ float g_v  [H * TT * HD];
__device__ float g_x1x[L_X * D];
__device__ float g_x1c[S_C * D];
__device__ float g_t1x[L_X * FF];
__device__ float g_t3x[L_X * FF];
__device__ float g_t1c[S_C * FF];
__device__ float g_t3c[S_C * FF];

// fp16 operand buffers
__device__ __half g_w16  [33554432];          // converted weights arena (64MB)
__device__ __half g_cln16[S_C * D];
__device__ __half g_xln16[L_X * D];
__device__ __half g_y16  [TT * D];
__device__ __half g_h16x [L_X * D];
__device__ __half g_h16c [S_C * D];
__device__ __half g_g16x [L_X * FF];
__device__ __half g_g16c [S_C * FF];

// arena offsets (halves)
#define O_PCQK 0
#define O_PXQK 2097152
#define O_PCV  4194304
#define O_PXV  5242880
#define O_P1P  6291456
#define O_P2P  7340032
#define O_P1W1 8388608
#define O_P1W3 12582912
#define O_P2W1 16777216
#define O_P2W3 20971520
#define O_P1W2 25165824
#define O_P2W2 29360128

// ---------------- utils ----------------
__device__ __forceinline__ float warpSum(float v) {
    #pragma unroll
    for (int o = 16; o > 0; o >>= 1) v += __shfl_xor_sync(0xffffffffu, v, o);
    return v;
}
__device__ __forceinline__ uint32_t f2tf32(float v) {
    uint32_t r;
    asm("cvt.rna.tf32.f32 %0, %1;" : "=r"(r) : "f"(v));
    return r;
}
__device__ __forceinline__ float ex2f(float x) {
    float y;
    asm("ex2.approx.f32 %0, %1;" : "=f"(y) : "f"(x));
    return y;
}
__device__ __forceinline__ void mma_tf32(float* d, const uint32_t* a, const uint32_t* b) {
    asm volatile(
        "mma.sync.aligned.m16n8k8.row.col.f32.tf32.tf32.f32 "
        "{%0,%1,%2,%3}, {%4,%5,%6,%7}, {%8,%9}, {%0,%1,%2,%3};"
        : "+f"(d[0]), "+f"(d[1]), "+f"(d[2]), "+f"(d[3])
        : "r"(a[0]), "r"(a[1]), "r"(a[2]), "r"(a[3]), "r"(b[0]), "r"(b[1]));
}
__device__ __forceinline__ void mma_f16(float* d, const uint32_t* a, const uint32_t* b) {
    asm volatile(
        "mma.sync.aligned.m16n8k16.row.col.f32.f16.f16.f32 "
        "{%0,%1,%2,%3}, {%4,%5,%6,%7}, {%8,%9}, {%0,%1,%2,%3};"
        : "+f"(d[0]), "+f"(d[1]), "+f"(d[2]), "+f"(d[3])
        : "r"(a[0]), "r"(a[1]), "r"(a[2]), "r"(a[3]), "r"(b[0]), "r"(b[1]));
}
__device__ __forceinline__ uint32_t smem_u32(const void* p) {
    uint32_t a;
    asm("{ .reg .u64 t; cvta.to.shared.u64 t, %1; cvt.u32.u64 %0, t; }" : "=r"(a) : "l"(p));
    return a;
}
__device__ __forceinline__ void cp_async16(uint32_t saddr, const void* gaddr) {
    asm volatile("cp.async.cg.shared.global [%0], [%1], 16;" :: "r"(saddr), "l"(gaddr));
}
#define CP_COMMIT() asm volatile("cp.async.commit_group;" ::: "memory")
#define CP_WAIT0()  asm volatile("cp.async.wait_group 0;" ::: "memory")
#define CP_WAIT1()  asm volatile("cp.async.wait_group 1;" ::: "memory")

// ---------------- weight fp32 -> fp16 conversion ----------------
struct WJob { const float* src; __half* dst; int off; };
struct WJobs { WJob j[12]; };

__global__ __launch_bounds__(256) void cvt16(WJobs J) {
    int ji = 0;
    #pragma unroll
    for (int t = 1; t < 12; t++) if ((int)blockIdx.x >= J.j[t].off) ji = t;
    size_t idx = ((size_t)(blockIdx.x - J.j[ji].off) * 256 + threadIdx.x) * 8;
    const float4* s = (const float4*)(J.j[ji].src + idx);
    float4 v0 = s[0], v1 = s[1];
    __half2* d = (__half2*)(J.j[ji].dst + idx);
    d[0] = __floats2half2_rn(v0.x, v0.y);
    d[1] = __floats2half2_rn(v0.z, v0.w);
    d[2] = __floats2half2_rn(v1.x, v1.y);
    d[3] = __floats2half2_rn(v1.z, v1.w);
}

// ---------------- LayerNorm pair -> fp16 outputs ----------------
__global__ void ln2_kernel(const float* __restrict__ in0, __half* __restrict__ out0,
                           int rows0,
                           const float* __restrict__ in1, __half* __restrict__ out1) {
    int row = blockIdx.x;
    const float* x;
    __half* o;
    if (row < rows0) { x = in0 + (size_t)row * D; o = out0 + (size_t)row * D; }
    else             { x = in1 + (size_t)(row - rows0) * D; o = out1 + (size_t)(row - rows0) * D; }
    float s = 0.f, ss = 0.f;
    for (int i = threadIdx.x; i < D; i += 256) {
        float v = x[i]; s += v; ss += v * v;
    }
    __shared__ float shs[8], shss[8];
    float ws = warpSum(s), wss = warpSum(ss);
    int w = threadIdx.x >> 5;
    if ((threadIdx.x & 31) == 0) { shs[w] = ws; shss[w] = wss; }
    __syncthreads();
    float ts = 0.f, tss = 0.f;
    #pragma unroll
    for (int i = 0; i < 8; i++) { ts += shs[i]; tss += shss[i]; }
    float mean = ts * (1.0f / D);
    float var  = tss * (1.0f / D) - mean * mean;
    float inv  = rsqrtf(var + 1e-6f);
    for (int i = threadIdx.x; i < D; i += 256)
        o[i] = __float2half_rn((x[i] - mean) * inv);
}

// ======================================================================
// Multi-job fp16 GEMM (m16n8k16), 3-stage cp.async, padded smem rows.
// C[M,N] = A[M,K] @ B[N,K]^T (+bias fp32) (+resid fp32) -> fp32 C.
// Tile 128x128x32; 128 threads = 4 warps (2x2), warp tile 64x64.
// smem rows: 64B data + 16B pad = 20 words -> conflict-free fragments.
// ======================================================================
struct GJob {
    const __half* A; const __half* B; const float* bias; const float* resid;
    float* C; int N, K, off, mode, t_off;
};
struct GJobs { GJob j[4]; int n; };

#define HST 20                          // words per smem row
#define HBUF (128 * HST)                // words per operand per stage
#define MMG_SMEM (3 * 2 * HBUF * 4)     // 61440 bytes

__global__ __launch_bounds__(128)
void mma_gemm_mj(GJobs jobs) {
    int ji = 0;
    if (jobs.n > 1 && (int)blockIdx.x >= jobs.j[1].off) ji = 1;
    if (jobs.n > 2 && (int)blockIdx.x >= jobs.j[2].off) ji = 2;
    if (jobs.n > 3 && (int)blockIdx.x >= jobs.j[3].off) ji = 3;
    const __half* A = jobs.j[ji].A;
    const __half* B = jobs.j[ji].B;
    const float* bias = jobs.j[ji].bias;
    const float* resid = jobs.j[ji].resid;
    float* C = jobs.j[ji].C;
    int N = jobs.j[ji].N, K = jobs.j[ji].K;
    int mode = jobs.j[ji].mode, t_off = jobs.j[ji].t_off;
    int lid0 = blockIdx.x - jobs.j[ji].off;
    int nbx = N >> 7;
    int by = lid0 / nbx, bx = lid0 - by * nbx;
    int m0 = by * 128, n0 = bx * 128;

    extern __shared__ uint32_t smw[];
    uint32_t sbase = smem_u32(smw);
    int tid = threadIdx.x;
    int wid = tid >> 5, lane = tid & 31;
    int gid = lane >> 2, tig = lane & 3;
    int warp_m = wid >> 1, warp_n = wid & 1;

    float acc[4][8][4];
    #pragma unroll
    for (int mt = 0; mt < 4; mt++)
        #pragma unroll
        for (int nt = 0; nt < 8; nt++)
            #pragma unroll
            for (int e = 0; e < 4; e++) acc[mt][nt][e] = 0.f;

    const int nchunk = K >> 5;          // 32 halves per chunk
    int lrow = tid >> 2;                // 0..31
    int lblk = tid & 3;                 // 16B block in row

    #pragma unroll
    for (int pc = 0; pc < 2; pc++) {
        const __half* Ap = A + (size_t)m0 * K + pc * 32 + lblk * 8;
        const __half* Bp = B + (size_t)n0 * K + pc * 32 + lblk * 8;
        uint32_t sA = sbase + pc * 2 * HBUF * 4;
        uint32_t sB = sA + HBUF * 4;
        #pragma unroll
        for (int l = 0; l < 4; l++) {
            int r = lrow + l * 32;
            uint32_t so = (r * HST + lblk * 4) * 4;
            cp_async16(sA + so, Ap + (size_t)r * K);
            cp_async16(sB + so, Bp + (size_t)r * K);
        }
        CP_COMMIT();
    }

    int st = 0;
    for (int i = 0; i < nchunk; i++) {
        CP_WAIT1();
        __syncthreads();
        if (i + 2 < nchunk) {
            int ps = st + 2; if (ps >= 3) ps -= 3;
            const __half* Ap = A + (size_t)m0 * K + (i + 2) * 32 + lblk * 8;
            const __half* Bp = B + (size_t)n0 * K + (i + 2) * 32 + lblk * 8;
            uint32_t sA = sbase + ps * 2 * HBUF * 4;
            uint32_t sB = sA + HBUF * 4;
            #pragma unroll
            for (int l = 0; l < 4; l++) {
                int r = lrow + l * 32;
                uint32_t so = (r * HST + lblk * 4) * 4;
                cp_async16(sA + so, Ap + (size_t)r * K);
                cp_async16(sB + so, Bp + (size_t)r * K);
            }
        }
        CP_COMMIT();
        const uint32_t* As = smw + st * 2 * HBUF;
        const uint32_t* Bs = As + HBUF;
        #pragma unroll
        for (int s = 0; s < 2; s++) {           // two k16 steps per chunk
            int wb = s * 8;
            uint32_t af[4][4], bf[8][2];
            #pragma unroll
            for (int mt = 0; mt < 4; mt++) {
                int r0 = warp_m * 64 + mt * 16 + gid;
                af[mt][0] = As[r0 * HST + wb + tig];
                af[mt][1] = As[(r0 + 8) * HST + wb + tig];
                af[mt][2] = As[r0 * HST + wb + tig + 4];
                af[mt][3] = As[(r0 + 8) * HST + wb + tig + 4];
            }
            #pragma unroll
            for (int nt = 0; nt < 8; nt++) {
                int col = warp_n * 64 + nt * 8 + gid;
                bf[nt][0] = Bs[col * HST + wb + tig];
                bf[nt][1] = Bs[col * HST + wb + tig + 4];
            }
            #pragma unroll
            for (int mt = 0; mt < 4; mt++)
                #pragma unroll
                for (int nt = 0; nt < 8; nt++)
                    mma_f16(acc[mt][nt], af[mt], bf[nt]);
        }
        st++; if (st >= 3) st = 0;
    }

    #pragma unroll
    for (int mt = 0; mt < 4; mt++) {
        #pragma unroll
        for (int nt = 0; nt < 8; nt++) {
            int row = m0 + warp_m * 64 + mt * 16 + gid;
            int col = n0 + warp_n * 64 + nt * 8 + tig * 2;
            #pragma unroll
            for (int half = 0; half < 2; half++) {
                int r = row + half * 8;
                float2 v = make_float2(acc[mt][nt][half * 2], acc[mt][nt][half * 2 + 1]);
                if (bias) {
                    float2 bv2 = *(const float2*)(bias + col);
                    v.x += bv2.x; v.y += bv2.y;
                }
                if (mode == 0) {
                    size_t off = (size_t)r * N + col;
                    if (resid) {
                        float2 rv = *(const float2*)(resid + off);
                        v.x += rv.x; v.y += rv.y;
                    }
                    *(float2*)(C + off) = v;
                } else {
                    int hh = col >> 6, dd = col & 63;
                    *(float2*)(C + ((size_t)hh * TT + t_off + r) * HD + dd) = v;
                }
            }
        }
    }
}

// ---------------- qk finish (both streams, one launch) ----------------
__global__ void qk_finish_all(const float* __restrict__ qkc, const float* __restrict__ qkx,
                              const float* __restrict__ cqn, const float* __restrict__ ckn,
                              const float* __restrict__ xqn, const float* __restrict__ xkn,
                              const float* __restrict__ freqs,
                              float* __restrict__ Q, float* __restrict__ Ko) {
    int t = blockIdx.x, h = blockIdx.y, d = threadIdx.x;
    const float* qk; const float* qn; const float* kn; int row;
    if (t < S_C) { qk = qkc; qn = cqn; kn = ckn; row = t; }
    else         { qk = qkx; qn = xqn; kn = xkn; row = t - S_C; }
    float qv = qk[(size_t)row * (2 * D) + h * HD + d];
    float kv = qk[(size_t)row * (2 * D) + D + h * HD + d];
    __shared__ float sh[4];
    float sq = qv * qv, sk = kv * kv;
    #pragma unroll
    for (int o = 16; o > 0; o >>= 1) { sq += __shfl_xor_sync(0xffffffffu, sq, o); sk += __shfl_xor_sync(0xffffffffu, sk, o); }
    int w = d >> 5;
    if ((d & 31) == 0) { sh[w] = sq; sh[2 + w] = sk; }
    __syncthreads();
    float rq = rsqrtf((sh[0] + sh[1]) * (1.0f / HD) + 1e-6f);
    float rk = rsqrtf((sh[2] + sh[3]) * (1.0f / HD) + 1e-6f);
    __shared__ float sQ[HD], sK[HD];
    sQ[d] = qv * rq * qn[d];
    sK[d] = kv * rk * kn[d];
    __syncthreads();
    int i = d >> 1;
    float cs = freqs[((size_t)t * 32 + i) * 2 + 0];
    float sn = freqs[((size_t)t * 32 + i) * 2 + 1];
    float oq, ok;
    if ((d & 1) == 0) { oq = sQ[d] * cs - sQ[d + 1] * sn; ok = sK[d] * cs - sK[d + 1] * sn; }
    else              { oq = sQ[d - 1] * sn + sQ[d] * cs; ok = sK[d - 1] * sn + sK[d] * cs; }
    size_t off = ((size_t)h * TT + t) * HD + d;
    Q[off] = oq; Ko[off] = ok;
}

// ======================================================================
// Tensor-core flash attention (tf32), 64-row q-tiles, cp.async K/V.
// Output written fp16 (consumed by proj GEMM).
// ======================================================================
#define AST 72
#define ATN_SMEM (5 * 64 * AST * 4)

__global__ __launch_bounds__(128)
void attn_tc(const float* __restrict__ Q, const float* __restrict__ K,
             const float* __restrict__ V, __half* __restrict__ Y) {
    extern __shared__ float sm[];
    float* Pw = sm;
    uint32_t sbase = smem_u32(sm);
    int tid = threadIdx.x, wid = tid >> 5, lane = tid & 31;
    int gid = lane >> 2, tig = lane & 3;
    int bxr = 31 - blockIdx.x;
    int h = blockIdx.y;
    int q0 = bxr * 64;
    const float* Qh = Q + (size_t)h * TT * HD;
    const float* Kh = K + (size_t)h * TT * HD;
    const float* Vh = V + (size_t)h * TT * HD;
    const float QSC = 0.125f * 1.4426950408889634f;

    int lrow = tid >> 4;
    int lc4 = (tid & 15) << 2;

    {
        uint32_t kb = sbase + (64 * AST) * 4;
        uint32_t vb = sbase + (3 * 64 * AST) * 4;
        #pragma unroll
        for (int l = 0; l < 8; l++) {
            int r = lrow + l * 8;
            uint32_t so = (r * AST + lc4) * 4;
            cp_async16(kb + so, Kh + (size_t)r * HD + lc4);
            cp_async16(vb + so, Vh + (size_t)r * HD + lc4);
        }
        CP_COMMIT();
    }

    #pragma unroll
    for (int l = 0; l < 8; l++) {
        int e = tid + l * 128;
        int r = e >> 4, c4 = (e & 15) << 2;
        float4 v = *(const float4*)(Qh + (size_t)(q0 + r) * HD + c4);
        uint32_t* p = (uint32_t*)(Pw + r * AST + c4);
        p[0] = f2tf32(v.x * QSC); p[1] = f2tf32(v.y * QSC);
        p[2] = f2tf32(v.z * QSC); p[3] = f2tf32(v.w * QSC);
    }
    __syncthreads();
    uint32_t qf[8][4];
    int qrow = wid * 16 + gid;
    #pragma unroll
    for (int ks = 0; ks < 8; ks++) {
        int k0 = ks * 8;
        const uint32_t* p0 = (const uint32_t*)(Pw + qrow * AST + k0);
        const uint32_t* p1 = (const uint32_t*)(Pw + (qrow + 8) * AST + k0);
        qf[ks][0] = p0[tig];
        qf[ks][1] = p1[tig];
        qf[ks][2] = p0[tig + 4];
        qf[ks][3] = p1[tig + 4];
    }
    __syncwarp();

    float ofr[8][4];
    #pragma unroll
    for (int ot = 0; ot < 8; ot++)
        #pragma unroll
        for (int e = 0; e < 4; e++) ofr[ot][e] = 0.f;
    float m0r = -INFINITY, m1r = -INFINITY, l0r = 0.f, l1r = 0.f;

    int ntile = bxr + 1;
    for (int kt = 0; kt < ntile; kt++) {
        int k0g = kt * 64;
        int buf = kt & 1;
        const float* Ksb = sm + (1 + buf) * 64 * AST;
        const float* Vsb = sm + (3 + buf) * 64 * AST;
        CP_WAIT0();
        __syncthreads();
        float sacc[8][4];
        #pragma unroll
        for (int nt = 0; nt < 8; nt++)
            #pragma unroll
            for (int e = 0; e < 4; e++) sacc[nt][e] = 0.f;
        #pragma unroll
        for (int ks = 0; ks < 8; ks++) {
            int k0 = ks * 8;
            #pragma unroll
            for (int nt = 0; nt < 8; nt++) {
                uint32_t bf[2];
                const uint32_t* p = (const uint32_t*)(Ksb + (nt * 8 + gid) * AST + k0);
                bf[0] = p[tig];
                bf[1] = p[tig + 4];
                mma_tf32(sacc[nt], qf[ks], bf);
            }
        }
        if (kt + 1 < ntile) {
            const float* Kp = Kh + (size_t)(k0g + 64) * HD;
            const float* Vp = Vh + (size_t)(k0g + 64) * HD;
            uint32_t kb = sbase + ((1 + (buf ^ 1)) * 64 * AST) * 4;
            uint32_t vb = sbase + ((3 + (buf ^ 1)) * 64 * AST) * 4;
            #pragma unroll
            for (int l = 0; l < 8; l++) {
                int r = lrow + l * 8;
                uint32_t so = (r * AST + lc4) * 4;
                cp_async16(kb + so, Kp + (size_t)r * HD + lc4);
                cp_async16(vb + so, Vp + (size_t)r * HD + lc4);
            }
        }
        CP_COMMIT();
        if (kt == ntile - 1) {
            int r0 = q0 + wid * 16 + gid;
            #pragma unroll
            for (int nt = 0; nt < 8; nt++) {
                int c0 = k0g + nt * 8 + tig * 2;
                if (c0 > r0)     sacc[nt][0] = -INFINITY;
                if (c0 + 1 > r0) sacc[nt][1] = -INFINITY;
                if (c0 > r0 + 8)     sacc[nt][2] = -INFINITY;
                if (c0 + 1 > r0 + 8) sacc[nt][3] = -INFINITY;
            }
        }
        float tm0 = -INFINITY, tm1 = -INFINITY;
        #pragma unroll
        for (int nt = 0; nt < 8; nt++) {
            tm0 = fmaxf(tm0, fmaxf(sacc[nt][0], sacc[nt][1]));
            tm1 = fmaxf(tm1, fmaxf(sacc[nt][2], sacc[nt][3]));
        }
        #pragma unroll
        for (int o = 1; o < 4; o <<= 1) {
            tm0 = fmaxf(tm0, __shfl_xor_sync(0xffffffffu, tm0, o));
            tm1 = fmaxf(tm1, __shfl_xor_sync(0xffffffffu, tm1, o));
        }
        float nm0 = fmaxf(m0r, tm0), nm1 = fmaxf(m1r, tm1);
        float c0 = ex2f(m0r - nm0), c1 = ex2f(m1r - nm1);
        m0r = nm0; m1r = nm1;
        float ps0 = 0.f, ps1 = 0.f;
        #pragma unroll
        for (int nt = 0; nt < 8; nt++) {
            float p00 = ex2f(sacc[nt][0] - nm0);
            float p01 = ex2f(sacc[nt][1] - nm0);
            float p10 = ex2f(sacc[nt][2] - nm1);
            float p11 = ex2f(sacc[nt][3] - nm1);
            ps0 += p00 + p01; ps1 += p10 + p11;
            uint32_t* pr0 = (uint32_t*)(Pw + (wid * 16 + gid) * AST + nt * 8 + tig * 2);
            uint32_t* pr1 = (uint32_t*)(Pw + (wid * 16 + gid + 8) * AST + nt * 8 + tig * 2);
            pr0[0] = f2tf32(p00); pr0[1] = f2tf32(p01);
            pr1[0] = f2tf32(p10); pr1[1] = f2tf32(p11);
        }
        #pragma unroll
        for (int o = 1; o < 4; o <<= 1) {
            ps0 += __shfl_xor_sync(0xffffffffu, ps0, o);
            ps1 += __shfl_xor_sync(0xffffffffu, ps1, o);
        }
        l0r = l0r * c0 + ps0;
        l1r = l1r * c1 + ps1;
        #pragma unroll
        for (int ot = 0; ot < 8; ot++) {
            ofr[ot][0] *= c0; ofr[ot][1] *= c0;
            ofr[ot][2] *= c1; ofr[ot][3] *= c1;
        }
        __syncwarp();
        #pragma unroll
        for (int ks = 0; ks < 8; ks++) {
            int k0 = ks * 8;
            uint32_t af[4];
            const uint32_t* p0 = (const uint32_t*)(Pw + (wid * 16 + gid) * AST + k0);
            const uint32_t* p1 = (const uint32_t*)(Pw + (wid * 16 + gid + 8) * AST + k0);
            af[0] = p0[tig];
            af[1] = p1[tig];
            af[2] = p0[tig + 4];
            af[3] = p1[tig + 4];
            #pragma unroll
            for (int ot = 0; ot < 8; ot++) {
                uint32_t bf[2];
                bf[0] = *(const uint32_t*)(Vsb + (k0 + tig) * AST + ot * 8 + gid);
                bf[1] = *(const uint32_t*)(Vsb + (k0 + tig + 4) * AST + ot * 8 + gid);
                mma_tf32(ofr[ot], af, bf);
            }
        }
        __syncthreads();
    }
    float i0 = 1.0f / l0r, i1 = 1.0f / l1r;
    int t0 = q0 + wid * 16 + gid, t1 = t0 + 8;
    #pragma unroll
    for (int ot = 0; ot < 8; ot++) {
        int col = h * HD + ot * 8 + tig * 2;
        *(__half2*)(Y + (size_t)t0 * D + col) = __floats2half2_rn(ofr[ot][0] * i0, ofr[ot][1] * i0);
        *(__half2*)(Y + (size_t)t1 * D + col) = __floats2half2_rn(ofr[ot][2] * i1, ofr[ot][3] * i1);
    }
}

// ---------------- SiLU gate -> fp16 ----------------
__global__ void silu_all(const float* __restrict__ a0, const float* __restrict__ b0,
                         __half* __restrict__ g0, int n0,
                         const float* __restrict__ a1, const float* __restrict__ b1,
                         __half* __restrict__ g1, int n1) {
    int i = blockIdx.x * 256 + threadIdx.x;
    if (i < n0) {
        float x = a0[i];
        g0[i] = __float2half_rn((x / (1.0f + expf(-x))) * b0[i]);
    } else if (i < n0 + n1) {
        int j = i - n0;
        float x = a1[j];
        g1[j] = __float2half_rn((x / (1.0f + expf(-x))) * b1[j]);
    }
}

// ---------------- host launcher ----------------
static inline int nct(int M, int N) { return (M / 128) * (N / 128); }

extern "C" void kernel_launch(void* const* d_in, const int* in_sizes, int n_in,
                              void* d_out, int out_size) {
    const float* x        = (const float*)d_in[0];
    const float* c        = (const float*)d_in[1];
    const float* freqs    = (const float*)d_in[2];
    const float* px_qk_w  = (const float*)d_in[3];
    const float* px_qn    = (const float*)d_in[4];
    const float* px_kn    = (const float*)d_in[5];
    const float* px_v_w   = (const float*)d_in[6];
    const float* px_v_b   = (const float*)d_in[7];
    const float* pc_qk_w  = (const float*)d_in[8];
    const float* pc_qn    = (const float*)d_in[9];
    const float* pc_kn    = (const float*)d_in[10];
    const float* pc_v_w   = (const float*)d_in[11];
    const float* pc_v_b   = (const float*)d_in[12];
    const float* p1_proj_w = (const float*)d_in[13];
    const float* p1_proj_b = (const float*)d_in[14];
    const float* p1_w1    = (const float*)d_in[15];
    const float* p1_b1    = (const float*)d_in[16];
    const float* p1_w3    = (const float*)d_in[17];
    const float* p1_b3    = (const float*)d_in[18];
    const float* p1_w2    = (const float*)d_in[19];
    const float* p1_b2    = (const float*)d_in[20];
    const float* p2_proj_w = (const float*)d_in[21];
    const float* p2_proj_b = (const float*)d_in[22];
    const float* p2_w1    = (const float*)d_in[23];
    const float* p2_b1    = (const float*)d_in[24];
    const float* p2_w3    = (const float*)d_in[25];
    const float* p2_b3    = (const float*)d_in[26];
    const float* p2_w2    = (const float*)d_in[27];
    const float* p2_b2    = (const float*)d_in[28];
    float* out = (float*)d_out;

    float *qkx, *qkc, *q, *k, *v, *x1x, *x1c, *t1x, *t3x, *t1c, *t3c;
    __half *w16, *cln16, *xln16, *y16, *h16x, *h16c, *g16x, *g16c;
    cudaGetSymbolAddress((void**)&qkx, g_qkx);
    cudaGetSymbolAddress((void**)&qkc, g_qkc);
    cudaGetSymbolAddress((void**)&q,   g_q);
    cudaGetSymbolAddress((void**)&k,   g_k);
    cudaGetSymbolAddress((void**)&v,   g_v);
    cudaGetSymbolAddress((void**)&x1x, g_x1x);
    cudaGetSymbolAddress((void**)&x1c, g_x1c);
    cudaGetSymbolAddress((void**)&t1x, g_t1x);
    cudaGetSymbolAddress((void**)&t3x, g_t3x);
    cudaGetSymbolAddress((void**)&t1c, g_t1c);
    cudaGetSymbolAddress((void**)&t3c, g_t3c);
    cudaGetSymbolAddress((void**)&w16,   g_w16);
    cudaGetSymbolAddress((void**)&cln16, g_cln16);
    cudaGetSymbolAddress((void**)&xln16, g_xln16);
    cudaGetSymbolAddress((void**)&y16,   g_y16);
    cudaGetSymbolAddress((void**)&h16x,  g_h16x);
    cudaGetSymbolAddress((void**)&h16c,  g_h16c);
    cudaGetSymbolAddress((void**)&g16x,  g_g16x);
    cudaGetSymbolAddress((void**)&g16c,  g_g16c);

    cudaFuncSetAttribute(attn_tc, cudaFuncAttributeMaxDynamicSharedMemorySize, ATN_SMEM);
    cudaFuncSetAttribute(mma_gemm_mj, cudaFuncAttributeMaxDynamicSharedMemorySize, MMG_SMEM);

    // 0) convert weights to fp16 arena
    {
        WJobs W;
        int o = 0;
        W.j[0]  = {pc_qk_w,  w16 + O_PCQK, o}; o += 1024;
        W.j[1]  = {px_qk_w,  w16 + O_PXQK, o}; o += 1024;
        W.j[2]  = {pc_v_w,   w16 + O_PCV,  o}; o += 512;
        W.j[3]  = {px_v_w,   w16 + O_PXV,  o}; o += 512;
        W.j[4]  = {p1_proj_w, w16 + O_P1P, o}; o += 512;
        W.j[5]  = {p2_proj_w, w16 + O_P2P, o}; o += 512;
        W.j[6]  = {p1_w1,    w16 + O_P1W1, o}; o += 2048;
        W.j[7]  = {p1_w3,    w16 + O_P1W3, o}; o += 2048;
        W.j[8]  = {p2_w1,    w16 + O_P2W1, o}; o += 2048;
        W.j[9]  = {p2_w3,    w16 + O_P2W3, o}; o += 2048;
        W.j[10] = {p1_w2,    w16 + O_P1W2, o}; o += 2048;
        W.j[11] = {p2_w2,    w16 + O_P2W2, o}; o += 2048;
        cvt16<<<o, 256>>>(W);
    }

    // 1) LayerNorm both streams -> fp16
    ln2_kernel<<<L_X + S_C, 256>>>(x, xln16, L_X, c, cln16);

    // 2) QKV GEMMs; V written directly in attn layout
    {
        GJobs J; J.n = 4;
        int o = 0;
        J.j[0] = {cln16, w16 + O_PCQK, nullptr, nullptr, qkc, 2 * D, D, o, 0, 0};  o += nct(S_C, 2 * D);
        J.j[1] = {cln16, w16 + O_PCV,  pc_v_b,  nullptr, v,   D,     D, o, 1, 0};  o += nct(S_C, D);
        J.j[2] = {xln16, w16 + O_PXQK, nullptr, nullptr, qkx, 2 * D, D, o, 0, 0};  o += nct(L_X, 2 * D);
        J.j[3] = {xln16, w16 + O_PXV,  px_v_b,  nullptr, v,   D,     D, o, 1, S_C}; o += nct(L_X, D);
        mma_gemm_mj<<<o, 128, MMG_SMEM>>>(J);
    }
    qk_finish_all<<<dim3(TT, H), HD>>>(qkc, qkx, pc_qn, pc_kn, px_qn, px_kn, freqs, q, k);

    // 3) causal attention -> y fp16
    attn_tc<<<dim3(32, H), 128, ATN_SMEM>>>(q, k, v, y16);

    // 4) output projections (batched)
    const __half* yx16 = y16 + (size_t)S_C * D;
    {
        GJobs J; J.n = 2;
        int o = 0;
        J.j[0] = {yx16, w16 + O_P1P, p1_proj_b, x, x1x, D, D, o, 0, 0}; o += nct(L_X, D);
        J.j[1] = {y16,  w16 + O_P2P, p2_proj_b, c, x1c, D, D, o, 0, 0}; o += nct(S_C, D);
        J.j[2] = J.j[0]; J.j[3] = J.j[0];
        mma_gemm_mj<<<o, 128, MMG_SMEM>>>(J);
    }
    ln2_kernel<<<L_X + S_C, 256>>>(x1x, h16x, L_X, x1c, h16c);

    // 5) w1/w3 (batched)
    {
        GJobs J; J.n = 4;
        int o = 0;
        J.j[0] = {h16x, w16 + O_P1W1, p1_b1, nullptr, t1x, FF, D, o, 0, 0}; o += nct(L_X, FF);
        J.j[1] = {h16x, w16 + O_P1W3, p1_b3, nullptr, t3x, FF, D, o, 0, 0}; o += nct(L_X, FF);
        J.j[2] = {h16c, w16 + O_P2W1, p2_b1, nullptr, t1c, FF, D, o, 0, 0}; o += nct(S_C, FF);
        J.j[3] = {h16c, w16 + O_P2W3, p2_b3, nullptr, t3c, FF, D, o, 0, 0}; o += nct(S_C, FF);
        mma_gemm_mj<<<o, 128, MMG_SMEM>>>(J);
    }
    silu_all<<<(TT * FF + 255) / 256, 256>>>(t1x, t3x, g16x, L_X * FF, t1c, t3c, g16c, S_C * FF);

    // 6) w2 (batched)
    {
        GJobs J; J.n = 2;
        int o = 0;
        J.j[0] = {g16x, w16 + O_P1W2, p1_b2, x1x, out,                   D, FF, o, 0, 0}; o += nct(L_X, D);
        J.j[1] = {g16c, w16 + O_P2W2, p2_b2, x1c, out + (size_t)L_X * D, D, FF, o, 0, 0}; o += nct(S_C, D);
        J.j[2] = J.j[0]; J.j[3] = J.j[0];
        mma_gemm_mj<<<o, 128, MMG_SMEM>>>(J);
    }
}

// round 10
// speedup vs baseline: 8.0466x; 1.0663x over previous
#include <cuda_runtime.h>
#include <cuda_fp16.h>
#include <cstdint>
#include <math.h>

// ---------------- problem constants ----------------
#define L_X   1536
#define S_C   512
#define TT    2048          // L_X + S_C
#define D     1024
#define H     16
#define HD    64
#define FF    4096

// ---------------- scratch (device globals; no cudaMalloc allowed) ----------
__device__ float g_qkx[L_X * 2 * D];
__device__ float g_qkc[S_C * 2 * D];
__device__ float g_x1x[L_X * D];
__device__ float g_x1c[S_C * D];

// fp16 buffers
__device__ __half g_w16  [33554432];          // converted weights arena (64MB)
__device__ __half g_cln16[S_C * D];
__device__ __half g_xln16[L_X * D];
__device__ __half g_q16  [H * TT * HD];       // scaled Q, natural layout
__device__ __half g_k16  [H * TT * HD];       // K, natural layout
__device__ __half g_v16t [H * HD * TT];       // V, dim-major (transposed)
__device__ __half g_y16  [TT * D];
__device__ __half g_h16x [L_X * D];
__device__ __half g_h16c [S_C * D];
__device__ __half g_t16x1[L_X * FF];
__device__ __half g_t16x3[L_X * FF];
__device__ __half g_t16c1[S_C * FF];
__device__ __half g_t16c3[S_C * FF];
__device__ __half g_g16x [L_X * FF];
__device__ __half g_g16c [S_C * FF];

// arena offsets (halves)
#define O_PCQK 0
#define O_PXQK 2097152
#define O_PCV  4194304
#define O_PXV  5242880
#define O_P1P  6291456
#define O_P2P  7340032
#define O_P1W1 8388608
#define O_P1W3 12582912
#define O_P2W1 16777216
#define O_P2W3 20971520
#define O_P1W2 25165824
#define O_P2W2 29360128

// ---------------- utils ----------------
__device__ __forceinline__ float warpSum(float v) {
    #pragma unroll
    for (int o = 16; o > 0; o >>= 1) v += __shfl_xor_sync(0xffffffffu, v, o);
    return v;
}
__device__ __forceinline__ float ex2f(float x) {
    float y;
    asm("ex2.approx.f32 %0, %1;" : "=f"(y) : "f"(x));
    return y;
}
__device__ __forceinline__ void mma_f16(float* d, const uint32_t* a, const uint32_t* b) {
    asm volatile(
        "mma.sync.aligned.m16n8k16.row.col.f32.f16.f16.f32 "
        "{%0,%1,%2,%3}, {%4,%5,%6,%7}, {%8,%9}, {%0,%1,%2,%3};"
        : "+f"(d[0]), "+f"(d[1]), "+f"(d[2]), "+f"(d[3])
        : "r"(a[0]), "r"(a[1]), "r"(a[2]), "r"(a[3]), "r"(b[0]), "r"(b[1]));
}
__device__ __forceinline__ uint32_t smem_u32(const void* p) {
    uint32_t a;
    asm("{ .reg .u64 t; cvta.to.shared.u64 t, %1; cvt.u32.u64 %0, t; }" : "=r"(a) : "l"(p));
    return a;
}
__device__ __forceinline__ void cp_async16(uint32_t saddr, const void* gaddr) {
    asm volatile("cp.async.cg.shared.global [%0], [%1], 16;" :: "r"(saddr), "l"(gaddr));
}
#define CP_COMMIT() asm volatile("cp.async.commit_group;" ::: "memory")
#define CP_WAIT0()  asm volatile("cp.async.wait_group 0;" ::: "memory")
#define CP_WAIT1()  asm volatile("cp.async.wait_group 1;" ::: "memory")

// ---------------- weight fp32 -> fp16 conversion ----------------
struct WJob { const float* src; __half* dst; int off; };
struct WJobs { WJob j[12]; };

__global__ __launch_bounds__(256) void cvt16(WJobs J) {
    int ji = 0;
    #pragma unroll
    for (int t = 1; t < 12; t++) if ((int)blockIdx.x >= J.j[t].off) ji = t;
    size_t idx = ((size_t)(blockIdx.x - J.j[ji].off) * 256 + threadIdx.x) * 8;
    const float4* s = (const float4*)(J.j[ji].src + idx);
    float4 v0 = s[0], v1 = s[1];
    __half2* d = (__half2*)(J.j[ji].dst + idx);
    d[0] = __floats2half2_rn(v0.x, v0.y);
    d[1] = __floats2half2_rn(v0.z, v0.w);
    d[2] = __floats2half2_rn(v1.x, v1.y);
    d[3] = __floats2half2_rn(v1.z, v1.w);
}

// ---------------- LayerNorm pair -> fp16 outputs ----------------
__global__ void ln2_kernel(const float* __restrict__ in0, __half* __restrict__ out0,
                           int rows0,
                           const float* __restrict__ in1, __half* __restrict__ out1) {
    int row = blockIdx.x;
    const float* x;
    __half* o;
    if (row < rows0) { x = in0 + (size_t)row * D; o = out0 + (size_t)row * D; }
    else             { x = in1 + (size_t)(row - rows0) * D; o = out1 + (size_t)(row - rows0) * D; }
    float s = 0.f, ss = 0.f;
    for (int i = threadIdx.x; i < D; i += 256) {
        float v = x[i]; s += v; ss += v * v;
    }
    __shared__ float shs[8], shss[8];
    float ws = warpSum(s), wss = warpSum(ss);
    int w = threadIdx.x >> 5;
    if ((threadIdx.x & 31) == 0) { shs[w] = ws; shss[w] = wss; }
    __syncthreads();
    float ts = 0.f, tss = 0.f;
    #pragma unroll
    for (int i = 0; i < 8; i++) { ts += shs[i]; tss += shss[i]; }
    float mean = ts * (1.0f / D);
    float var  = tss * (1.0f / D) - mean * mean;
    float inv  = rsqrtf(var + 1e-6f);
    for (int i = threadIdx.x; i < D; i += 256)
        o[i] = __float2half_rn((x[i] - mean) * inv);
}

// ======================================================================
// Multi-job fp16 GEMM (m16n8k16), 3-stage cp.async, padded smem rows.
// mode 0: fp32 row-major C (+resid). mode 1: fp16 V dim-major [H][HD][TT].
// mode 2: fp16 row-major C.
// ======================================================================
struct GJob {
    const __half* A; const __half* B; const float* bias; const float* resid;
    void* C; int N, K, off, mode, t_off;
};
struct GJobs { GJob j[4]; int n; };

#define HST 20
#define HBUF (128 * HST)
#define MMG_SMEM (3 * 2 * HBUF * 4)

__global__ __launch_bounds__(128)
void mma_gemm_mj(GJobs jobs) {
    int ji = 0;
    if (jobs.n > 1 && (int)blockIdx.x >= jobs.j[1].off) ji = 1;
    if (jobs.n > 2 && (int)blockIdx.x >= jobs.j[2].off) ji = 2;
    if (jobs.n > 3 && (int)blockIdx.x >= jobs.j[3].off) ji = 3;
    const __half* A = jobs.j[ji].A;
    const __half* B = jobs.j[ji].B;
    const float* bias = jobs.j[ji].bias;
    const float* resid = jobs.j[ji].resid;
    void* C = jobs.j[ji].C;
    int N = jobs.j[ji].N, K = jobs.j[ji].K;
    int mode = jobs.j[ji].mode, t_off = jobs.j[ji].t_off;
    int lid0 = blockIdx.x - jobs.j[ji].off;
    int nbx = N >> 7;
    int by = lid0 / nbx, bx = lid0 - by * nbx;
    int m0 = by * 128, n0 = bx * 128;

    extern __shared__ uint32_t smw[];
    uint32_t sbase = smem_u32(smw);
    int tid = threadIdx.x;
    int wid = tid >> 5, lane = tid & 31;
    int gid = lane >> 2, tig = lane & 3;
    int warp_m = wid >> 1, warp_n = wid & 1;

    float acc[4][8][4];
    #pragma unroll
    for (int mt = 0; mt < 4; mt++)
        #pragma unroll
        for (int nt = 0; nt < 8; nt++)
            #pragma unroll
            for (int e = 0; e < 4; e++) acc[mt][nt][e] = 0.f;

    const int nchunk = K >> 5;
    int lrow = tid >> 2;
    int lblk = tid & 3;

    #pragma unroll
    for (int pc = 0; pc < 2; pc++) {
        const __half* Ap = A + (size_t)m0 * K + pc * 32 + lblk * 8;
        const __half* Bp = B + (size_t)n0 * K + pc * 32 + lblk * 8;
        uint32_t sA = sbase + pc * 2 * HBUF * 4;
        uint32_t sB = sA + HBUF * 4;
        #pragma unroll
        for (int l = 0; l < 4; l++) {
            int r = lrow + l * 32;
            uint32_t so = (r * HST + lblk * 4) * 4;
            cp_async16(sA + so, Ap + (size_t)r * K);
            cp_async16(sB + so, Bp + (size_t)r * K);
        }
        CP_COMMIT();
    }

    int st = 0;
    for (int i = 0; i < nchunk; i++) {
        CP_WAIT1();
        __syncthreads();
        if (i + 2 < nchunk) {
            int ps = st + 2; if (ps >= 3) ps -= 3;
            const __half* Ap = A + (size_t)m0 * K + (i + 2) * 32 + lblk * 8;
            const __half* Bp = B + (size_t)n0 * K + (i + 2) * 32 + lblk * 8;
            uint32_t sA = sbase + ps * 2 * HBUF * 4;
            uint32_t sB = sA + HBUF * 4;
            #pragma unroll
            for (int l = 0; l < 4; l++) {
                int r = lrow + l * 32;
                uint32_t so = (r * HST + lblk * 4) * 4;
                cp_async16(sA + so, Ap + (size_t)r * K);
                cp_async16(sB + so, Bp + (size_t)r * K);
            }
        }
        CP_COMMIT();
        const uint32_t* As = smw + st * 2 * HBUF;
        const uint32_t* Bs = As + HBUF;
        #pragma unroll
        for (int s = 0; s < 2; s++) {
            int wb = s * 8;
            uint32_t af[4][4], bf[8][2];
            #pragma unroll
            for (int mt = 0; mt < 4; mt++) {
                int r0 = warp_m * 64 + mt * 16 + gid;
                af[mt][0] = As[r0 * HST + wb + tig];
                af[mt][1] = As[(r0 + 8) * HST + wb + tig];
                af[mt][2] = As[r0 * HST + wb + tig + 4];
                af[mt][3] = As[(r0 + 8) * HST + wb + tig + 4];
            }
            #pragma unroll
            for (int nt = 0; nt < 8; nt++) {
                int col = warp_n * 64 + nt * 8 + gid;
                bf[nt][0] = Bs[col * HST + wb + tig];
                bf[nt][1] = Bs[col * HST + wb + tig + 4];
            }
            #pragma unroll
            for (int mt = 0; mt < 4; mt++)
                #pragma unroll
                for (int nt = 0; nt < 8; nt++)
                    mma_f16(acc[mt][nt], af[mt], bf[nt]);
        }
        st++; if (st >= 3) st = 0;
    }

    #pragma unroll
    for (int mt = 0; mt < 4; mt++) {
        #pragma unroll
        for (int nt = 0; nt < 8; nt++) {
            int row = m0 + warp_m * 64 + mt * 16 + gid;
            int col = n0 + warp_n * 64 + nt * 8 + tig * 2;
            #pragma unroll
            for (int half = 0; half < 2; half++) {
                int r = row + half * 8;
                float2 v = make_float2(acc[mt][nt][half * 2], acc[mt][nt][half * 2 + 1]);
                if (bias) {
                    float2 bv2 = *(const float2*)(bias + col);
                    v.x += bv2.x; v.y += bv2.y;
                }
                if (mode == 0) {
                    float* Cf = (float*)C;
                    size_t off = (size_t)r * N + col;
                    if (resid) {
                        float2 rv = *(const float2*)(resid + off);
                        v.x += rv.x; v.y += rv.y;
                    }
                    *(float2*)(Cf + off) = v;
                } else if (mode == 1) {
                    // V dim-major: element (t=r, ch=col) -> [h][d][t]
                    __half* Ch = (__half*)C;
                    int hh = col >> 6, dd = col & 63;
                    Ch[((size_t)hh * HD + dd) * TT + t_off + r]     = __float2half_rn(v.x);
                    Ch[((size_t)hh * HD + dd + 1) * TT + t_off + r] = __float2half_rn(v.y);
                } else {
                    __half* Ch = (__half*)C;
                    *(__half2*)(Ch + (size_t)r * N + col) = __floats2half2_rn(v.x, v.y);
                }
            }
        }
    }
}

// ---------------- qk finish (both streams) -> fp16 Q (scaled), K -------
__global__ void qk_finish_all(const float* __restrict__ qkc, const float* __restrict__ qkx,
                              const float* __restrict__ cqn, const float* __restrict__ ckn,
                              const float* __restrict__ xqn, const float* __restrict__ xkn,
                              const float* __restrict__ freqs,
                              __half* __restrict__ Q, __half* __restrict__ Ko) {
    int t = blockIdx.x, h = blockIdx.y, d = threadIdx.x;
    const float* qk; const float* qn; const float* kn; int row;
    if (t < S_C) { qk = qkc; qn = cqn; kn = ckn; row = t; }
    else         { qk = qkx; qn = xqn; kn = xkn; row = t - S_C; }
    float qv = qk[(size_t)row * (2 * D) + h * HD + d];
    float kv = qk[(size_t)row * (2 * D) + D + h * HD + d];
    __shared__ float sh[4];
    float sq = qv * qv, sk = kv * kv;
    #pragma unroll
    for (int o = 16; o > 0; o >>= 1) { sq += __shfl_xor_sync(0xffffffffu, sq, o); sk += __shfl_xor_sync(0xffffffffu, sk, o); }
    int w = d >> 5;
    if ((d & 31) == 0) { sh[w] = sq; sh[2 + w] = sk; }
    __syncthreads();
    float rq = rsqrtf((sh[0] + sh[1]) * (1.0f / HD) + 1e-6f);
    float rk = rsqrtf((sh[2] + sh[3]) * (1.0f / HD) + 1e-6f);
    __shared__ float sQ[HD], sK[HD];
    sQ[d] = qv * rq * qn[d];
    sK[d] = kv * rk * kn[d];
    __syncthreads();
    int i = d >> 1;
    float cs = freqs[((size_t)t * 32 + i) * 2 + 0];
    float sn = freqs[((size_t)t * 32 + i) * 2 + 1];
    float oq, ok;
    if ((d & 1) == 0) { oq = sQ[d] * cs - sQ[d + 1] * sn; ok = sK[d] * cs - sK[d + 1] * sn; }
    else              { oq = sQ[d - 1] * sn + sQ[d] * cs; ok = sK[d - 1] * sn + sK[d] * cs; }
    const float QSC = 0.125f * 1.4426950408889634f;
    size_t off = ((size_t)h * TT + t) * HD + d;
    Q[off] = __float2half_rn(oq * QSC);
    Ko[off] = __float2half_rn(ok);
}

// ======================================================================
// fp16 tensor-core flash attention, 64-row q-tiles, cp.async K/V.
// Q,K natural [H][T][64] fp16 (Q prescaled); V dim-major [H][64][T] fp16.
// smem halves, row stride 72: Qs | Ks0 | Ks1 | Vt0 | Vt1 | Pw
// ======================================================================
#define AHS 72                          // halves per smem row
#define AWS 36                          // words per smem row
#define ATN_SMEM (6 * 64 * AHS * 2)     // 55296 bytes

__global__ __launch_bounds__(128)
void attn_tc(const __half* __restrict__ Q, const __half* __restrict__ K,
             const __half* __restrict__ V, __half* __restrict__ Y) {
    extern __shared__ uint32_t smw[];
    uint32_t sbase = smem_u32(smw);
    int tid = threadIdx.x, wid = tid >> 5, lane = tid & 31;
    int gid = lane >> 2, tig = lane & 3;
    int bxr = 31 - blockIdx.x;
    int h = blockIdx.y;
    int q0 = bxr * 64;
    const __half* Qh = Q + (size_t)h * TT * HD;
    const __half* Kh = K + (size_t)h * TT * HD;
    const __half* Vh = V + (size_t)h * HD * TT;   // dim-major

    const uint32_t* QsW = smw;
    uint32_t* PwW = smw + 5 * 64 * AWS;

    int lrow = tid >> 1;                // 0..63
    int lblk = tid & 1;                 // 64B half-row

    // prefetch Q tile + K/V tile 0
    {
        uint32_t qb = sbase;
        uint32_t kb = sbase + (1 * 64 * AWS) * 4;
        uint32_t vb = sbase + (3 * 64 * AWS) * 4;
        #pragma unroll
        for (int j = 0; j < 4; j++) {
            uint32_t so = (lrow * AHS + lblk * 32 + j * 8) * 2;
            cp_async16(qb + so, Qh + (size_t)(q0 + lrow) * HD + lblk * 32 + j * 8);
            cp_async16(kb + so, Kh + (size_t)lrow * HD + lblk * 32 + j * 8);
            cp_async16(vb + so, Vh + (size_t)lrow * TT + lblk * 32 + j * 8);
        }
        CP_COMMIT();
    }
    CP_WAIT0();
    __syncthreads();

    // Q fragments: rows wid*16+gid, +8; 4 k16 steps
    uint32_t qf[4][4];
    int qrow = wid * 16 + gid;
    #pragma unroll
    for (int ks = 0; ks < 4; ks++) {
        qf[ks][0] = QsW[qrow * AWS + ks * 8 + tig];
        qf[ks][1] = QsW[(qrow + 8) * AWS + ks * 8 + tig];
        qf[ks][2] = QsW[qrow * AWS + ks * 8 + tig + 4];
        qf[ks][3] = QsW[(qrow + 8) * AWS + ks * 8 + tig + 4];
    }
    __syncwarp();

    float ofr[8][4];
    #pragma unroll
    for (int ot = 0; ot < 8; ot++)
        #pragma unroll
        for (int e = 0; e < 4; e++) ofr[ot][e] = 0.f;
    float m0r = -INFINITY, m1r = -INFINITY, l0r = 0.f, l1r = 0.f;

    int ntile = bxr + 1;
    for (int kt = 0; kt < ntile; kt++) {
        int k0g = kt * 64;
        int buf = kt & 1;
        const uint32_t* KsW = smw + (1 + buf) * 64 * AWS;
        const uint32_t* VtW = smw + (3 + buf) * 64 * AWS;
        if (kt > 0) { CP_WAIT0(); __syncthreads(); }
        // S = Q K^T  (fp16, 4 k16 steps x 8 n-tiles)
        float sacc[8][4];
        #pragma unroll
        for (int nt = 0; nt < 8; nt++)
            #pragma unroll
            for (int e = 0; e < 4; e++) sacc[nt][e] = 0.f;
        #pragma unroll
        for (int ks = 0; ks < 4; ks++) {
            #pragma unroll
            for (int nt = 0; nt < 8; nt++) {
                uint32_t bf[2];
                bf[0] = KsW[(nt * 8 + gid) * AWS + ks * 8 + tig];
                bf[1] = KsW[(nt * 8 + gid) * AWS + ks * 8 + tig + 4];
                mma_f16(sacc[nt], qf[ks], bf);
            }
        }
        // prefetch next K/V tile
        if (kt + 1 < ntile) {
            uint32_t kb = sbase + ((1 + (buf ^ 1)) * 64 * AWS) * 4;
            uint32_t vb = sbase + ((3 + (buf ^ 1)) * 64 * AWS) * 4;
            const __half* Kp = Kh + (size_t)(k0g + 64) * HD;
            const __half* Vp = Vh + k0g + 64;
            #pragma unroll
            for (int j = 0; j < 4; j++) {
                uint32_t so = (lrow * AHS + lblk * 32 + j * 8) * 2;
                cp_async16(kb + so, Kp + (size_t)lrow * HD + lblk * 32 + j * 8);
                cp_async16(vb + so, Vp + (size_t)lrow * TT + lblk * 32 + j * 8);
            }
        }
        CP_COMMIT();
        // causal mask on diagonal tile
        if (kt == ntile - 1) {
            int r0 = q0 + wid * 16 + gid;
            #pragma unroll
            for (int nt = 0; nt < 8; nt++) {
                int c0 = k0g + nt * 8 + tig * 2;
                if (c0 > r0)     sacc[nt][0] = -INFINITY;
                if (c0 + 1 > r0) sacc[nt][1] = -INFINITY;
                if (c0 > r0 + 8)     sacc[nt][2] = -INFINITY;
                if (c0 + 1 > r0 + 8) sacc[nt][3] = -INFINITY;
            }
        }
        // online softmax
        float tm0 = -INFINITY, tm1 = -INFINITY;
        #pragma unroll
        for (int nt = 0; nt < 8; nt++) {
            tm0 = fmaxf(tm0, fmaxf(sacc[nt][0], sacc[nt][1]));
            tm1 = fmaxf(tm1, fmaxf(sacc[nt][2], sacc[nt][3]));
        }
        #pragma unroll
        for (int o = 1; o < 4; o <<= 1) {
            tm0 = fmaxf(tm0, __shfl_xor_sync(0xffffffffu, tm0, o));
            tm1 = fmaxf(tm1, __shfl_xor_sync(0xffffffffu, tm1, o));
        }
        float nm0 = fmaxf(m0r, tm0), nm1 = fmaxf(m1r, tm1);
        float c0 = ex2f(m0r - nm0), c1 = ex2f(m1r - nm1);
        m0r = nm0; m1r = nm1;
        float ps0 = 0.f, ps1 = 0.f;
        int row0 = wid * 16 + gid, row1 = row0 + 8;
        #pragma unroll
        for (int nt = 0; nt < 8; nt++) {
            float p00 = ex2f(sacc[nt][0] - nm0);
            float p01 = ex2f(sacc[nt][1] - nm0);
            float p10 = ex2f(sacc[nt][2] - nm1);
            float p11 = ex2f(sacc[nt][3] - nm1);
            ps0 += p00 + p01; ps1 += p10 + p11;
            __half2 h0 = __floats2half2_rn(p00, p01);
            __half2 h1 = __floats2half2_rn(p10, p11);
            PwW[row0 * AWS + nt * 4 + tig] = *(uint32_t*)&h0;
            PwW[row1 * AWS + nt * 4 + tig] = *(uint32_t*)&h1;
        }
        #pragma unroll
        for (int o = 1; o < 4; o <<= 1) {
            ps0 += __shfl_xor_sync(0xffffffffu, ps0, o);
            ps1 += __shfl_xor_sync(0xffffffffu, ps1, o);
        }
        l0r = l0r * c0 + ps0;
        l1r = l1r * c1 + ps1;
        #pragma unroll
        for (int ot = 0; ot < 8; ot++) {
            ofr[ot][0] *= c0; ofr[ot][1] *= c0;
            ofr[ot][2] *= c1; ofr[ot][3] *= c1;
        }
        __syncwarp();
        // O += P V  (A = P rows, B = V dim-major rows)
        #pragma unroll
        for (int ks = 0; ks < 4; ks++) {
            uint32_t af[4];
            af[0] = PwW[row0 * AWS + ks * 8 + tig];
            af[1] = PwW[row1 * AWS + ks * 8 + tig];
            af[2] = PwW[row0 * AWS + ks * 8 + tig + 4];
            af[3] = PwW[row1 * AWS + ks * 8 + tig + 4];
            #pragma unroll
            for (int ot = 0; ot < 8; ot++) {
                uint32_t bf[2];
                bf[0] = VtW[(ot * 8 + gid) * AWS + ks * 8 + tig];
                bf[1] = VtW[(ot * 8 + gid) * AWS + ks * 8 + tig + 4];
                mma_f16(ofr[ot], af, bf);
            }
        }
        __syncwarp();
    }
    float i0 = 1.0f / l0r, i1 = 1.0f / l1r;
    int t0 = q0 + wid * 16 + gid, t1 = t0 + 8;
    #pragma unroll
    for (int ot = 0; ot < 8; ot++) {
        int col = h * HD + ot * 8 + tig * 2;
        *(__half2*)(Y + (size_t)t0 * D + col) = __floats2half2_rn(ofr[ot][0] * i0, ofr[ot][1] * i0);
        *(__half2*)(Y + (size_t)t1 * D + col) = __floats2half2_rn(ofr[ot][2] * i1, ofr[ot][3] * i1);
    }
}

// ---------------- SiLU gate fp16 -> fp16 ----------------
__global__ void silu_all(const __half* __restrict__ a0, const __half* __restrict__ b0,
                         __half* __restrict__ g0, int n0,
                         const __half* __restrict__ a1, const __half* __restrict__ b1,
                         __half* __restrict__ g1, int n1) {
    int i = blockIdx.x * 256 + threadIdx.x;
    if (i < n0) {
        float x = __half2float(a0[i]);
        g0[i] = __float2half_rn((x / (1.0f + expf(-x))) * __half2float(b0[i]));
    } else if (i < n0 + n1) {
        int j = i - n0;
        float x = __half2float(a1[j]);
        g1[j] = __float2half_rn((x / (1.0f + expf(-x))) * __half2float(b1[j]));
    }
}

// ---------------- host launcher ----------------
static inline int nct(int M, int N) { return (M / 128) * (N / 128); }

extern "C" void kernel_launch(void* const* d_in, const int* in_sizes, int n_in,
                              void* d_out, int out_size) {
    const float* x        = (const float*)d_in[0];
    const float* c        = (const float*)d_in[1];
    const float* freqs    = (const float*)d_in[2];
    const float* px_qk_w  = (const float*)d_in[3];
    const float* px_qn    = (const float*)d_in[4];
    const float* px_kn    = (const float*)d_in[5];
    const float* px_v_w   = (const float*)d_in[6];
    const float* px_v_b   = (const float*)d_in[7];
    const float* pc_qk_w  = (const float*)d_in[8];
    const float* pc_qn    = (const float*)d_in[9];
    const float* pc_kn    = (const float*)d_in[10];
    const float* pc_v_w   = (const float*)d_in[11];
    const float* pc_v_b   = (const float*)d_in[12];
    const float* p1_proj_w = (const float*)d_in[13];
    const float* p1_proj_b = (const float*)d_in[14];
    const float* p1_w1    = (const float*)d_in[15];
    const float* p1_b1    = (const float*)d_in[16];
    const float* p1_w3    = (const float*)d_in[17];
    const float* p1_b3    = (const float*)d_in[18];
    const float* p1_w2    = (const float*)d_in[19];
    const float* p1_b2    = (const float*)d_in[20];
    const float* p2_proj_w = (const float*)d_in[21];
    const float* p2_proj_b = (const float*)d_in[22];
    const float* p2_w1    = (const float*)d_in[23];
    const float* p2_b1    = (const float*)d_in[24];
    const float* p2_w3    = (const float*)d_in[25];
    const float* p2_b3    = (const float*)d_in[26];
    const float* p2_w2    = (const float*)d_in[27];
    const float* p2_b2    = (const float*)d_in[28];
    float* out = (float*)d_out;

    float *qkx, *qkc, *x1x, *x1c;
    __half *w16, *cln16, *xln16, *q16, *k16, *v16t, *y16;
    __half *h16x, *h16c, *t16x1, *t16x3, *t16c1, *t16c3, *g16x, *g16c;
    cudaGetSymbolAddress((void**)&qkx, g_qkx);
    cudaGetSymbolAddress((void**)&qkc, g_qkc);
    cudaGetSymbolAddress((void**)&x1x, g_x1x);
    cudaGetSymbolAddress((void**)&x1c, g_x1c);
    cudaGetSymbolAddress((void**)&w16,   g_w16);
    cudaGetSymbolAddress((void**)&cln16, g_cln16);
    cudaGetSymbolAddress((void**)&xln16, g_xln16);
    cudaGetSymbolAddress((void**)&q16,   g_q16);
    cudaGetSymbolAddress((void**)&k16,   g_k16);
    cudaGetSymbolAddress((void**)&v16t,  g_v16t);
    cudaGetSymbolAddress((void**)&y16,   g_y16);
    cudaGetSymbolAddress((void**)&h16x,  g_h16x);
    cudaGetSymbolAddress((void**)&h16c,  g_h16c);
    cudaGetSymbolAddress((void**)&t16x1, g_t16x1);
    cudaGetSymbolAddress((void**)&t16x3, g_t16x3);
    cudaGetSymbolAddress((void**)&t16c1, g_t16c1);
    cudaGetSymbolAddress((void**)&t16c3, g_t16c3);
    cudaGetSymbolAddress((void**)&g16x,  g_g16x);
    cudaGetSymbolAddress((void**)&g16c,  g_g16c);

    cudaFuncSetAttribute(attn_tc, cudaFuncAttributeMaxDynamicSharedMemorySize, ATN_SMEM);
    cudaFuncSetAttribute(mma_gemm_mj, cudaFuncAttributeMaxDynamicSharedMemorySize, MMG_SMEM);

    // 0) convert weights to fp16 arena
    {
        WJobs W;
        int o = 0;
        W.j[0]  = {pc_qk_w,  w16 + O_PCQK, o}; o += 1024;
        W.j[1]  = {px_qk_w,  w16 + O_PXQK, o}; o += 1024;
        W.j[2]  = {pc_v_w,   w16 + O_PCV,  o}; o += 512;
        W.j[3]  = {px_v_w,   w16 + O_PXV,  o}; o += 512;
        W.j[4]  = {p1_proj_w, w16 + O_P1P, o}; o += 512;
        W.j[5]  = {p2_proj_w, w16 + O_P2P, o}; o += 512;
        W.j[6]  = {p1_w1,    w16 + O_P1W1, o}; o += 2048;
        W.j[7]  = {p1_w3,    w16 + O_P1W3, o}; o += 2048;
        W.j[8]  = {p2_w1,    w16 + O_P2W1, o}; o += 2048;
        W.j[9]  = {p2_w3,    w16 + O_P2W3, o}; o += 2048;
        W.j[10] = {p1_w2,    w16 + O_P1W2, o}; o += 2048;
        W.j[11] = {p2_w2,    w16 + O_P2W2, o}; o += 2048;
        cvt16<<<o, 256>>>(W);
    }

    // 1) LayerNorm both streams -> fp16
    ln2_kernel<<<L_X + S_C, 256>>>(x, xln16, L_X, c, cln16);

    // 2) QKV GEMMs; V written fp16 dim-major
    {
        GJobs J; J.n = 4;
        int o = 0;
        J.j[0] = {cln16, w16 + O_PCQK, nullptr, nullptr, qkc,  2 * D, D, o, 0, 0};  o += nct(S_C, 2 * D);
        J.j[1] = {cln16, w16 + O_PCV,  pc_v_b,  nullptr, v16t, D,     D, o, 1, 0};  o += nct(S_C, D);
        J.j[2] = {xln16, w16 + O_PXQK, nullptr, nullptr, qkx,  2 * D, D, o, 0, 0};  o += nct(L_X, 2 * D);
        J.j[3] = {xln16, w16 + O_PXV,  px_v_b,  nullptr, v16t, D,     D, o, 1, S_C}; o += nct(L_X, D);
        mma_gemm_mj<<<o, 128, MMG_SMEM>>>(J);
    }
    qk_finish_all<<<dim3(TT, H), HD>>>(qkc, qkx, pc_qn, pc_kn, px_qn, px_kn, freqs, q16, k16);

    // 3) causal attention (fp16 tensor cores) -> y fp16
    attn_tc<<<dim3(32, H), 128, ATN_SMEM>>>(q16, k16, v16t, y16);

    // 4) output projections (batched)
    const __half* yx16 = y16 + (size_t)S_C * D;
    {
        GJobs J; J.n = 2;
        int o = 0;
        J.j[0] = {yx16, w16 + O_P1P, p1_proj_b, x, x1x, D, D, o, 0, 0}; o += nct(L_X, D);
        J.j[1] = {y16,  w16 + O_P2P, p2_proj_b, c, x1c, D, D, o, 0, 0}; o += nct(S_C, D);
        J.j[2] = J.j[0]; J.j[3] = J.j[0];
        mma_gemm_mj<<<o, 128, MMG_SMEM>>>(J);
    }
    ln2_kernel<<<L_X + S_C, 256>>>(x1x, h16x, L_X, x1c, h16c);

    // 5) w1/w3 (batched) -> fp16 outputs
    {
        GJobs J; J.n = 4;
        int o = 0;
        J.j[0] = {h16x, w16 + O_P1W1, p1_b1, nullptr, t16x1, FF, D, o, 2, 0}; o += nct(L_X, FF);
        J.j[1] = {h16x, w16 + O_P1W3, p1_b3, nullptr, t16x3, FF, D, o, 2, 0}; o += nct(L_X, FF);
        J.j[2] = {h16c, w16 + O_P2W1, p2_b1, nullptr, t16c1, FF, D, o, 2, 0}; o += nct(S_C, FF);
        J.j[3] = {h16c, w16 + O_P2W3, p2_b3, nullptr, t16c3, FF, D, o, 2, 0}; o += nct(S_C, FF);
        mma_gemm_mj<<<o, 128, MMG_SMEM>>>(J);
    }
    silu_all<<<(TT * FF + 255) / 256, 256>>>(t16x1, t16x3, g16x, L_X * FF, t16c1, t16c3, g16c, S_C * FF);

    // 6) w2 (batched)
    {
        GJobs J; J.n = 2;
        int o = 0;
        J.j[0] = {g16x, w16 + O_P1W2, p1_b2, x1x, out,                   D, FF, o, 0, 0}; o += nct(L_X, D);
        J.j[1] = {g16c, w16 + O_P2W2, p2_b2, x1c, out + (size_t)L_X * D, D, FF, o, 0, 0}; o += nct(S_C, D);
        J.j[2] = J.j[0]; J.j[3] = J.j[0];
        mma_gemm_mj<<<o, 128, MMG_SMEM>>>(J);
    }
}

// round 11
// speedup vs baseline: 8.7298x; 1.0849x over previous
#include <cuda_runtime.h>
#include <cuda_fp16.h>
#include <cstdint>
#include <math.h>

// ---------------- problem constants ----------------
#define L_X   1536
#define S_C   512
#define TT    2048          // L_X + S_C
#define D     1024
#define H     16
#define HD    64
#define FF    4096

// ---------------- scratch (device globals; no cudaMalloc allowed) ----------
__device__ float g_qkx[L_X * 2 * D];
__device__ float g_qkc[S_C * 2 * D];
__device__ float g_x1x[L_X * D];
__device__ float g_x1c[S_C * D];

// fp16 buffers
__device__ __half g_w16  [33554432];
__device__ __half g_cln16[S_C * D];
__device__ __half g_xln16[L_X * D];
__device__ __half g_q16  [H * TT * HD];
__device__ __half g_k16  [H * TT * HD];
__device__ __half g_v16t [H * HD * TT];
__device__ __half g_y16  [TT * D];
__device__ __half g_h16x [L_X * D];
__device__ __half g_h16c [S_C * D];
__device__ __half g_t16x1[L_X * FF];
__device__ __half g_t16x3[L_X * FF];
__device__ __half g_t16c1[S_C * FF];
__device__ __half g_t16c3[S_C * FF];
__device__ __half g_g16x [L_X * FF];
__device__ __half g_g16c [S_C * FF];

// arena offsets (halves)
#define O_PCQK 0
#define O_PXQK 2097152
#define O_PCV  4194304
#define O_PXV  5242880
#define O_P1P  6291456
#define O_P2P  7340032
#define O_P1W1 8388608
#define O_P1W3 12582912
#define O_P2W1 16777216
#define O_P2W3 20971520
#define O_P1W2 25165824
#define O_P2W2 29360128

// ---------------- utils ----------------
__device__ __forceinline__ float warpSum(float v) {
    #pragma unroll
    for (int o = 16; o > 0; o >>= 1) v += __shfl_xor_sync(0xffffffffu, v, o);
    return v;
}
__device__ __forceinline__ float ex2f(float x) {
    float y;
    asm("ex2.approx.f32 %0, %1;" : "=f"(y) : "f"(x));
    return y;
}
__device__ __forceinline__ void mma_f16(float* d, const uint32_t* a, const uint32_t* b) {
    asm volatile(
        "mma.sync.aligned.m16n8k16.row.col.f32.f16.f16.f32 "
        "{%0,%1,%2,%3}, {%4,%5,%6,%7}, {%8,%9}, {%0,%1,%2,%3};"
        : "+f"(d[0]), "+f"(d[1]), "+f"(d[2]), "+f"(d[3])
        : "r"(a[0]), "r"(a[1]), "r"(a[2]), "r"(a[3]), "r"(b[0]), "r"(b[1]));
}
__device__ __forceinline__ void ldsm_x4(uint32_t* r, uint32_t addr) {
    asm volatile("ldmatrix.sync.aligned.m8n8.x4.shared.b16 {%0,%1,%2,%3}, [%4];"
        : "=r"(r[0]), "=r"(r[1]), "=r"(r[2]), "=r"(r[3]) : "r"(addr));
}
__device__ __forceinline__ uint32_t smem_u32(const void* p) {
    uint32_t a;
    asm("{ .reg .u64 t; cvta.to.shared.u64 t, %1; cvt.u32.u64 %0, t; }" : "=r"(a) : "l"(p));
    return a;
}
__device__ __forceinline__ void cp_async16(uint32_t saddr, const void* gaddr) {
    asm volatile("cp.async.cg.shared.global [%0], [%1], 16;" :: "r"(saddr), "l"(gaddr));
}
#define CP_COMMIT() asm volatile("cp.async.commit_group;" ::: "memory")
#define CP_WAIT0()  asm volatile("cp.async.wait_group 0;" ::: "memory")
#define CP_WAIT1()  asm volatile("cp.async.wait_group 1;" ::: "memory")

// ---------------- weight fp32 -> fp16 conversion ----------------
struct WJob { const float* src; __half* dst; int off; };
struct WJobs { WJob j[12]; };

__global__ __launch_bounds__(256) void cvt16(WJobs J) {
    int ji = 0;
    #pragma unroll
    for (int t = 1; t < 12; t++) if ((int)blockIdx.x >= J.j[t].off) ji = t;
    size_t idx = ((size_t)(blockIdx.x - J.j[ji].off) * 256 + threadIdx.x) * 8;
    const float4* s = (const float4*)(J.j[ji].src + idx);
    float4 v0 = s[0], v1 = s[1];
    __half2* d = (__half2*)(J.j[ji].dst + idx);
    d[0] = __floats2half2_rn(v0.x, v0.y);
    d[1] = __floats2half2_rn(v0.z, v0.w);
    d[2] = __floats2half2_rn(v1.x, v1.y);
    d[3] = __floats2half2_rn(v1.z, v1.w);
}

// ---------------- LayerNorm pair -> fp16 outputs ----------------
__global__ void ln2_kernel(const float* __restrict__ in0, __half* __restrict__ out0,
                           int rows0,
                           const float* __restrict__ in1, __half* __restrict__ out1) {
    int row = blockIdx.x;
    const float* x;
    __half* o;
    if (row < rows0) { x = in0 + (size_t)row * D; o = out0 + (size_t)row * D; }
    else             { x = in1 + (size_t)(row - rows0) * D; o = out1 + (size_t)(row - rows0) * D; }
    float s = 0.f, ss = 0.f;
    for (int i = threadIdx.x; i < D; i += 256) {
        float v = x[i]; s += v; ss += v * v;
    }
    __shared__ float shs[8], shss[8];
    float ws = warpSum(s), wss = warpSum(ss);
    int w = threadIdx.x >> 5;
    if ((threadIdx.x & 31) == 0) { shs[w] = ws; shss[w] = wss; }
    __syncthreads();
    float ts = 0.f, tss = 0.f;
    #pragma unroll
    for (int i = 0; i < 8; i++) { ts += shs[i]; tss += shss[i]; }
    float mean = ts * (1.0f / D);
    float var  = tss * (1.0f / D) - mean * mean;
    float inv  = rsqrtf(var + 1e-6f);
    for (int i = threadIdx.x; i < D; i += 256)
        o[i] = __float2half_rn((x[i] - mean) * inv);
}

// ======================================================================
// Multi-job fp16 GEMM (m16n8k16), 3-stage cp.async, ldmatrix fragments.
// mode 0: fp32 row-major C (+resid). mode 1: fp16 V dim-major. mode 2: fp16 C.
// ======================================================================
struct GJob {
    const __half* A; const __half* B; const float* bias; const float* resid;
    void* C; int N, K, off, mode, t_off;
};
struct GJobs { GJob j[4]; int n; };

#define HST 20
#define HBUF (128 * HST)
#define MMG_SMEM (3 * 2 * HBUF * 4)

__global__ __launch_bounds__(128)
void mma_gemm_mj(GJobs jobs) {
    int ji = 0;
    if (jobs.n > 1 && (int)blockIdx.x >= jobs.j[1].off) ji = 1;
    if (jobs.n > 2 && (int)blockIdx.x >= jobs.j[2].off) ji = 2;
    if (jobs.n > 3 && (int)blockIdx.x >= jobs.j[3].off) ji = 3;
    const __half* A = jobs.j[ji].A;
    const __half* B = jobs.j[ji].B;
    const float* bias = jobs.j[ji].bias;
    const float* resid = jobs.j[ji].resid;
    void* C = jobs.j[ji].C;
    int N = jobs.j[ji].N, K = jobs.j[ji].K;
    int mode = jobs.j[ji].mode, t_off = jobs.j[ji].t_off;
    int lid0 = blockIdx.x - jobs.j[ji].off;
    int nbx = N >> 7;
    int by = lid0 / nbx, bx = lid0 - by * nbx;
    int m0 = by * 128, n0 = bx * 128;

    extern __shared__ uint32_t smw[];
    uint32_t sbase = smem_u32(smw);
    int tid = threadIdx.x;
    int wid = tid >> 5, lane = tid & 31;
    int gid = lane >> 2, tig = lane & 3;
    int warp_m = wid >> 1, warp_n = wid & 1;

    float acc[4][8][4];
    #pragma unroll
    for (int mt = 0; mt < 4; mt++)
        #pragma unroll
        for (int nt = 0; nt < 8; nt++)
            #pragma unroll
            for (int e = 0; e < 4; e++) acc[mt][nt][e] = 0.f;

    const int nchunk = K >> 5;
    int lrow = tid >> 2;
    int lblk = tid & 3;

    // ldmatrix per-lane address components (byte offsets within stage)
    int tileid = lane >> 3;
    uint32_t aoff = (uint32_t)(warp_m * 64 + (tileid & 1) * 8 + (lane & 7)) * 80
                    + (uint32_t)(tileid >> 1) * 16;
    uint32_t boff = (uint32_t)(warp_n * 64 + (tileid >> 1) * 8 + (lane & 7)) * 80
                    + (uint32_t)(tileid & 1) * 16;

    #pragma unroll
    for (int pc = 0; pc < 2; pc++) {
        const __half* Ap = A + (size_t)m0 * K + pc * 32 + lblk * 8;
        const __half* Bp = B + (size_t)n0 * K + pc * 32 + lblk * 8;
        uint32_t sA = sbase + pc * 2 * HBUF * 4;
        uint32_t sB = sA + HBUF * 4;
        #pragma unroll
        for (int l = 0; l < 4; l++) {
            int r = lrow + l * 32;
            uint32_t so = (r * HST + lblk * 4) * 4;
            cp_async16(sA + so, Ap + (size_t)r * K);
            cp_async16(sB + so, Bp + (size_t)r * K);
        }
        CP_COMMIT();
    }

    int st = 0;
    for (int i = 0; i < nchunk; i++) {
        CP_WAIT1();
        __syncthreads();
        if (i + 2 < nchunk) {
            int ps = st + 2; if (ps >= 3) ps -= 3;
            const __half* Ap = A + (size_t)m0 * K + (i + 2) * 32 + lblk * 8;
            const __half* Bp = B + (size_t)n0 * K + (i + 2) * 32 + lblk * 8;
            uint32_t sA = sbase + ps * 2 * HBUF * 4;
            uint32_t sB = sA + HBUF * 4;
            #pragma unroll
            for (int l = 0; l < 4; l++) {
                int r = lrow + l * 32;
                uint32_t so = (r * HST + lblk * 4) * 4;
                cp_async16(sA + so, Ap + (size_t)r * K);
                cp_async16(sB + so, Bp + (size_t)r * K);
            }
        }
        CP_COMMIT();
        uint32_t stA = sbase + st * 2 * HBUF * 4;
        uint32_t stB = stA + HBUF * 4;
        #pragma unroll
        for (int s = 0; s < 2; s++) {
            uint32_t kbyte = s * 32;
            uint32_t af[4][4], bf[4][4];
            #pragma unroll
            for (int mt = 0; mt < 4; mt++)
                ldsm_x4(af[mt], stA + aoff + (uint32_t)mt * (16 * 80) + kbyte);
            #pragma unroll
            for (int ntp = 0; ntp < 4; ntp++)
                ldsm_x4(bf[ntp], stB + boff + (uint32_t)ntp * (16 * 80) + kbyte);
            #pragma unroll
            for (int mt = 0; mt < 4; mt++)
                #pragma unroll
                for (int ntp = 0; ntp < 4; ntp++) {
                    mma_f16(acc[mt][ntp * 2 + 0], af[mt], &bf[ntp][0]);
                    mma_f16(acc[mt][ntp * 2 + 1], af[mt], &bf[ntp][2]);
                }
        }
        st++; if (st >= 3) st = 0;
    }

    #pragma unroll
    for (int mt = 0; mt < 4; mt++) {
        #pragma unroll
        for (int nt = 0; nt < 8; nt++) {
            int row = m0 + warp_m * 64 + mt * 16 + gid;
            int col = n0 + warp_n * 64 + nt * 8 + tig * 2;
            #pragma unroll
            for (int half = 0; half < 2; half++) {
                int r = row + half * 8;
                float2 v = make_float2(acc[mt][nt][half * 2], acc[mt][nt][half * 2 + 1]);
                if (bias) {
                    float2 bv2 = *(const float2*)(bias + col);
                    v.x += bv2.x; v.y += bv2.y;
                }
                if (mode == 0) {
                    float* Cf = (float*)C;
                    size_t off = (size_t)r * N + col;
                    if (resid) {
                        float2 rv = *(const float2*)(resid + off);
                        v.x += rv.x; v.y += rv.y;
                    }
                    *(float2*)(Cf + off) = v;
                } else if (mode == 1) {
                    __half* Ch = (__half*)C;
                    int hh = col >> 6, dd = col & 63;
                    Ch[((size_t)hh * HD + dd) * TT + t_off + r]     = __float2half_rn(v.x);
                    Ch[((size_t)hh * HD + dd + 1) * TT + t_off + r] = __float2half_rn(v.y);
                } else {
                    __half* Ch = (__half*)C;
                    *(__half2*)(Ch + (size_t)r * N + col) = __floats2half2_rn(v.x, v.y);
                }
            }
        }
    }
}

// ---------------- qk finish: warp per (t,h), lane owns RoPE pair --------
__global__ __launch_bounds__(256)
void qk_finish_all(const float* __restrict__ qkc, const float* __restrict__ qkx,
                   const float* __restrict__ cqn, const float* __restrict__ ckn,
                   const float* __restrict__ xqn, const float* __restrict__ xkn,
                   const float* __restrict__ freqs,
                   __half* __restrict__ Q, __half* __restrict__ Ko) {
    int gidx = blockIdx.x * 8 + (threadIdx.x >> 5);
    int lane = threadIdx.x & 31;
    int t = gidx >> 4;
    int h = gidx & 15;
    const float* qk; const float* qn; const float* kn; int row;
    if (t < S_C) { qk = qkc; qn = cqn; kn = ckn; row = t; }
    else         { qk = qkx; qn = xqn; kn = xkn; row = t - S_C; }
    size_t base = (size_t)row * (2 * D) + h * HD + lane * 2;
    float2 qv = *(const float2*)(qk + base);
    float2 kv = *(const float2*)(qk + base + D);
    float sq = qv.x * qv.x + qv.y * qv.y;
    float sk = kv.x * kv.x + kv.y * kv.y;
    #pragma unroll
    for (int o = 16; o > 0; o >>= 1) {
        sq += __shfl_xor_sync(0xffffffffu, sq, o);
        sk += __shfl_xor_sync(0xffffffffu, sk, o);
    }
    float rq = rsqrtf(sq * (1.0f / HD) + 1e-6f);
    float rk = rsqrtf(sk * (1.0f / HD) + 1e-6f);
    float2 qw = *(const float2*)(qn + lane * 2);
    float2 kw = *(const float2*)(kn + lane * 2);
    float q0 = qv.x * rq * qw.x, q1 = qv.y * rq * qw.y;
    float k0 = kv.x * rk * kw.x, k1 = kv.y * rk * kw.y;
    float2 f = *(const float2*)(freqs + ((size_t)t * 32 + lane) * 2);
    float cs = f.x, sn = f.y;
    const float QSC = 0.125f * 1.4426950408889634f;
    float oq0 = (q0 * cs - q1 * sn) * QSC;
    float oq1 = (q0 * sn + q1 * cs) * QSC;
    float ok0 = k0 * cs - k1 * sn;
    float ok1 = k0 * sn + k1 * cs;
    size_t off = ((size_t)h * TT + t) * HD + lane * 2;
    *(__half2*)(Q + off)  = __floats2half2_rn(oq0, oq1);
    *(__half2*)(Ko + off) = __floats2half2_rn(ok0, ok1);
}

// ======================================================================
// fp16 tensor-core flash attention (unchanged from R10).
// ======================================================================
#define AHS 72
#define AWS 36
#define ATN_SMEM (6 * 64 * AHS * 2)

__global__ __launch_bounds__(128)
void attn_tc(const __half* __restrict__ Q, const __half* __restrict__ K,
             const __half* __restrict__ V, __half* __restrict__ Y) {
    extern __shared__ uint32_t smw[];
    uint32_t sbase = smem_u32(smw);
    int tid = threadIdx.x, wid = tid >> 5, lane = tid & 31;
    int gid = lane >> 2, tig = lane & 3;
    int bxr = 31 - blockIdx.x;
    int h = blockIdx.y;
    int q0 = bxr * 64;
    const __half* Qh = Q + (size_t)h * TT * HD;
    const __half* Kh = K + (size_t)h * TT * HD;
    const __half* Vh = V + (size_t)h * HD * TT;

    const uint32_t* QsW = smw;
    uint32_t* PwW = smw + 5 * 64 * AWS;

    int lrow = tid >> 1;
    int lblk = tid & 1;

    {
        uint32_t qb = sbase;
        uint32_t kb = sbase + (1 * 64 * AWS) * 4;
        uint32_t vb = sbase + (3 * 64 * AWS) * 4;
        #pragma unroll
        for (int j = 0; j < 4; j++) {
            uint32_t so = (lrow * AHS + lblk * 32 + j * 8) * 2;
            cp_async16(qb + so, Qh + (size_t)(q0 + lrow) * HD + lblk * 32 + j * 8);
            cp_async16(kb + so, Kh + (size_t)lrow * HD + lblk * 32 + j * 8);
            cp_async16(vb + so, Vh + (size_t)lrow * TT + lblk * 32 + j * 8);
        }
        CP_COMMIT();
    }
    CP_WAIT0();
    __syncthreads();

    uint32_t qf[4][4];
    int qrow = wid * 16 + gid;
    #pragma unroll
    for (int ks = 0; ks < 4; ks++) {
        qf[ks][0] = QsW[qrow * AWS + ks * 8 + tig];
        qf[ks][1] = QsW[(qrow + 8) * AWS + ks * 8 + tig];
        qf[ks][2] = QsW[qrow * AWS + ks * 8 + tig + 4];
        qf[ks][3] = QsW[(qrow + 8) * AWS + ks * 8 + tig + 4];
    }
    __syncwarp();

    float ofr[8][4];
    #pragma unroll
    for (int ot = 0; ot < 8; ot++)
        #pragma unroll
        for (int e = 0; e < 4; e++) ofr[ot][e] = 0.f;
    float m0r = -INFINITY, m1r = -INFINITY, l0r = 0.f, l1r = 0.f;

    int ntile = bxr + 1;
    for (int kt = 0; kt < ntile; kt++) {
        int k0g = kt * 64;
        int buf = kt & 1;
        const uint32_t* KsW = smw + (1 + buf) * 64 * AWS;
        const uint32_t* VtW = smw + (3 + buf) * 64 * AWS;
        if (kt > 0) { CP_WAIT0(); __syncthreads(); }
        float sacc[8][4];
        #pragma unroll
        for (int nt = 0; nt < 8; nt++)
            #pragma unroll
            for (int e = 0; e < 4; e++) sacc[nt][e] = 0.f;
        #pragma unroll
        for (int ks = 0; ks < 4; ks++) {
            #pragma unroll
            for (int nt = 0; nt < 8; nt++) {
                uint32_t bf[2];
                bf[0] = KsW[(nt * 8 + gid) * AWS + ks * 8 + tig];
                bf[1] = KsW[(nt * 8 + gid) * AWS + ks * 8 + tig + 4];
                mma_f16(sacc[nt], qf[ks], bf);
            }
        }
        if (kt + 1 < ntile) {
            uint32_t kb = sbase + ((1 + (buf ^ 1)) * 64 * AWS) * 4;
            uint32_t vb = sbase + ((3 + (buf ^ 1)) * 64 * AWS) * 4;
            const __half* Kp = Kh + (size_t)(k0g + 64) * HD;
            const __half* Vp = Vh + k0g + 64;
            #pragma unroll
            for (int j = 0; j < 4; j++) {
                uint32_t so = (lrow * AHS + lblk * 32 + j * 8) * 2;
                cp_async16(kb + so, Kp + (size_t)lrow * HD + lblk * 32 + j * 8);
                cp_async16(vb + so, Vp + (size_t)lrow * TT + lblk * 32 + j * 8);
            }
        }
        CP_COMMIT();
        if (kt == ntile - 1) {
            int r0 = q0 + wid * 16 + gid;
            #pragma unroll
            for (int nt = 0; nt < 8; nt++) {
                int c0 = k0g + nt * 8 + tig * 2;
                if (c0 > r0)     sacc[nt][0] = -INFINITY;
                if (c0 + 1 > r0) sacc[nt][1] = -INFINITY;
                if (c0 > r0 + 8)     sacc[nt][2] = -INFINITY;
                if (c0 + 1 > r0 + 8) sacc[nt][3] = -INFINITY;
            }
        }
        float tm0 = -INFINITY, tm1 = -INFINITY;
        #pragma unroll
        for (int nt = 0; nt < 8; nt++) {
            tm0 = fmaxf(tm0, fmaxf(sacc[nt][0], sacc[nt][1]));
            tm1 = fmaxf(tm1, fmaxf(sacc[nt][2], sacc[nt][3]));
        }
        #pragma unroll
        for (int o = 1; o < 4; o <<= 1) {
            tm0 = fmaxf(tm0, __shfl_xor_sync(0xffffffffu, tm0, o));
            tm1 = fmaxf(tm1, __shfl_xor_sync(0xffffffffu, tm1, o));
        }
        float nm0 = fmaxf(m0r, tm0), nm1 = fmaxf(m1r, tm1);
        float c0 = ex2f(m0r - nm0), c1 = ex2f(m1r - nm1);
        m0r = nm0; m1r = nm1;
        float ps0 = 0.f, ps1 = 0.f;
        int row0 = wid * 16 + gid, row1 = row0 + 8;
        #pragma unroll
        for (int nt = 0; nt < 8; nt++) {
            float p00 = ex2f(sacc[nt][0] - nm0);
            float p01 = ex2f(sacc[nt][1] - nm0);
            float p10 = ex2f(sacc[nt][2] - nm1);
            float p11 = ex2f(sacc[nt][3] - nm1);
            ps0 += p00 + p01; ps1 += p10 + p11;
            __half2 h0 = __floats2half2_rn(p00, p01);
            __half2 h1 = __floats2half2_rn(p10, p11);
            PwW[row0 * AWS + nt * 4 + tig] = *(uint32_t*)&h0;
            PwW[row1 * AWS + nt * 4 + tig] = *(uint32_t*)&h1;
        }
        #pragma unroll
        for (int o = 1; o < 4; o <<= 1) {
            ps0 += __shfl_xor_sync(0xffffffffu, ps0, o);
            ps1 += __shfl_xor_sync(0xffffffffu, ps1, o);
        }
        l0r = l0r * c0 + ps0;
        l1r = l1r * c1 + ps1;
        #pragma unroll
        for (int ot = 0; ot < 8; ot++) {
            ofr[ot][0] *= c0; ofr[ot][1] *= c0;
            ofr[ot][2] *= c1; ofr[ot][3] *= c1;
        }
        __syncwarp();
        #pragma unroll
        for (int ks = 0; ks < 4; ks++) {
            uint32_t af[4];
            af[0] = PwW[row0 * AWS + ks * 8 + tig];
            af[1] = PwW[row1 * AWS + ks * 8 + tig];
            af[2] = PwW[row0 * AWS + ks * 8 + tig + 4];
            af[3] = PwW[row1 * AWS + ks * 8 + tig + 4];
            #pragma unroll
            for (int ot = 0; ot < 8; ot++) {
                uint32_t bf[2];
                bf[0] = VtW[(ot * 8 + gid) * AWS + ks * 8 + tig];
                bf[1] = VtW[(ot * 8 + gid) * AWS + ks * 8 + tig + 4];
                mma_f16(ofr[ot], af, bf);
            }
        }
        __syncwarp();
    }
    float i0 = 1.0f / l0r, i1 = 1.0f / l1r;
    int t0 = q0 + wid * 16 + gid, t1 = t0 + 8;
    #pragma unroll
    for (int ot = 0; ot < 8; ot++) {
        int col = h * HD + ot * 8 + tig * 2;
        *(__half2*)(Y + (size_t)t0 * D + col) = __floats2half2_rn(ofr[ot][0] * i0, ofr[ot][1] * i0);
        *(__half2*)(Y + (size_t)t1 * D + col) = __floats2half2_rn(ofr[ot][2] * i1, ofr[ot][3] * i1);
    }
}

// ---------------- SiLU gate fp16 -> fp16 (half2 vectorized) ------------
__global__ __launch_bounds__(256)
void silu_all(const __half* __restrict__ a0, const __half* __restrict__ b0,
              __half* __restrict__ g0, int n0,
              const __half* __restrict__ a1, const __half* __restrict__ b1,
              __half* __restrict__ g1, int n1) {
    int i = blockIdx.x * 256 + threadIdx.x;       // pair index
    int h0 = n0 >> 1;
    if (i < h0) {
        __half2 av = ((const __half2*)a0)[i];
        __half2 bv = ((const __half2*)b0)[i];
        float x0 = __half2float(__low2half(av)), x1 = __half2float(__high2half(av));
        float s0 = (x0 / (1.0f + expf(-x0))) * __half2float(__low2half(bv));
        float s1 = (x1 / (1.0f + expf(-x1))) * __half2float(__high2half(bv));
        ((__half2*)g0)[i] = __floats2half2_rn(s0, s1);
    } else if (i < h0 + (n1 >> 1)) {
        int j = i - h0;
        __half2 av = ((const __half2*)a1)[j];
        __half2 bv = ((const __half2*)b1)[j];
        float x0 = __half2float(__low2half(av)), x1 = __half2float(__high2half(av));
        float s0 = (x0 / (1.0f + expf(-x0))) * __half2float(__low2half(bv));
        float s1 = (x1 / (1.0f + expf(-x1))) * __half2float(__high2half(bv));
        ((__half2*)g1)[j] = __floats2half2_rn(s0, s1);
    }
}

// ---------------- host launcher ----------------
static inline int nct(int M, int N) { return (M / 128) * (N / 128); }

extern "C" void kernel_launch(void* const* d_in, const int* in_sizes, int n_in,
                              void* d_out, int out_size) {
    const float* x        = (const float*)d_in[0];
    const float* c        = (const float*)d_in[1];
    const float* freqs    = (const float*)d_in[2];
    const float* px_qk_w  = (const float*)d_in[3];
    const float* px_qn    = (const float*)d_in[4];
    const float* px_kn    = (const float*)d_in[5];
    const float* px_v_w   = (const float*)d_in[6];
    const float* px_v_b   = (const float*)d_in[7];
    const float* pc_qk_w  = (const float*)d_in[8];
    const float* pc_qn    = (const float*)d_in[9];
    const float* pc_kn    = (const float*)d_in[10];
    const float* pc_v_w   = (const float*)d_in[11];
    const float* pc_v_b   = (const float*)d_in[12];
    const float* p1_proj_w = (const float*)d_in[13];
    const float* p1_proj_b = (const float*)d_in[14];
    const float* p1_w1    = (const float*)d_in[15];
    const float* p1_b1    = (const float*)d_in[16];
    const float* p1_w3    = (const float*)d_in[17];
    const float* p1_b3    = (const float*)d_in[18];
    const float* p1_w2    = (const float*)d_in[19];
    const float* p1_b2    = (const float*)d_in[20];
    const float* p2_proj_w = (const float*)d_in[21];
    const float* p2_proj_b = (const float*)d_in[22];
    const float* p2_w1    = (const float*)d_in[23];
    const float* p2_b1    = (const float*)d_in[24];
    const float* p2_w3    = (const float*)d_in[25];
    const float* p2_b3    = (const float*)d_in[26];
    const float* p2_w2    = (const float*)d_in[27];
    const float* p2_b2    = (const float*)d_in[28];
    float* out = (float*)d_out;

    float *qkx, *qkc, *x1x, *x1c;
    __half *w16, *cln16, *xln16, *q16, *k16, *v16t, *y16;
    __half *h16x, *h16c, *t16x1, *t16x3, *t16c1, *t16c3, *g16x, *g16c;
    cudaGetSymbolAddress((void**)&qkx, g_qkx);
    cudaGetSymbolAddress((void**)&qkc, g_qkc);
    cudaGetSymbolAddress((void**)&x1x, g_x1x);
    cudaGetSymbolAddress((void**)&x1c, g_x1c);
    cudaGetSymbolAddress((void**)&w16,   g_w16);
    cudaGetSymbolAddress((void**)&cln16, g_cln16);
    cudaGetSymbolAddress((void**)&xln16, g_xln16);
    cudaGetSymbolAddress((void**)&q16,   g_q16);
    cudaGetSymbolAddress((void**)&k16,   g_k16);
    cudaGetSymbolAddress((void**)&v16t,  g_v16t);
    cudaGetSymbolAddress((void**)&y16,   g_y16);
    cudaGetSymbolAddress((void**)&h16x,  g_h16x);
    cudaGetSymbolAddress((void**)&h16c,  g_h16c);
    cudaGetSymbolAddress((void**)&t16x1, g_t16x1);
    cudaGetSymbolAddress((void**)&t16x3, g_t16x3);
    cudaGetSymbolAddress((void**)&t16c1, g_t16c1);
    cudaGetSymbolAddress((void**)&t16c3, g_t16c3);
    cudaGetSymbolAddress((void**)&g16x,  g_g16x);
    cudaGetSymbolAddress((void**)&g16c,  g_g16c);

    cudaFuncSetAttribute(attn_tc, cudaFuncAttributeMaxDynamicSharedMemorySize, ATN_SMEM);
    cudaFuncSetAttribute(mma_gemm_mj, cudaFuncAttributeMaxDynamicSharedMemorySize, MMG_SMEM);

    // 0) convert weights to fp16 arena
    {
        WJobs W;
        int o = 0;
        W.j[0]  = {pc_qk_w,  w16 + O_PCQK, o}; o += 1024;
        W.j[1]  = {px_qk_w,  w16 + O_PXQK, o}; o += 1024;
        W.j[2]  = {pc_v_w,   w16 + O_PCV,  o}; o += 512;
        W.j[3]  = {px_v_w,   w16 + O_PXV,  o}; o += 512;
        W.j[4]  = {p1_proj_w, w16 + O_P1P, o}; o += 512;
        W.j[5]  = {p2_proj_w, w16 + O_P2P, o}; o += 512;
        W.j[6]  = {p1_w1,    w16 + O_P1W1, o}; o += 2048;
        W.j[7]  = {p1_w3,    w16 + O_P1W3, o}; o += 2048;
        W.j[8]  = {p2_w1,    w16 + O_P2W1, o}; o += 2048;
        W.j[9]  = {p2_w3,    w16 + O_P2W3, o}; o += 2048;
        W.j[10] = {p1_w2,    w16 + O_P1W2, o}; o += 2048;
        W.j[11] = {p2_w2,    w16 + O_P2W2, o}; o += 2048;
        cvt16<<<o, 256>>>(W);
    }

    // 1) LayerNorm both streams -> fp16
    ln2_kernel<<<L_X + S_C, 256>>>(x, xln16, L_X, c, cln16);

    // 2) QKV GEMMs; V written fp16 dim-major
    {
        GJobs J; J.n = 4;
        int o = 0;
        J.j[0] = {cln16, w16 + O_PCQK, nullptr, nullptr, qkc,  2 * D, D, o, 0, 0};  o += nct(S_C, 2 * D);
        J.j[1] = {cln16, w16 + O_PCV,  pc_v_b,  nullptr, v16t, D,     D, o, 1, 0};  o += nct(S_C, D);
        J.j[2] = {xln16, w16 + O_PXQK, nullptr, nullptr, qkx,  2 * D, D, o, 0, 0};  o += nct(L_X, 2 * D);
        J.j[3] = {xln16, w16 + O_PXV,  px_v_b,  nullptr, v16t, D,     D, o, 1, S_C}; o += nct(L_X, D);
        mma_gemm_mj<<<o, 128, MMG_SMEM>>>(J);
    }
    qk_finish_all<<<TT * H / 8, 256>>>(qkc, qkx, pc_qn, pc_kn, px_qn, px_kn, freqs, q16, k16);

    // 3) causal attention (fp16 tensor cores) -> y fp16
    attn_tc<<<dim3(32, H), 128, ATN_SMEM>>>(q16, k16, v16t, y16);

    // 4) output projections (batched)
    const __half* yx16 = y16 + (size_t)S_C * D;
    {
        GJobs J; J.n = 2;
        int o = 0;
        J.j[0] = {yx16, w16 + O_P1P, p1_proj_b, x, x1x, D, D, o, 0, 0}; o += nct(L_X, D);
        J.j[1] = {y16,  w16 + O_P2P, p2_proj_b, c, x1c, D, D, o, 0, 0}; o += nct(S_C, D);
        J.j[2] = J.j[0]; J.j[3] = J.j[0];
        mma_gemm_mj<<<o, 128, MMG_SMEM>>>(J);
    }
    ln2_kernel<<<L_X + S_C, 256>>>(x1x, h16x, L_X, x1c, h16c);

    // 5) w1/w3 (batched) -> fp16 outputs
    {
        GJobs J; J.n = 4;
        int o = 0;
        J.j[0] = {h16x, w16 + O_P1W1, p1_b1, nullptr, t16x1, FF, D, o, 2, 0}; o += nct(L_X, FF);
        J.j[1] = {h16x, w16 + O_P1W3, p1_b3, nullptr, t16x3, FF, D, o, 2, 0}; o += nct(L_X, FF);
        J.j[2] = {h16c, w16 + O_P2W1, p2_b1, nullptr, t16c1, FF, D, o, 2, 0}; o += nct(S_C, FF);
        J.j[3] = {h16c, w16 + O_P2W3, p2_b3, nullptr, t16c3, FF, D, o, 2, 0}; o += nct(S_C, FF);
        mma_gemm_mj<<<o, 128, MMG_SMEM>>>(J);
    }
    silu_all<<<(TT * FF / 2 + 255) / 256, 256>>>(t16x1, t16x3, g16x, L_X * FF, t16c1, t16c3, g16c, S_C * FF);

    // 6) w2 (batched)
    {
        GJobs J; J.n = 2;
        int o = 0;
        J.j[0] = {g16x, w16 + O_P1W2, p1_b2, x1x, out,                   D, FF, o, 0, 0}; o += nct(L_X, D);
        J.j[1] = {g16c, w16 + O_P2W2, p2_b2, x1c, out + (size_t)L_X * D, D, FF, o, 0, 0}; o += nct(S_C, D);
        J.j[2] = J.j[0]; J.j[3] = J.j[0];
        mma_gemm_mj<<<o, 128, MMG_SMEM>>>(J);
    }
}

// round 12
// speedup vs baseline: 9.0392x; 1.0354x over previous
#include <cuda_runtime.h>
#include <cuda_fp16.h>
#include <cstdint>
#include <math.h>

// ---------------- problem constants ----------------
#define L_X   1536
#define S_C   512
#define TT    2048          // L_X + S_C
#define D     1024
#define H     16
#define HD    64
#define FF    4096

// ---------------- scratch (device globals; no cudaMalloc allowed) ----------
__device__ float g_x1x[L_X * D];
__device__ float g_x1c[S_C * D];

// fp16 buffers
__device__ __half g_w16  [33554432];
__device__ __half g_qk16x[L_X * 2 * D];
__device__ __half g_qk16c[S_C * 2 * D];
__device__ __half g_cln16[S_C * D];
__device__ __half g_xln16[L_X * D];
__device__ __half g_q16  [H * TT * HD];
__device__ __half g_k16  [H * TT * HD];
__device__ __half g_v16t [H * HD * TT];
__device__ __half g_y16  [TT * D];
__device__ __half g_h16x [L_X * D];
__device__ __half g_h16c [S_C * D];
__device__ __half g_t16x1[L_X * FF];
__device__ __half g_t16x3[L_X * FF];
__device__ __half g_t16c1[S_C * FF];
__device__ __half g_t16c3[S_C * FF];
__device__ __half g_g16x [L_X * FF];
__device__ __half g_g16c [S_C * FF];

// arena offsets (halves)
#define O_PCQK 0
#define O_PXQK 2097152
#define O_PCV  4194304
#define O_PXV  5242880
#define O_P1P  6291456
#define O_P2P  7340032
#define O_P1W1 8388608
#define O_P1W3 12582912
#define O_P2W1 16777216
#define O_P2W3 20971520
#define O_P1W2 25165824
#define O_P2W2 29360128

// ---------------- utils ----------------
__device__ __forceinline__ float warpSum(float v) {
    #pragma unroll
    for (int o = 16; o > 0; o >>= 1) v += __shfl_xor_sync(0xffffffffu, v, o);
    return v;
}
__device__ __forceinline__ float ex2f(float x) {
    float y;
    asm("ex2.approx.f32 %0, %1;" : "=f"(y) : "f"(x));
    return y;
}
__device__ __forceinline__ void mma_f16(float* d, const uint32_t* a, const uint32_t* b) {
    asm volatile(
        "mma.sync.aligned.m16n8k16.row.col.f32.f16.f16.f32 "
        "{%0,%1,%2,%3}, {%4,%5,%6,%7}, {%8,%9}, {%0,%1,%2,%3};"
        : "+f"(d[0]), "+f"(d[1]), "+f"(d[2]), "+f"(d[3])
        : "r"(a[0]), "r"(a[1]), "r"(a[2]), "r"(a[3]), "r"(b[0]), "r"(b[1]));
}
__device__ __forceinline__ void ldsm_x4(uint32_t* r, uint32_t addr) {
    asm volatile("ldmatrix.sync.aligned.m8n8.x4.shared.b16 {%0,%1,%2,%3}, [%4];"
        : "=r"(r[0]), "=r"(r[1]), "=r"(r[2]), "=r"(r[3]) : "r"(addr));
}
__device__ __forceinline__ uint32_t smem_u32(const void* p) {
    uint32_t a;
    asm("{ .reg .u64 t; cvta.to.shared.u64 t, %1; cvt.u32.u64 %0, t; }" : "=r"(a) : "l"(p));
    return a;
}
__device__ __forceinline__ void cp_async16(uint32_t saddr, const void* gaddr) {
    asm volatile("cp.async.cg.shared.global [%0], [%1], 16;" :: "r"(saddr), "l"(gaddr));
}
#define CP_COMMIT() asm volatile("cp.async.commit_group;" ::: "memory")
#define CP_WAIT0()  asm volatile("cp.async.wait_group 0;" ::: "memory")
#define CP_WAIT1()  asm volatile("cp.async.wait_group 1;" ::: "memory")

// ---------------- weight fp32 -> fp16 conversion ----------------
struct WJob { const float* src; __half* dst; int off; };
struct WJobs { WJob j[12]; };

__global__ __launch_bounds__(256) void cvt16(WJobs J) {
    int ji = 0;
    #pragma unroll
    for (int t = 1; t < 12; t++) if ((int)blockIdx.x >= J.j[t].off) ji = t;
    size_t idx = ((size_t)(blockIdx.x - J.j[ji].off) * 256 + threadIdx.x) * 8;
    const float4* s = (const float4*)(J.j[ji].src + idx);
    float4 v0 = s[0], v1 = s[1];
    __half2* d = (__half2*)(J.j[ji].dst + idx);
    d[0] = __floats2half2_rn(v0.x, v0.y);
    d[1] = __floats2half2_rn(v0.z, v0.w);
    d[2] = __floats2half2_rn(v1.x, v1.y);
    d[3] = __floats2half2_rn(v1.z, v1.w);
}

// ---------------- LayerNorm pair -> fp16 (row cached in registers) -----
__global__ __launch_bounds__(256)
void ln2_kernel(const float* __restrict__ in0, __half* __restrict__ out0,
                int rows0,
                const float* __restrict__ in1, __half* __restrict__ out1) {
    int row = blockIdx.x;
    const float* x;
    __half* o;
    if (row < rows0) { x = in0 + (size_t)row * D; o = out0 + (size_t)row * D; }
    else             { x = in1 + (size_t)(row - rows0) * D; o = out1 + (size_t)(row - rows0) * D; }
    float4 v = *(const float4*)(x + threadIdx.x * 4);
    float s = v.x + v.y + v.z + v.w;
    float ss = v.x * v.x + v.y * v.y + v.z * v.z + v.w * v.w;
    __shared__ float shs[8], shss[8];
    float ws = warpSum(s), wss = warpSum(ss);
    int w = threadIdx.x >> 5;
    if ((threadIdx.x & 31) == 0) { shs[w] = ws; shss[w] = wss; }
    __syncthreads();
    float ts = 0.f, tss = 0.f;
    #pragma unroll
    for (int i = 0; i < 8; i++) { ts += shs[i]; tss += shss[i]; }
    float mean = ts * (1.0f / D);
    float var  = tss * (1.0f / D) - mean * mean;
    float inv  = rsqrtf(var + 1e-6f);
    __half2* o2 = (__half2*)(o + threadIdx.x * 4);
    o2[0] = __floats2half2_rn((v.x - mean) * inv, (v.y - mean) * inv);
    o2[1] = __floats2half2_rn((v.z - mean) * inv, (v.w - mean) * inv);
}

// ======================================================================
// Multi-job fp16 GEMM (m16n8k16), 3-stage cp.async, ldmatrix fragments.
// mode 0: fp32 row-major C (+resid). mode 1: fp16 V dim-major. mode 2: fp16 C.
// ======================================================================
struct GJob {
    const __half* A; const __half* B; const float* bias; const float* resid;
    void* C; int N, K, off, mode, t_off;
};
struct GJobs { GJob j[4]; int n; };

#define HST 20
#define HBUF (128 * HST)
#define MMG_SMEM (3 * 2 * HBUF * 4)

__global__ __launch_bounds__(128)
void mma_gemm_mj(GJobs jobs) {
    int ji = 0;
    if (jobs.n > 1 && (int)blockIdx.x >= jobs.j[1].off) ji = 1;
    if (jobs.n > 2 && (int)blockIdx.x >= jobs.j[2].off) ji = 2;
    if (jobs.n > 3 && (int)blockIdx.x >= jobs.j[3].off) ji = 3;
    const __half* A = jobs.j[ji].A;
    const __half* B = jobs.j[ji].B;
    const float* bias = jobs.j[ji].bias;
    const float* resid = jobs.j[ji].resid;
    void* C = jobs.j[ji].C;
    int N = jobs.j[ji].N, K = jobs.j[ji].K;
    int mode = jobs.j[ji].mode, t_off = jobs.j[ji].t_off;
    int lid0 = blockIdx.x - jobs.j[ji].off;
    int nbx = N >> 7;
    int by = lid0 / nbx, bx = lid0 - by * nbx;
    int m0 = by * 128, n0 = bx * 128;

    extern __shared__ uint32_t smw[];
    uint32_t sbase = smem_u32(smw);
    int tid = threadIdx.x;
    int wid = tid >> 5, lane = tid & 31;
    int gid = lane >> 2, tig = lane & 3;
    int warp_m = wid >> 1, warp_n = wid & 1;

    float acc[4][8][4];
    #pragma unroll
    for (int mt = 0; mt < 4; mt++)
        #pragma unroll
        for (int nt = 0; nt < 8; nt++)
            #pragma unroll
            for (int e = 0; e < 4; e++) acc[mt][nt][e] = 0.f;

    const int nchunk = K >> 5;
    int lrow = tid >> 2;
    int lblk = tid & 3;

    int tileid = lane >> 3;
    uint32_t aoff = (uint32_t)(warp_m * 64 + (tileid & 1) * 8 + (lane & 7)) * 80
                    + (uint32_t)(tileid >> 1) * 16;
    uint32_t boff = (uint32_t)(warp_n * 64 + (tileid >> 1) * 8 + (lane & 7)) * 80
                    + (uint32_t)(tileid & 1) * 16;

    #pragma unroll
    for (int pc = 0; pc < 2; pc++) {
        const __half* Ap = A + (size_t)m0 * K + pc * 32 + lblk * 8;
        const __half* Bp = B + (size_t)n0 * K + pc * 32 + lblk * 8;
        uint32_t sA = sbase + pc * 2 * HBUF * 4;
        uint32_t sB = sA + HBUF * 4;
        #pragma unroll
        for (int l = 0; l < 4; l++) {
            int r = lrow + l * 32;
            uint32_t so = (r * HST + lblk * 4) * 4;
            cp_async16(sA + so, Ap + (size_t)r * K);
            cp_async16(sB + so, Bp + (size_t)r * K);
        }
        CP_COMMIT();
    }

    int st = 0;
    for (int i = 0; i < nchunk; i++) {
        CP_WAIT1();
        __syncthreads();
        if (i + 2 < nchunk) {
            int ps = st + 2; if (ps >= 3) ps -= 3;
            const __half* Ap = A + (size_t)m0 * K + (i + 2) * 32 + lblk * 8;
            const __half* Bp = B + (size_t)n0 * K + (i + 2) * 32 + lblk * 8;
            uint32_t sA = sbase + ps * 2 * HBUF * 4;
            uint32_t sB = sA + HBUF * 4;
            #pragma unroll
            for (int l = 0; l < 4; l++) {
                int r = lrow + l * 32;
                uint32_t so = (r * HST + lblk * 4) * 4;
                cp_async16(sA + so, Ap + (size_t)r * K);
                cp_async16(sB + so, Bp + (size_t)r * K);
            }
        }
        CP_COMMIT();
        uint32_t stA = sbase + st * 2 * HBUF * 4;
        uint32_t stB = stA + HBUF * 4;
        #pragma unroll
        for (int s = 0; s < 2; s++) {
            uint32_t kbyte = s * 32;
            uint32_t af[4][4], bf[4][4];
            #pragma unroll
            for (int mt = 0; mt < 4; mt++)
                ldsm_x4(af[mt], stA + aoff + (uint32_t)mt * (16 * 80) + kbyte);
            #pragma unroll
            for (int ntp = 0; ntp < 4; ntp++)
                ldsm_x4(bf[ntp], stB + boff + (uint32_t)ntp * (16 * 80) + kbyte);
            #pragma unroll
            for (int mt = 0; mt < 4; mt++)
                #pragma unroll
                for (int ntp = 0; ntp < 4; ntp++) {
                    mma_f16(acc[mt][ntp * 2 + 0], af[mt], &bf[ntp][0]);
                    mma_f16(acc[mt][ntp * 2 + 1], af[mt], &bf[ntp][2]);
                }
        }
        st++; if (st >= 3) st = 0;
    }

    #pragma unroll
    for (int mt = 0; mt < 4; mt++) {
        #pragma unroll
        for (int nt = 0; nt < 8; nt++) {
            int row = m0 + warp_m * 64 + mt * 16 + gid;
            int col = n0 + warp_n * 64 + nt * 8 + tig * 2;
            #pragma unroll
            for (int half = 0; half < 2; half++) {
                int r = row + half * 8;
                float2 v = make_float2(acc[mt][nt][half * 2], acc[mt][nt][half * 2 + 1]);
                if (bias) {
                    float2 bv2 = *(const float2*)(bias + col);
                    v.x += bv2.x; v.y += bv2.y;
                }
                if (mode == 0) {
                    float* Cf = (float*)C;
                    size_t off = (size_t)r * N + col;
                    if (resid) {
                        float2 rv = *(const float2*)(resid + off);
                        v.x += rv.x; v.y += rv.y;
                    }
                    *(float2*)(Cf + off) = v;
                } else if (mode == 1) {
                    __half* Ch = (__half*)C;
                    int hh = col >> 6, dd = col & 63;
                    Ch[((size_t)hh * HD + dd) * TT + t_off + r]     = __float2half_rn(v.x);
                    Ch[((size_t)hh * HD + dd + 1) * TT + t_off + r] = __float2half_rn(v.y);
                } else {
                    __half* Ch = (__half*)C;
                    *(__half2*)(Ch + (size_t)r * N + col) = __floats2half2_rn(v.x, v.y);
                }
            }
        }
    }
}

// ---------------- qk finish: warp per (t,h), lane owns RoPE pair --------
__global__ __launch_bounds__(256)
void qk_finish_all(const __half* __restrict__ qkc, const __half* __restrict__ qkx,
                   const float* __restrict__ cqn, const float* __restrict__ ckn,
                   const float* __restrict__ xqn, const float* __restrict__ xkn,
                   const float* __restrict__ freqs,
                   __half* __restrict__ Q, __half* __restrict__ Ko) {
    int gidx = blockIdx.x * 8 + (threadIdx.x >> 5);
    int lane = threadIdx.x & 31;
    int t = gidx >> 4;
    int h = gidx & 15;
    const __half* qk; const float* qn; const float* kn; int row;
    if (t < S_C) { qk = qkc; qn = cqn; kn = ckn; row = t; }
    else         { qk = qkx; qn = xqn; kn = xkn; row = t - S_C; }
    size_t base = (size_t)row * (2 * D) + h * HD + lane * 2;
    float2 qv = __half22float2(*(const __half2*)(qk + base));
    float2 kv = __half22float2(*(const __half2*)(qk + base + D));
    float sq = qv.x * qv.x + qv.y * qv.y;
    float sk = kv.x * kv.x + kv.y * kv.y;
    #pragma unroll
    for (int o = 16; o > 0; o >>= 1) {
        sq += __shfl_xor_sync(0xffffffffu, sq, o);
        sk += __shfl_xor_sync(0xffffffffu, sk, o);
    }
    float rq = rsqrtf(sq * (1.0f / HD) + 1e-6f);
    float rk = rsqrtf(sk * (1.0f / HD) + 1e-6f);
    float2 qw = *(const float2*)(qn + lane * 2);
    float2 kw = *(const float2*)(kn + lane * 2);
    float q0 = qv.x * rq * qw.x, q1 = qv.y * rq * qw.y;
    float k0 = kv.x * rk * kw.x, k1 = kv.y * rk * kw.y;
    float2 f = *(const float2*)(freqs + ((size_t)t * 32 + lane) * 2);
    float cs = f.x, sn = f.y;
    const float QSC = 0.125f * 1.4426950408889634f;
    float oq0 = (q0 * cs - q1 * sn) * QSC;
    float oq1 = (q0 * sn + q1 * cs) * QSC;
    float ok0 = k0 * cs - k1 * sn;
    float ok1 = k0 * sn + k1 * cs;
    size_t off = ((size_t)h * TT + t) * HD + lane * 2;
    *(__half2*)(Q + off)  = __floats2half2_rn(oq0, oq1);
    *(__half2*)(Ko + off) = __floats2half2_rn(ok0, ok1);
}

// ======================================================================
// fp16 tensor-core flash attention, ldmatrix fragments.
// Q,K natural [H][T][64] fp16 (Q prescaled); V dim-major [H][64][T] fp16.
// smem halves, row stride 72: Qs | Ks0 | Ks1 | Vt0 | Vt1 | Pw
// ======================================================================
#define AHS 72
#define AWS 36
#define ATN_SMEM (6 * 64 * AHS * 2)

__global__ __launch_bounds__(128)
void attn_tc(const __half* __restrict__ Q, const __half* __restrict__ K,
             const __half* __restrict__ V, __half* __restrict__ Y) {
    extern __shared__ uint32_t smw[];
    uint32_t sbase = smem_u32(smw);
    int tid = threadIdx.x, wid = tid >> 5, lane = tid & 31;
    int gid = lane >> 2, tig = lane & 3;
    int bxr = 31 - blockIdx.x;
    int h = blockIdx.y;
    int q0 = bxr * 64;
    const __half* Qh = Q + (size_t)h * TT * HD;
    const __half* Kh = K + (size_t)h * TT * HD;
    const __half* Vh = V + (size_t)h * HD * TT;

    const uint32_t* QsW = smw;
    uint32_t* PwW = smw + 5 * 64 * AWS;

    int lrow = tid >> 1;
    int lblk = tid & 1;

    int tileid = lane >> 3;
    // A-frag (P) rows: wid*16 block; B-frag (K/V) rows: 16-row groups
    uint32_t poff = (uint32_t)(wid * 16 + (tileid & 1) * 8 + (lane & 7)) * (AHS * 2)
                    + (uint32_t)(tileid >> 1) * 16;
    uint32_t boff = (uint32_t)((tileid >> 1) * 8 + (lane & 7)) * (AHS * 2)
                    + (uint32_t)(tileid & 1) * 16;

    {
        uint32_t qb = sbase;
        uint32_t kb = sbase + (1 * 64 * AWS) * 4;
        uint32_t vb = sbase + (3 * 64 * AWS) * 4;
        #pragma unroll
        for (int j = 0; j < 4; j++) {
            uint32_t so = (lrow * AHS + lblk * 32 + j * 8) * 2;
            cp_async16(qb + so, Qh + (size_t)(q0 + lrow) * HD + lblk * 32 + j * 8);
            cp_async16(kb + so, Kh + (size_t)lrow * HD + lblk * 32 + j * 8);
            cp_async16(vb + so, Vh + (size_t)lrow * TT + lblk * 32 + j * 8);
        }
        CP_COMMIT();
    }
    CP_WAIT0();
    __syncthreads();

    uint32_t qf[4][4];
    int qrow = wid * 16 + gid;
    #pragma unroll
    for (int ks = 0; ks < 4; ks++) {
        qf[ks][0] = QsW[qrow * AWS + ks * 8 + tig];
        qf[ks][1] = QsW[(qrow + 8) * AWS + ks * 8 + tig];
        qf[ks][2] = QsW[qrow * AWS + ks * 8 + tig + 4];
        qf[ks][3] = QsW[(qrow + 8) * AWS + ks * 8 + tig + 4];
    }
    __syncwarp();

    float ofr[8][4];
    #pragma unroll
    for (int ot = 0; ot < 8; ot++)
        #pragma unroll
        for (int e = 0; e < 4; e++) ofr[ot][e] = 0.f;
    float m0r = -INFINITY, m1r = -INFINITY, l0r = 0.f, l1r = 0.f;

    int ntile = bxr + 1;
    for (int kt = 0; kt < ntile; kt++) {
        int k0g = kt * 64;
        int buf = kt & 1;
        uint32_t kbase = sbase + ((1 + buf) * 64 * AWS) * 4;
        uint32_t vbase = sbase + ((3 + buf) * 64 * AWS) * 4;
        uint32_t pbase = sbase + (5 * 64 * AWS) * 4;
        if (kt > 0) { CP_WAIT0(); __syncthreads(); }
        // S = Q K^T  (ldmatrix B-frags)
        float sacc[8][4];
        #pragma unroll
        for (int nt = 0; nt < 8; nt++)
            #pragma unroll
            for (int e = 0; e < 4; e++) sacc[nt][e] = 0.f;
        #pragma unroll
        for (int ks = 0; ks < 4; ks++) {
            uint32_t bk[4][4];
            #pragma unroll
            for (int kp = 0; kp < 4; kp++)
                ldsm_x4(bk[kp], kbase + boff + (uint32_t)kp * (16 * AHS * 2) + ks * 32);
            #pragma unroll
            for (int kp = 0; kp < 4; kp++) {
                mma_f16(sacc[kp * 2 + 0], qf[ks], &bk[kp][0]);
                mma_f16(sacc[kp * 2 + 1], qf[ks], &bk[kp][2]);
            }
        }
        if (kt + 1 < ntile) {
            uint32_t kb = sbase + ((1 + (buf ^ 1)) * 64 * AWS) * 4;
            uint32_t vb = sbase + ((3 + (buf ^ 1)) * 64 * AWS) * 4;
            const __half* Kp = Kh + (size_t)(k0g + 64) * HD;
            const __half* Vp = Vh + k0g + 64;
            #pragma unroll
            for (int j = 0; j < 4; j++) {
                uint32_t so = (lrow * AHS + lblk * 32 + j * 8) * 2;
                cp_async16(kb + so, Kp + (size_t)lrow * HD + lblk * 32 + j * 8);
                cp_async16(vb + so, Vp + (size_t)lrow * TT + lblk * 32 + j * 8);
            }
        }
        CP_COMMIT();
        if (kt == ntile - 1) {
            int r0 = q0 + wid * 16 + gid;
            #pragma unroll
            for (int nt = 0; nt < 8; nt++) {
                int c0 = k0g + nt * 8 + tig * 2;
                if (c0 > r0)     sacc[nt][0] = -INFINITY;
                if (c0 + 1 > r0) sacc[nt][1] = -INFINITY;
                if (c0 > r0 + 8)     sacc[nt][2] = -INFINITY;
                if (c0 + 1 > r0 + 8) sacc[nt][3] = -INFINITY;
            }
        }
        float tm0 = -INFINITY, tm1 = -INFINITY;
        #pragma unroll
        for (int nt = 0; nt < 8; nt++) {
            tm0 = fmaxf(tm0, fmaxf(sacc[nt][0], sacc[nt][1]));
            tm1 = fmaxf(tm1, fmaxf(sacc[nt][2], sacc[nt][3]));
        }
        #pragma unroll
        for (int o = 1; o < 4; o <<= 1) {
            tm0 = fmaxf(tm0, __shfl_xor_sync(0xffffffffu, tm0, o));
            tm1 = fmaxf(tm1, __shfl_xor_sync(0xffffffffu, tm1, o));
        }
        float nm0 = fmaxf(m0r, tm0), nm1 = fmaxf(m1r, tm1);
        float c0 = ex2f(m0r - nm0), c1 = ex2f(m1r - nm1);
        m0r = nm0; m1r = nm1;
        float ps0 = 0.f, ps1 = 0.f;
        int row0 = wid * 16 + gid, row1 = row0 + 8;
        #pragma unroll
        for (int nt = 0; nt < 8; nt++) {
            float p00 = ex2f(sacc[nt][0] - nm0);
            float p01 = ex2f(sacc[nt][1] - nm0);
            float p10 = ex2f(sacc[nt][2] - nm1);
            float p11 = ex2f(sacc[nt][3] - nm1);
            ps0 += p00 + p01; ps1 += p10 + p11;
            __half2 h0 = __floats2half2_rn(p00, p01);
            __half2 h1 = __floats2half2_rn(p10, p11);
            PwW[row0 * AWS + nt * 4 + tig] = *(uint32_t*)&h0;
            PwW[row1 * AWS + nt * 4 + tig] = *(uint32_t*)&h1;
        }
        #pragma unroll
        for (int o = 1; o < 4; o <<= 1) {
            ps0 += __shfl_xor_sync(0xffffffffu, ps0, o);
            ps1 += __shfl_xor_sync(0xffffffffu, ps1, o);
        }
        l0r = l0r * c0 + ps0;
        l1r = l1r * c1 + ps1;
        #pragma unroll
        for (int ot = 0; ot < 8; ot++) {
            ofr[ot][0] *= c0; ofr[ot][1] *= c0;
            ofr[ot][2] *= c1; ofr[ot][3] *= c1;
        }
        __syncwarp();
        // O += P V   (ldmatrix A from Pw, B from VtW)
        #pragma unroll
        for (int ks = 0; ks < 4; ks++) {
            uint32_t af[4];
            ldsm_x4(af, pbase + poff + ks * 32);
            uint32_t bv[4][4];
            #pragma unroll
            for (int vp = 0; vp < 4; vp++)
                ldsm_x4(bv[vp], vbase + boff + (uint32_t)vp * (16 * AHS * 2) + ks * 32);
            #pragma unroll
            for (int vp = 0; vp < 4; vp++) {
                mma_f16(ofr[vp * 2 + 0], af, &bv[vp][0]);
                mma_f16(ofr[vp * 2 + 1], af, &bv[vp][2]);
            }
        }
        __syncwarp();
    }
    float i0 = 1.0f / l0r, i1 = 1.0f / l1r;
    int t0 = q0 + wid * 16 + gid, t1 = t0 + 8;
    #pragma unroll
    for (int ot = 0; ot < 8; ot++) {
        int col = h * HD + ot * 8 + tig * 2;
        *(__half2*)(Y + (size_t)t0 * D + col) = __floats2half2_rn(ofr[ot][0] * i0, ofr[ot][1] * i0);
        *(__half2*)(Y + (size_t)t1 * D + col) = __floats2half2_rn(ofr[ot][2] * i1, ofr[ot][3] * i1);
    }
}

// ---------------- SiLU gate fp16 -> fp16 (fast sigmoid) ----------------
__global__ __launch_bounds__(256)
void silu_all(const __half* __restrict__ a0, const __half* __restrict__ b0,
              __half* __restrict__ g0, int n0,
              const __half* __restrict__ a1, const __half* __restrict__ b1,
              __half* __restrict__ g1, int n1) {
    const float L2E = 1.4426950408889634f;
    int i = blockIdx.x * 256 + threadIdx.x;
    int h0 = n0 >> 1;
    if (i < h0) {
        __half2 av = ((const __half2*)a0)[i];
        __half2 bv = ((const __half2*)b0)[i];
        float x0 = __half2float(__low2half(av)), x1 = __half2float(__high2half(av));
        float s0 = x0 / (1.0f + ex2f(-x0 * L2E)) * __half2float(__low2half(bv));
        float s1 = x1 / (1.0f + ex2f(-x1 * L2E)) * __half2float(__high2half(bv));
        ((__half2*)g0)[i] = __floats2half2_rn(s0, s1);
    } else if (i < h0 + (n1 >> 1)) {
        int j = i - h0;
        __half2 av = ((const __half2*)a1)[j];
        __half2 bv = ((const __half2*)b1)[j];
        float x0 = __half2float(__low2half(av)), x1 = __half2float(__high2half(av));
        float s0 = x0 / (1.0f + ex2f(-x0 * L2E)) * __half2float(__low2half(bv));
        float s1 = x1 / (1.0f + ex2f(-x1 * L2E)) * __half2float(__high2half(bv));
        ((__half2*)g1)[j] = __floats2half2_rn(s0, s1);
    }
}

// ---------------- host launcher ----------------
static inline int nct(int M, int N) { return (M / 128) * (N / 128); }

extern "C" void kernel_launch(void* const* d_in, const int* in_sizes, int n_in,
                              void* d_out, int out_size) {
    const float* x        = (const float*)d_in[0];
    const float* c        = (const float*)d_in[1];
    const float* freqs    = (const float*)d_in[2];
    const float* px_qk_w  = (const float*)d_in[3];
    const float* px_qn    = (const float*)d_in[4];
    const float* px_kn    = (const float*)d_in[5];
    const float* px_v_w   = (const float*)d_in[6];
    const float* px_v_b   = (const float*)d_in[7];
    const float* pc_qk_w  = (const float*)d_in[8];
    const float* pc_qn    = (const float*)d_in[9];
    const float* pc_kn    = (const float*)d_in[10];
    const float* pc_v_w   = (const float*)d_in[11];
    const float* pc_v_b   = (const float*)d_in[12];
    const float* p1_proj_w = (const float*)d_in[13];
    const float* p1_proj_b = (const float*)d_in[14];
    const float* p1_w1    = (const float*)d_in[15];
    const float* p1_b1    = (const float*)d_in[16];
    const float* p1_w3    = (const float*)d_in[17];
    const float* p1_b3    = (const float*)d_in[18];
    const float* p1_w2    = (const float*)d_in[19];
    const float* p1_b2    = (const float*)d_in[20];
    const float* p2_proj_w = (const float*)d_in[21];
    const float* p2_proj_b = (const float*)d_in[22];
    const float* p2_w1    = (const float*)d_in[23];
    const float* p2_b1    = (const float*)d_in[24];
    const float* p2_w3    = (const float*)d_in[25];
    const float* p2_b3    = (const float*)d_in[26];
    const float* p2_w2    = (const float*)d_in[27];
    const float* p2_b2    = (const float*)d_in[28];
    float* out = (float*)d_out;

    float *x1x, *x1c;
    __half *w16, *qk16x, *qk16c, *cln16, *xln16, *q16, *k16, *v16t, *y16;
    __half *h16x, *h16c, *t16x1, *t16x3, *t16c1, *t16c3, *g16x, *g16c;
    cudaGetSymbolAddress((void**)&x1x, g_x1x);
    cudaGetSymbolAddress((void**)&x1c, g_x1c);
    cudaGetSymbolAddress((void**)&w16,   g_w16);
    cudaGetSymbolAddress((void**)&qk16x, g_qk16x);
    cudaGetSymbolAddress((void**)&qk16c, g_qk16c);
    cudaGetSymbolAddress((void**)&cln16, g_cln16);
    cudaGetSymbolAddress((void**)&xln16, g_xln16);
    cudaGetSymbolAddress((void**)&q16,   g_q16);
    cudaGetSymbolAddress((void**)&k16,   g_k16);
    cudaGetSymbolAddress((void**)&v16t,  g_v16t);
    cudaGetSymbolAddress((void**)&y16,   g_y16);
    cudaGetSymbolAddress((void**)&h16x,  g_h16x);
    cudaGetSymbolAddress((void**)&h16c,  g_h16c);
    cudaGetSymbolAddress((void**)&t16x1, g_t16x1);
    cudaGetSymbolAddress((void**)&t16x3, g_t16x3);
    cudaGetSymbolAddress((void**)&t16c1, g_t16c1);
    cudaGetSymbolAddress((void**)&t16c3, g_t16c3);
    cudaGetSymbolAddress((void**)&g16x,  g_g16x);
    cudaGetSymbolAddress((void**)&g16c,  g_g16c);

    cudaFuncSetAttribute(attn_tc, cudaFuncAttributeMaxDynamicSharedMemorySize, ATN_SMEM);
    cudaFuncSetAttribute(mma_gemm_mj, cudaFuncAttributeMaxDynamicSharedMemorySize, MMG_SMEM);

    // 0) convert weights to fp16 arena
    {
        WJobs W;
        int o = 0;
        W.j[0]  = {pc_qk_w,  w16 + O_PCQK, o}; o += 1024;
        W.j[1]  = {px_qk_w,  w16 + O_PXQK, o}; o += 1024;
        W.j[2]  = {pc_v_w,   w16 + O_PCV,  o}; o += 512;
        W.j[3]  = {px_v_w,   w16 + O_PXV,  o}; o += 512;
        W.j[4]  = {p1_proj_w, w16 + O_P1P, o}; o += 512;
        W.j[5]  = {p2_proj_w, w16 + O_P2P, o}; o += 512;
        W.j[6]  = {p1_w1,    w16 + O_P1W1, o}; o += 2048;
        W.j[7]  = {p1_w3,    w16 + O_P1W3, o}; o += 2048;
        W.j[8]  = {p2_w1,    w16 + O_P2W1, o}; o += 2048;
        W.j[9]  = {p2_w3,    w16 + O_P2W3, o}; o += 2048;
        W.j[10] = {p1_w2,    w16 + O_P1W2, o}; o += 2048;
        W.j[11] = {p2_w2,    w16 + O_P2W2, o}; o += 2048;
        cvt16<<<o, 256>>>(W);
    }

    // 1) LayerNorm both streams -> fp16
    ln2_kernel<<<L_X + S_C, 256>>>(x, xln16, L_X, c, cln16);

    // 2) QKV GEMMs; qk fp16 out, V fp16 dim-major
    {
        GJobs J; J.n = 4;
        int o = 0;
        J.j[0] = {cln16, w16 + O_PCQK, nullptr, nullptr, qk16c, 2 * D, D, o, 2, 0};  o += nct(S_C, 2 * D);
        J.j[1] = {cln16, w16 + O_PCV,  pc_v_b,  nullptr, v16t,  D,     D, o, 1, 0};  o += nct(S_C, D);
        J.j[2] = {xln16, w16 + O_PXQK, nullptr, nullptr, qk16x, 2 * D, D, o, 2, 0};  o += nct(L_X, 2 * D);
        J.j[3] = {xln16, w16 + O_PXV,  px_v_b,  nullptr, v16t,  D,     D, o, 1, S_C}; o += nct(L_X, D);
        mma_gemm_mj<<<o, 128, MMG_SMEM>>>(J);
    }
    qk_finish_all<<<TT * H / 8, 256>>>(qk16c, qk16x, pc_qn, pc_kn, px_qn, px_kn, freqs, q16, k16);

    // 3) causal attention (fp16 tensor cores + ldmatrix) -> y fp16
    attn_tc<<<dim3(32, H), 128, ATN_SMEM>>>(q16, k16, v16t, y16);

    // 4) output projections (batched)
    const __half* yx16 = y16 + (size_t)S_C * D;
    {
        GJobs J; J.n = 2;
        int o = 0;
        J.j[0] = {yx16, w16 + O_P1P, p1_proj_b, x, x1x, D, D, o, 0, 0}; o += nct(L_X, D);
        J.j[1] = {y16,  w16 + O_P2P, p2_proj_b, c, x1c, D, D, o, 0, 0}; o += nct(S_C, D);
        J.j[2] = J.j[0]; J.j[3] = J.j[0];
        mma_gemm_mj<<<o, 128, MMG_SMEM>>>(J);
    }
    ln2_kernel<<<L_X + S_C, 256>>>(x1x, h16x, L_X, x1c, h16c);

    // 5) w1/w3 (batched) -> fp16 outputs
    {
        GJobs J; J.n = 4;
        int o = 0;
        J.j[0] = {h16x, w16 + O_P1W1, p1_b1, nullptr, t16x1, FF, D, o, 2, 0}; o += nct(L_X, FF);
        J.j[1] = {h16x, w16 + O_P1W3, p1_b3, nullptr, t16x3, FF, D, o, 2, 0}; o += nct(L_X, FF);
        J.j[2] = {h16c, w16 + O_P2W1, p2_b1, nullptr, t16c1, FF, D, o, 2, 0}; o += nct(S_C, FF);
        J.j[3] = {h16c, w16 + O_P2W3, p2_b3, nullptr, t16c3, FF, D, o, 2, 0}; o += nct(S_C, FF);
        mma_gemm_mj<<<o, 128, MMG_SMEM>>>(J);
    }
    silu_all<<<(TT * FF / 2 + 255) / 256, 256>>>(t16x1, t16x3, g16x, L_X * FF, t16c1, t16c3, g16c, S_C * FF);

    // 6) w2 (batched)
    {
        GJobs J; J.n = 2;
        int o = 0;
        J.j[0] = {g16x, w16 + O_P1W2, p1_b2, x1x, out,                   D, FF, o, 0, 0}; o += nct(L_X, D);
        J.j[1] = {g16c, w16 + O_P2W2, p2_b2, x1c, out + (size_t)L_X * D, D, FF, o, 0, 0}; o += nct(S_C, D);
        J.j[2] = J.j[0]; J.j[3] = J.j[0];
        mma_gemm_mj<<<o, 128, MMG_SMEM>>>(J);
    }
}